// round 1
// baseline (speedup 1.0000x reference)
#include <cuda_runtime.h>
#include <cuda_bf16.h>
#include <cstdint>

// ---------------------------------------------------------------------------
// Problem constants
// ---------------------------------------------------------------------------
#define B_BATCH 4
#define SEQ_L   2048
#define D_MODEL 512
#define D_VALUE 512
#define N_HEADS 8
#define HEAD_E  64
#define D_FF    2048
#define M_ROWS  (B_BATCH * SEQ_L)   // 8192

// ---------------------------------------------------------------------------
// Scratch (static device allocations — allowed; no cudaMalloc anywhere)
// ---------------------------------------------------------------------------
__device__ float g_Q   [M_ROWS * D_MODEL];
__device__ float g_K   [M_ROWS * D_MODEL];
__device__ float g_V   [M_ROWS * D_MODEL];
__device__ float g_att [M_ROWS * D_MODEL];
__device__ float g_proj[M_ROWS * D_MODEL];
__device__ float g_x   [M_ROWS * D_VALUE];
__device__ float g_h   [M_ROWS * D_FF];
__device__ float g_y   [M_ROWS * D_VALUE];
__device__ float g_x2  [M_ROWS * D_VALUE];

// ---------------------------------------------------------------------------
// SGEMM: C[M,N] = A[M,K] @ W[N,K]^T + bias  (optionally ReLU)
// 128x128 block tile, BK=8, 256 threads, 8x8 microtile w/ 64-split blocking.
// ---------------------------------------------------------------------------
template<bool RELU>
__global__ __launch_bounds__(256) void gemm_nt_kernel(
    const float* __restrict__ A, const float* __restrict__ W,
    const float* __restrict__ bias, float* __restrict__ C,
    int M, int N, int K)
{
    __shared__ float As[8][132];
    __shared__ float Bs[8][132];

    const int tid = threadIdx.x;
    const int tx = tid & 15;
    const int ty = tid >> 4;
    const int m0 = blockIdx.y * 128;
    const int n0 = blockIdx.x * 128;

    const int lrow  = tid >> 1;        // 0..127
    const int lpart = (tid & 1) * 4;   // 0 or 4

    const float* Aptr = A + (size_t)(m0 + lrow) * K + lpart;
    const float* Bptr = W + (size_t)(n0 + lrow) * K + lpart;

    float acc[8][8];
#pragma unroll
    for (int i = 0; i < 8; ++i)
#pragma unroll
        for (int j = 0; j < 8; ++j) acc[i][j] = 0.f;

    for (int k0 = 0; k0 < K; k0 += 8) {
        float4 av = *(const float4*)(Aptr + k0);
        float4 bv = *(const float4*)(Bptr + k0);
        __syncthreads();
        As[lpart + 0][lrow] = av.x; As[lpart + 1][lrow] = av.y;
        As[lpart + 2][lrow] = av.z; As[lpart + 3][lrow] = av.w;
        Bs[lpart + 0][lrow] = bv.x; Bs[lpart + 1][lrow] = bv.y;
        Bs[lpart + 2][lrow] = bv.z; Bs[lpart + 3][lrow] = bv.w;
        __syncthreads();
#pragma unroll
        for (int k = 0; k < 8; ++k) {
            float a[8], b[8];
            *(float4*)(a + 0) = *(const float4*)&As[k][ty * 4];
            *(float4*)(a + 4) = *(const float4*)&As[k][64 + ty * 4];
            *(float4*)(b + 0) = *(const float4*)&Bs[k][tx * 4];
            *(float4*)(b + 4) = *(const float4*)&Bs[k][64 + tx * 4];
#pragma unroll
            for (int i = 0; i < 8; ++i)
#pragma unroll
                for (int j = 0; j < 8; ++j)
                    acc[i][j] = fmaf(a[i], b[j], acc[i][j]);
        }
    }

    float bvals[8];
    *(float4*)(bvals + 0) = *(const float4*)&bias[n0 + tx * 4];
    *(float4*)(bvals + 4) = *(const float4*)&bias[n0 + 64 + tx * 4];

#pragma unroll
    for (int i = 0; i < 8; ++i) {
        int m = m0 + ((i < 4) ? (ty * 4 + i) : (64 + ty * 4 + (i - 4)));
        float4 r0, r1;
        float c0 = acc[i][0] + bvals[0], c1 = acc[i][1] + bvals[1];
        float c2 = acc[i][2] + bvals[2], c3 = acc[i][3] + bvals[3];
        float c4 = acc[i][4] + bvals[4], c5 = acc[i][5] + bvals[5];
        float c6 = acc[i][6] + bvals[6], c7 = acc[i][7] + bvals[7];
        if (RELU) {
            c0 = fmaxf(c0, 0.f); c1 = fmaxf(c1, 0.f); c2 = fmaxf(c2, 0.f); c3 = fmaxf(c3, 0.f);
            c4 = fmaxf(c4, 0.f); c5 = fmaxf(c5, 0.f); c6 = fmaxf(c6, 0.f); c7 = fmaxf(c7, 0.f);
        }
        r0 = make_float4(c0, c1, c2, c3);
        r1 = make_float4(c4, c5, c6, c7);
        *(float4*)&C[(size_t)m * N + n0 + tx * 4]      = r0;
        *(float4*)&C[(size_t)m * N + n0 + 64 + tx * 4] = r1;
    }
}

// ---------------------------------------------------------------------------
// Causal flash attention: 64-query tile per block per (b,h).
// Online softmax; S and P@V register-tiled 4x4 per thread over 16x16 threads.
// ---------------------------------------------------------------------------
#define ATT_STRIDE 65

__global__ __launch_bounds__(256) void attn_kernel(
    const float* __restrict__ Q, const float* __restrict__ K,
    const float* __restrict__ V, float* __restrict__ O)
{
    extern __shared__ float sm[];
    float* Qs  = sm;                       // 64 * 65
    float* KPs = sm + 64 * ATT_STRIDE;     // K tile, reused as P
    float* Vs  = sm + 2 * 64 * ATT_STRIDE;

    const int tid = threadIdx.x;
    const int tx = tid & 15;
    const int ty = tid >> 4;
    const int qt = blockIdx.x;
    const int h  = blockIdx.y;
    const int b  = blockIdx.z;
    const int q0 = qt * 64;

    const size_t base = (size_t)b * SEQ_L * D_MODEL + (size_t)h * HEAD_E;

    // load Q tile (64 rows x 64 cols)
    {
        int row = tid >> 2;
        int cb  = (tid & 3) * 16;
        const float* src = Q + base + (size_t)(q0 + row) * D_MODEL + cb;
        float* dst = Qs + row * ATT_STRIDE + cb;
#pragma unroll
        for (int c = 0; c < 16; c += 4) {
            float4 t = *(const float4*)(src + c);
            dst[c] = t.x; dst[c + 1] = t.y; dst[c + 2] = t.z; dst[c + 3] = t.w;
        }
    }

    float m_i[4], l_i[4], o[4][4];
#pragma unroll
    for (int i = 0; i < 4; ++i) {
        m_i[i] = -1e30f; l_i[i] = 0.f;
#pragma unroll
        for (int j = 0; j < 4; ++j) o[i][j] = 0.f;
    }

    const float scale = 0.125f;  // 1/sqrt(64)

    for (int kt = 0; kt <= qt; ++kt) {
        const int k0 = kt * 64;
        __syncthreads();  // prior P@V reads done before overwriting KPs/Vs
        {
            int row = tid >> 2;
            int cb  = (tid & 3) * 16;
            const float* ksrc = K + base + (size_t)(k0 + row) * D_MODEL + cb;
            const float* vsrc = V + base + (size_t)(k0 + row) * D_MODEL + cb;
            float* kdst = KPs + row * ATT_STRIDE + cb;
            float* vdst = Vs  + row * ATT_STRIDE + cb;
#pragma unroll
            for (int c = 0; c < 16; c += 4) {
                float4 tk = *(const float4*)(ksrc + c);
                float4 tv = *(const float4*)(vsrc + c);
                kdst[c] = tk.x; kdst[c + 1] = tk.y; kdst[c + 2] = tk.z; kdst[c + 3] = tk.w;
                vdst[c] = tv.x; vdst[c + 1] = tv.y; vdst[c + 2] = tv.z; vdst[c + 3] = tv.w;
            }
        }
        __syncthreads();

        // S = Q @ K^T (4x4 per thread)
        float s[4][4];
#pragma unroll
        for (int i = 0; i < 4; ++i)
#pragma unroll
            for (int j = 0; j < 4; ++j) s[i][j] = 0.f;

#pragma unroll 8
        for (int e = 0; e < 64; ++e) {
            float qv[4], kv[4];
#pragma unroll
            for (int i = 0; i < 4; ++i) qv[i] = Qs[(4 * ty + i) * ATT_STRIDE + e];
#pragma unroll
            for (int j = 0; j < 4; ++j) kv[j] = KPs[(4 * tx + j) * ATT_STRIDE + e];
#pragma unroll
            for (int i = 0; i < 4; ++i)
#pragma unroll
                for (int j = 0; j < 4; ++j)
                    s[i][j] = fmaf(qv[i], kv[j], s[i][j]);
        }

        // scale + causal mask
#pragma unroll
        for (int i = 0; i < 4; ++i) {
            int qg = q0 + 4 * ty + i;
#pragma unroll
            for (int j = 0; j < 4; ++j) {
                int kg = k0 + 4 * tx + j;
                float v = s[i][j] * scale;
                s[i][j] = (kg > qg) ? -1e30f : v;
            }
        }

        // online softmax update
        float p[4][4];
#pragma unroll
        for (int i = 0; i < 4; ++i) {
            float mx = fmaxf(fmaxf(s[i][0], s[i][1]), fmaxf(s[i][2], s[i][3]));
#pragma unroll
            for (int off = 8; off >= 1; off >>= 1)
                mx = fmaxf(mx, __shfl_xor_sync(0xffffffffu, mx, off));
            float mnew = fmaxf(m_i[i], mx);
            float alpha = __expf(m_i[i] - mnew);
            m_i[i] = mnew;
            float sum = 0.f;
#pragma unroll
            for (int j = 0; j < 4; ++j) {
                p[i][j] = __expf(s[i][j] - mnew);
                sum += p[i][j];
            }
#pragma unroll
            for (int off = 8; off >= 1; off >>= 1)
                sum += __shfl_xor_sync(0xffffffffu, sum, off);
            l_i[i] = l_i[i] * alpha + sum;
#pragma unroll
            for (int j = 0; j < 4; ++j) o[i][j] *= alpha;
        }

        __syncthreads();  // all threads done reading K tile
#pragma unroll
        for (int i = 0; i < 4; ++i)
#pragma unroll
            for (int j = 0; j < 4; ++j)
                KPs[(4 * ty + i) * ATT_STRIDE + 4 * tx + j] = p[i][j];
        __syncthreads();

        // O += P @ V
#pragma unroll 8
        for (int kk = 0; kk < 64; ++kk) {
            float a[4], bb[4];
#pragma unroll
            for (int i = 0; i < 4; ++i) a[i] = KPs[(4 * ty + i) * ATT_STRIDE + kk];
#pragma unroll
            for (int j = 0; j < 4; ++j) bb[j] = Vs[kk * ATT_STRIDE + 4 * tx + j];
#pragma unroll
            for (int i = 0; i < 4; ++i)
#pragma unroll
                for (int j = 0; j < 4; ++j)
                    o[i][j] = fmaf(a[i], bb[j], o[i][j]);
        }
    }

    // normalize + write
#pragma unroll
    for (int i = 0; i < 4; ++i) {
        float inv = 1.f / l_i[i];
        float4 r = make_float4(o[i][0] * inv, o[i][1] * inv, o[i][2] * inv, o[i][3] * inv);
        *(float4*)&O[base + (size_t)(q0 + 4 * ty + i) * D_MODEL + 4 * tx] = r;
    }
}

// ---------------------------------------------------------------------------
// Residual + LayerNorm over rows of 512. 128 threads/row, float4 per thread.
// ---------------------------------------------------------------------------
__global__ __launch_bounds__(128) void residual_ln_kernel(
    const float* __restrict__ a, const float* __restrict__ b,
    const float* __restrict__ gamma, const float* __restrict__ beta,
    float* __restrict__ out)
{
    const int row = blockIdx.x;
    const int tid = threadIdx.x;
    const size_t base = (size_t)row * D_VALUE;

    float4 va = ((const float4*)(a + base))[tid];
    float4 vb = ((const float4*)(b + base))[tid];
    float4 v = make_float4(va.x + vb.x, va.y + vb.y, va.z + vb.z, va.w + vb.w);

    float s  = v.x + v.y + v.z + v.w;
    float ss = v.x * v.x + v.y * v.y + v.z * v.z + v.w * v.w;
#pragma unroll
    for (int off = 16; off >= 1; off >>= 1) {
        s  += __shfl_xor_sync(0xffffffffu, s, off);
        ss += __shfl_xor_sync(0xffffffffu, ss, off);
    }
    __shared__ float red[8];
    const int wid = tid >> 5;
    if ((tid & 31) == 0) { red[wid] = s; red[4 + wid] = ss; }
    __syncthreads();
    s  = red[0] + red[1] + red[2] + red[3];
    ss = red[4] + red[5] + red[6] + red[7];

    const float mu  = s * (1.f / (float)D_VALUE);
    float var = ss * (1.f / (float)D_VALUE) - mu * mu;
    const float rn = rsqrtf(var + 1e-5f);

    float4 g4 = ((const float4*)gamma)[tid];
    float4 b4 = ((const float4*)beta)[tid];
    float4 r;
    r.x = (v.x - mu) * rn * g4.x + b4.x;
    r.y = (v.y - mu) * rn * g4.y + b4.y;
    r.z = (v.z - mu) * rn * g4.z + b4.z;
    r.w = (v.w - mu) * rn * g4.w + b4.w;
    ((float4*)(out + base))[tid] = r;
}

// ---------------------------------------------------------------------------
// Launch
// ---------------------------------------------------------------------------
extern "C" void kernel_launch(void* const* d_in, const int* in_sizes, int n_in,
                              void* d_out, int out_size)
{
    const float* q   = (const float*)d_in[0];
    const float* k   = (const float*)d_in[1];
    const float* v   = (const float*)d_in[2];
    const float* Wq  = (const float*)d_in[3];
    const float* bq  = (const float*)d_in[4];
    const float* Wk  = (const float*)d_in[5];
    const float* bk  = (const float*)d_in[6];
    const float* Wv  = (const float*)d_in[7];
    const float* bv  = (const float*)d_in[8];
    const float* Wo  = (const float*)d_in[9];
    const float* bo  = (const float*)d_in[10];
    const float* Wc1 = (const float*)d_in[11];
    const float* bc1 = (const float*)d_in[12];
    const float* Wc2 = (const float*)d_in[13];
    const float* bc2 = (const float*)d_in[14];
    const float* g1  = (const float*)d_in[15];
    const float* b1  = (const float*)d_in[16];
    const float* g2  = (const float*)d_in[17];
    const float* b2  = (const float*)d_in[18];
    const float* Wl  = (const float*)d_in[19];
    const float* bl  = (const float*)d_in[20];
    float* out = (float*)d_out;

    float *Q, *K, *V, *Att, *Proj, *X, *Hh, *Y, *X2;
    cudaGetSymbolAddress((void**)&Q,    g_Q);
    cudaGetSymbolAddress((void**)&K,    g_K);
    cudaGetSymbolAddress((void**)&V,    g_V);
    cudaGetSymbolAddress((void**)&Att,  g_att);
    cudaGetSymbolAddress((void**)&Proj, g_proj);
    cudaGetSymbolAddress((void**)&X,    g_x);
    cudaGetSymbolAddress((void**)&Hh,   g_h);
    cudaGetSymbolAddress((void**)&Y,    g_y);
    cudaGetSymbolAddress((void**)&X2,   g_x2);

    const dim3 blk(256);
    const dim3 grid512(D_MODEL / 128, M_ROWS / 128);   // (4, 64)
    const dim3 gridFF (D_FF   / 128, M_ROWS / 128);    // (16, 64)

    // QKV projections
    gemm_nt_kernel<false><<<grid512, blk>>>(q, Wq, bq, Q, M_ROWS, D_MODEL, D_MODEL);
    gemm_nt_kernel<false><<<grid512, blk>>>(k, Wk, bk, K, M_ROWS, D_MODEL, D_MODEL);
    gemm_nt_kernel<false><<<grid512, blk>>>(v, Wv, bv, V, M_ROWS, D_MODEL, D_MODEL);

    // causal attention
    int smem = 3 * 64 * ATT_STRIDE * (int)sizeof(float);  // 49920 B
    cudaFuncSetAttribute(attn_kernel, cudaFuncAttributeMaxDynamicSharedMemorySize, smem);
    attn_kernel<<<dim3(SEQ_L / 64, N_HEADS, B_BATCH), blk, smem>>>(Q, K, V, Att);

    // output projection
    gemm_nt_kernel<false><<<grid512, blk>>>(Att, Wo, bo, Proj, M_ROWS, D_MODEL, D_MODEL);

    // residual + LN1
    residual_ln_kernel<<<M_ROWS, 128>>>(v, Proj, g1, b1, X);

    // FFN
    gemm_nt_kernel<true ><<<gridFF,  blk>>>(X,  Wc1, bc1, Hh, M_ROWS, D_FF,    D_VALUE);
    gemm_nt_kernel<false><<<grid512, blk>>>(Hh, Wc2, bc2, Y,  M_ROWS, D_VALUE, D_FF);

    // residual + LN2
    residual_ln_kernel<<<M_ROWS, 128>>>(X, Y, g2, b2, X2);

    // final projection -> out
    gemm_nt_kernel<false><<<grid512, blk>>>(X2, Wl, bl, out, M_ROWS, D_MODEL, D_VALUE);
}

// round 3
// speedup vs baseline: 1.1402x; 1.1402x over previous
#include <cuda_runtime.h>
#include <cuda_bf16.h>
#include <cstdint>

// ---------------------------------------------------------------------------
// Problem constants
// ---------------------------------------------------------------------------
#define B_BATCH 4
#define SEQ_L   2048
#define D_MODEL 512
#define D_VALUE 512
#define N_HEADS 8
#define HEAD_E  64
#define D_FF    2048
#define M_ROWS  (B_BATCH * SEQ_L)   // 8192

// ---------------------------------------------------------------------------
// Scratch (static device allocations — allowed; no cudaMalloc anywhere)
// ---------------------------------------------------------------------------
__device__ float g_Q   [M_ROWS * D_MODEL];
__device__ float g_K   [M_ROWS * D_MODEL];
__device__ float g_V   [M_ROWS * D_MODEL];
__device__ float g_att [M_ROWS * D_MODEL];
__device__ float g_proj[M_ROWS * D_MODEL];
__device__ float g_x   [M_ROWS * D_VALUE];
__device__ float g_h   [M_ROWS * D_FF];
__device__ float g_y   [M_ROWS * D_VALUE];
__device__ float g_x2  [M_ROWS * D_VALUE];

// ---------------------------------------------------------------------------
// SGEMM: C[M,N] = A[M,K] @ W[N,K]^T + bias  (optionally ReLU)
// 128x128 block tile, BK=8, 256 threads, 8x8 microtile, gmem prefetch.
// ---------------------------------------------------------------------------
template<bool RELU>
__global__ __launch_bounds__(256) void gemm_nt_kernel(
    const float* __restrict__ A, const float* __restrict__ W,
    const float* __restrict__ bias, float* __restrict__ C,
    int M, int N, int K)
{
    __shared__ float As[8][132];
    __shared__ float Bs[8][132];

    const int tid = threadIdx.x;
    const int tx = tid & 15;
    const int ty = tid >> 4;
    const int m0 = blockIdx.y * 128;
    const int n0 = blockIdx.x * 128;

    const int lrow  = tid >> 1;        // 0..127
    const int lpart = (tid & 1) * 4;   // 0 or 4

    const float* Aptr = A + (size_t)(m0 + lrow) * K + lpart;
    const float* Bptr = W + (size_t)(n0 + lrow) * K + lpart;

    float acc[8][8];
#pragma unroll
    for (int i = 0; i < 8; ++i)
#pragma unroll
        for (int j = 0; j < 8; ++j) acc[i][j] = 0.f;

    // prefetch first slice
    float4 av = *(const float4*)(Aptr);
    float4 bv = *(const float4*)(Bptr);

    for (int k0 = 0; k0 < K; k0 += 8) {
        __syncthreads();
        As[lpart + 0][lrow] = av.x; As[lpart + 1][lrow] = av.y;
        As[lpart + 2][lrow] = av.z; As[lpart + 3][lrow] = av.w;
        Bs[lpart + 0][lrow] = bv.x; Bs[lpart + 1][lrow] = bv.y;
        Bs[lpart + 2][lrow] = bv.z; Bs[lpart + 3][lrow] = bv.w;
        __syncthreads();
        // prefetch next slice while computing this one
        if (k0 + 8 < K) {
            av = *(const float4*)(Aptr + k0 + 8);
            bv = *(const float4*)(Bptr + k0 + 8);
        }
#pragma unroll
        for (int k = 0; k < 8; ++k) {
            float a[8], b[8];
            *(float4*)(a + 0) = *(const float4*)&As[k][ty * 4];
            *(float4*)(a + 4) = *(const float4*)&As[k][64 + ty * 4];
            *(float4*)(b + 0) = *(const float4*)&Bs[k][tx * 4];
            *(float4*)(b + 4) = *(const float4*)&Bs[k][64 + tx * 4];
#pragma unroll
            for (int i = 0; i < 8; ++i)
#pragma unroll
                for (int j = 0; j < 8; ++j)
                    acc[i][j] = fmaf(a[i], b[j], acc[i][j]);
        }
    }

    float bvals[8];
    *(float4*)(bvals + 0) = *(const float4*)&bias[n0 + tx * 4];
    *(float4*)(bvals + 4) = *(const float4*)&bias[n0 + 64 + tx * 4];

#pragma unroll
    for (int i = 0; i < 8; ++i) {
        int m = m0 + ((i < 4) ? (ty * 4 + i) : (64 + ty * 4 + (i - 4)));
        float c0 = acc[i][0] + bvals[0], c1 = acc[i][1] + bvals[1];
        float c2 = acc[i][2] + bvals[2], c3 = acc[i][3] + bvals[3];
        float c4 = acc[i][4] + bvals[4], c5 = acc[i][5] + bvals[5];
        float c6 = acc[i][6] + bvals[6], c7 = acc[i][7] + bvals[7];
        if (RELU) {
            c0 = fmaxf(c0, 0.f); c1 = fmaxf(c1, 0.f); c2 = fmaxf(c2, 0.f); c3 = fmaxf(c3, 0.f);
            c4 = fmaxf(c4, 0.f); c5 = fmaxf(c5, 0.f); c6 = fmaxf(c6, 0.f); c7 = fmaxf(c7, 0.f);
        }
        *(float4*)&C[(size_t)m * N + n0 + tx * 4]      = make_float4(c0, c1, c2, c3);
        *(float4*)&C[(size_t)m * N + n0 + 64 + tx * 4] = make_float4(c4, c5, c6, c7);
    }
}

// ---------------------------------------------------------------------------
// Causal flash attention v2: 128-query x 64-key tiles per block per (b,h).
// 8x4 microtile per thread (16x16 thread grid). Q/K/P held TRANSPOSED in
// smem so all inner-loop reads are vectorized LDS.128.
// ---------------------------------------------------------------------------
#define BQ 128
#define BK 64
#define QS 132   // padded stride for q-dim arrays
#define KS 68    // padded stride for k/e-dim arrays

__global__ __launch_bounds__(256, 2) void attn_kernel(
    const float* __restrict__ Q, const float* __restrict__ K,
    const float* __restrict__ V, float* __restrict__ O)
{
    extern __shared__ float sm[];
    float* Qt = sm;                    // [64 e][132]  (transposed Q tile)
    float* Kt = Qt + 64 * QS;          // [64 e][68]   (transposed K tile)
    float* Vs = Kt + 64 * KS;          // [64 k][68]   (natural V tile)
    float* Pt = Vs + 64 * KS;          // [64 k][132]  (transposed P tile)

    const int tid = threadIdx.x;
    const int tx = tid & 15;           // k-dim: 4 cols each
    const int ty = tid >> 4;           // q-dim: 8 rows each
    const int qt = blockIdx.x;
    const int h  = blockIdx.y;
    const int b  = blockIdx.z;
    const int q0 = qt * BQ;

    const size_t base = (size_t)b * SEQ_L * D_MODEL + (size_t)h * HEAD_E;

    // ---- load + transpose Q tile: Qt[e][q] ----
    {
        int qq = tid >> 1;
        int e0 = (tid & 1) * 32;
        const float* src = Q + base + (size_t)(q0 + qq) * D_MODEL + e0;
#pragma unroll
        for (int c = 0; c < 8; ++c) {
            float4 t = *(const float4*)(src + c * 4);
            int e = e0 + c * 4;
            Qt[(e + 0) * QS + qq] = t.x; Qt[(e + 1) * QS + qq] = t.y;
            Qt[(e + 2) * QS + qq] = t.z; Qt[(e + 3) * QS + qq] = t.w;
        }
    }

    float m_i[8], l_i[8], o[8][4];
#pragma unroll
    for (int i = 0; i < 8; ++i) {
        m_i[i] = -1e30f; l_i[i] = 0.f;
#pragma unroll
        for (int j = 0; j < 4; ++j) o[i][j] = 0.f;
    }

    const float scale = 0.125f;  // 1/sqrt(64)
    const int ktmax = 2 * qt + 1;

    for (int kt = 0; kt <= ktmax; ++kt) {
        const int k0 = kt * BK;
        __syncthreads();  // prior P@V reads of Pt/Vs + S reads of Kt done
        // ---- load K (transposed) and V (natural) tiles ----
        {
            int kk = tid >> 2;
            int e0 = (tid & 3) * 16;
            const float* ksrc = K + base + (size_t)(k0 + kk) * D_MODEL + e0;
            const float* vsrc = V + base + (size_t)(k0 + kk) * D_MODEL + e0;
#pragma unroll
            for (int c = 0; c < 4; ++c) {
                int e = e0 + c * 4;
                float4 tk = *(const float4*)(ksrc + c * 4);
                Kt[(e + 0) * KS + kk] = tk.x; Kt[(e + 1) * KS + kk] = tk.y;
                Kt[(e + 2) * KS + kk] = tk.z; Kt[(e + 3) * KS + kk] = tk.w;
                float4 tv = *(const float4*)(vsrc + c * 4);
                *(float4*)&Vs[kk * KS + e] = tv;
            }
        }
        __syncthreads();

        // ---- S = Q @ K^T : 8x4 per thread, all LDS.128 ----
        float s[8][4];
#pragma unroll
        for (int i = 0; i < 8; ++i)
#pragma unroll
            for (int j = 0; j < 4; ++j) s[i][j] = 0.f;

#pragma unroll 8
        for (int e = 0; e < 64; ++e) {
            float4 kv = *(const float4*)&Kt[e * KS + tx * 4];
            float4 qa = *(const float4*)&Qt[e * QS + ty * 8];
            float4 qb = *(const float4*)&Qt[e * QS + ty * 8 + 4];
            float qv[8] = {qa.x, qa.y, qa.z, qa.w, qb.x, qb.y, qb.z, qb.w};
            float kw[4] = {kv.x, kv.y, kv.z, kv.w};
#pragma unroll
            for (int i = 0; i < 8; ++i)
#pragma unroll
                for (int j = 0; j < 4; ++j)
                    s[i][j] = fmaf(qv[i], kw[j], s[i][j]);
        }

        // ---- scale (+ causal mask only on the two boundary tiles) ----
        if (kt >= 2 * qt) {
#pragma unroll
            for (int i = 0; i < 8; ++i) {
                int qg = q0 + ty * 8 + i;
#pragma unroll
                for (int j = 0; j < 4; ++j) {
                    int kg = k0 + tx * 4 + j;
                    float v = s[i][j] * scale;
                    s[i][j] = (kg > qg) ? -1e30f : v;
                }
            }
        } else {
#pragma unroll
            for (int i = 0; i < 8; ++i)
#pragma unroll
                for (int j = 0; j < 4; ++j) s[i][j] *= scale;
        }

        // ---- online softmax (row reduce across tx via shfl, width 16) ----
#pragma unroll
        for (int i = 0; i < 8; ++i) {
            float mx = fmaxf(fmaxf(s[i][0], s[i][1]), fmaxf(s[i][2], s[i][3]));
#pragma unroll
            for (int off = 8; off >= 1; off >>= 1)
                mx = fmaxf(mx, __shfl_xor_sync(0xffffffffu, mx, off));
            float mnew = fmaxf(m_i[i], mx);
            float alpha = __expf(m_i[i] - mnew);
            m_i[i] = mnew;
            float sum = 0.f;
#pragma unroll
            for (int j = 0; j < 4; ++j) {
                s[i][j] = __expf(s[i][j] - mnew);
                sum += s[i][j];
            }
#pragma unroll
            for (int off = 8; off >= 1; off >>= 1)
                sum += __shfl_xor_sync(0xffffffffu, sum, off);
            l_i[i] = l_i[i] * alpha + sum;
#pragma unroll
            for (int j = 0; j < 4; ++j) o[i][j] *= alpha;
        }

        // ---- write P transposed: Pt[k][q], vectorized ----
#pragma unroll
        for (int j = 0; j < 4; ++j) {
            *(float4*)&Pt[(tx * 4 + j) * QS + ty * 8] =
                make_float4(s[0][j], s[1][j], s[2][j], s[3][j]);
            *(float4*)&Pt[(tx * 4 + j) * QS + ty * 8 + 4] =
                make_float4(s[4][j], s[5][j], s[6][j], s[7][j]);
        }
        __syncthreads();

        // ---- O += P @ V : all LDS.128 ----
#pragma unroll 8
        for (int kk = 0; kk < 64; ++kk) {
            float4 vv = *(const float4*)&Vs[kk * KS + tx * 4];
            float4 pa = *(const float4*)&Pt[kk * QS + ty * 8];
            float4 pb = *(const float4*)&Pt[kk * QS + ty * 8 + 4];
            float pv[8] = {pa.x, pa.y, pa.z, pa.w, pb.x, pb.y, pb.z, pb.w};
            float vw[4] = {vv.x, vv.y, vv.z, vv.w};
#pragma unroll
            for (int i = 0; i < 8; ++i)
#pragma unroll
                for (int j = 0; j < 4; ++j)
                    o[i][j] = fmaf(pv[i], vw[j], o[i][j]);
        }
    }

    // ---- normalize + write ----
#pragma unroll
    for (int i = 0; i < 8; ++i) {
        float inv = 1.f / l_i[i];
        float4 r = make_float4(o[i][0] * inv, o[i][1] * inv,
                               o[i][2] * inv, o[i][3] * inv);
        *(float4*)&O[base + (size_t)(q0 + ty * 8 + i) * D_MODEL + tx * 4] = r;
    }
}

// ---------------------------------------------------------------------------
// Residual + LayerNorm over rows of 512. 128 threads/row, float4 per thread.
// ---------------------------------------------------------------------------
__global__ __launch_bounds__(128) void residual_ln_kernel(
    const float* __restrict__ a, const float* __restrict__ b,
    const float* __restrict__ gamma, const float* __restrict__ beta,
    float* __restrict__ out)
{
    const int row = blockIdx.x;
    const int tid = threadIdx.x;
    const size_t base = (size_t)row * D_VALUE;

    float4 va = ((const float4*)(a + base))[tid];
    float4 vb = ((const float4*)(b + base))[tid];
    float4 v = make_float4(va.x + vb.x, va.y + vb.y, va.z + vb.z, va.w + vb.w);

    float s  = v.x + v.y + v.z + v.w;
    float ss = v.x * v.x + v.y * v.y + v.z * v.z + v.w * v.w;
#pragma unroll
    for (int off = 16; off >= 1; off >>= 1) {
        s  += __shfl_xor_sync(0xffffffffu, s, off);
        ss += __shfl_xor_sync(0xffffffffu, ss, off);
    }
    __shared__ float red[8];
    const int wid = tid >> 5;
    if ((tid & 31) == 0) { red[wid] = s; red[4 + wid] = ss; }
    __syncthreads();
    s  = red[0] + red[1] + red[2] + red[3];
    ss = red[4] + red[5] + red[6] + red[7];

    const float mu  = s * (1.f / (float)D_VALUE);
    float var = ss * (1.f / (float)D_VALUE) - mu * mu;
    const float rn = rsqrtf(var + 1e-5f);

    float4 g4 = ((const float4*)gamma)[tid];
    float4 b4 = ((const float4*)beta)[tid];
    float4 r;
    r.x = (v.x - mu) * rn * g4.x + b4.x;
    r.y = (v.y - mu) * rn * g4.y + b4.y;
    r.z = (v.z - mu) * rn * g4.z + b4.z;
    r.w = (v.w - mu) * rn * g4.w + b4.w;
    ((float4*)(out + base))[tid] = r;
}

// ---------------------------------------------------------------------------
// Launch
// ---------------------------------------------------------------------------
extern "C" void kernel_launch(void* const* d_in, const int* in_sizes, int n_in,
                              void* d_out, int out_size)
{
    const float* q   = (const float*)d_in[0];
    const float* k   = (const float*)d_in[1];
    const float* v   = (const float*)d_in[2];
    const float* Wq  = (const float*)d_in[3];
    const float* bq  = (const float*)d_in[4];
    const float* Wk  = (const float*)d_in[5];
    const float* bk  = (const float*)d_in[6];
    const float* Wv  = (const float*)d_in[7];
    const float* bv  = (const float*)d_in[8];
    const float* Wo  = (const float*)d_in[9];
    const float* bo  = (const float*)d_in[10];
    const float* Wc1 = (const float*)d_in[11];
    const float* bc1 = (const float*)d_in[12];
    const float* Wc2 = (const float*)d_in[13];
    const float* bc2 = (const float*)d_in[14];
    const float* g1  = (const float*)d_in[15];
    const float* b1  = (const float*)d_in[16];
    const float* g2  = (const float*)d_in[17];
    const float* b2  = (const float*)d_in[18];
    const float* Wl  = (const float*)d_in[19];
    const float* bl  = (const float*)d_in[20];
    float* out = (float*)d_out;

    float *Q, *K, *V, *Att, *Proj, *X, *Hh, *Y, *X2;
    cudaGetSymbolAddress((void**)&Q,    g_Q);
    cudaGetSymbolAddress((void**)&K,    g_K);
    cudaGetSymbolAddress((void**)&V,    g_V);
    cudaGetSymbolAddress((void**)&Att,  g_att);
    cudaGetSymbolAddress((void**)&Proj, g_proj);
    cudaGetSymbolAddress((void**)&X,    g_x);
    cudaGetSymbolAddress((void**)&Hh,   g_h);
    cudaGetSymbolAddress((void**)&Y,    g_y);
    cudaGetSymbolAddress((void**)&X2,   g_x2);

    const dim3 blk(256);
    const dim3 grid512(D_MODEL / 128, M_ROWS / 128);   // (4, 64)
    const dim3 gridFF (D_FF   / 128, M_ROWS / 128);    // (16, 64)

    // QKV projections
    gemm_nt_kernel<false><<<grid512, blk>>>(q, Wq, bq, Q, M_ROWS, D_MODEL, D_MODEL);
    gemm_nt_kernel<false><<<grid512, blk>>>(k, Wk, bk, K, M_ROWS, D_MODEL, D_MODEL);
    gemm_nt_kernel<false><<<grid512, blk>>>(v, Wv, bv, V, M_ROWS, D_MODEL, D_MODEL);

    // causal attention: 128q x 64k tiles
    int smem = (64 * QS + 64 * KS + 64 * KS + 64 * QS) * (int)sizeof(float);  // 102400
    cudaFuncSetAttribute(attn_kernel, cudaFuncAttributeMaxDynamicSharedMemorySize, smem);
    attn_kernel<<<dim3(SEQ_L / BQ, N_HEADS, B_BATCH), blk, smem>>>(Q, K, V, Att);

    // output projection
    gemm_nt_kernel<false><<<grid512, blk>>>(Att, Wo, bo, Proj, M_ROWS, D_MODEL, D_MODEL);

    // residual + LN1
    residual_ln_kernel<<<M_ROWS, 128>>>(v, Proj, g1, b1, X);

    // FFN
    gemm_nt_kernel<true ><<<gridFF,  blk>>>(X,  Wc1, bc1, Hh, M_ROWS, D_FF,    D_VALUE);
    gemm_nt_kernel<false><<<grid512, blk>>>(Hh, Wc2, bc2, Y,  M_ROWS, D_VALUE, D_FF);

    // residual + LN2
    residual_ln_kernel<<<M_ROWS, 128>>>(X, Y, g2, b2, X2);

    // final projection -> out
    gemm_nt_kernel<false><<<grid512, blk>>>(X2, Wl, bl, out, M_ROWS, D_MODEL, D_VALUE);
}

// round 5
// speedup vs baseline: 1.4342x; 1.2578x over previous
#include <cuda_runtime.h>
#include <cuda_bf16.h>
#include <cstdint>

// ---------------------------------------------------------------------------
// Problem constants
// ---------------------------------------------------------------------------
#define B_BATCH 4
#define SEQ_L   2048
#define D_MODEL 512
#define D_VALUE 512
#define N_HEADS 8
#define HEAD_E  64
#define D_FF    2048
#define M_ROWS  (B_BATCH * SEQ_L)   // 8192

// ---------------------------------------------------------------------------
// Scratch (static device allocations)
// ---------------------------------------------------------------------------
__device__ float g_Q   [M_ROWS * D_MODEL];
__device__ float g_K   [M_ROWS * D_MODEL];
__device__ float g_V   [M_ROWS * D_MODEL];
__device__ float g_att [M_ROWS * D_MODEL];
__device__ float g_proj[M_ROWS * D_MODEL];
__device__ float g_x   [M_ROWS * D_VALUE];
__device__ float g_h   [M_ROWS * D_FF];
__device__ float g_y   [M_ROWS * D_VALUE];
__device__ float g_x2  [M_ROWS * D_VALUE];

// bf16 hi/lo staging for tensor-core GEMMs
__device__ __nv_bfloat16 g_Ah[M_ROWS * D_FF];
__device__ __nv_bfloat16 g_Al[M_ROWS * D_FF];
__device__ __nv_bfloat16 g_Wh[D_FF * D_VALUE];
__device__ __nv_bfloat16 g_Wl[D_FF * D_VALUE];

// ---------------------------------------------------------------------------
// Split fp32 -> bf16 hi + bf16 lo (error-compensated pair)
// ---------------------------------------------------------------------------
__global__ __launch_bounds__(256) void split_kernel(
    const float* __restrict__ x,
    __nv_bfloat16* __restrict__ hi, __nv_bfloat16* __restrict__ lo, int n4)
{
    int i = blockIdx.x * 256 + threadIdx.x;
    if (i >= n4) return;
    float4 v = ((const float4*)x)[i];
    __nv_bfloat16 h0 = __float2bfloat16_rn(v.x);
    __nv_bfloat16 h1 = __float2bfloat16_rn(v.y);
    __nv_bfloat16 h2 = __float2bfloat16_rn(v.z);
    __nv_bfloat16 h3 = __float2bfloat16_rn(v.w);
    __nv_bfloat16 l0 = __float2bfloat16_rn(v.x - __bfloat162float(h0));
    __nv_bfloat16 l1 = __float2bfloat16_rn(v.y - __bfloat162float(h1));
    __nv_bfloat16 l2 = __float2bfloat16_rn(v.z - __bfloat162float(h2));
    __nv_bfloat16 l3 = __float2bfloat16_rn(v.w - __bfloat162float(h3));
    ((__nv_bfloat162*)hi)[2 * i]     = __halves2bfloat162(h0, h1);
    ((__nv_bfloat162*)hi)[2 * i + 1] = __halves2bfloat162(h2, h3);
    ((__nv_bfloat162*)lo)[2 * i]     = __halves2bfloat162(l0, l1);
    ((__nv_bfloat162*)lo)[2 * i + 1] = __halves2bfloat162(l2, l3);
}

// ---------------------------------------------------------------------------
// bf16 tensor-core GEMM with hi/lo compensation:
//   C[M,N] = A[M,K] @ W[N,K]^T + bias  (optionally ReLU)
// acc = Ah*Bh + Ah*Bl + Al*Bh  (fp32 accumulators)
// CTA tile 128x128, BK=32, 8 warps (warp tile 64x32), mma.m16n8k16.
// ---------------------------------------------------------------------------
#define GS 40   // padded smem stride in bf16 elems (80B rows -> conflict-free)

__device__ __forceinline__ void mma_bf16(
    float& d0, float& d1, float& d2, float& d3,
    uint32_t a0, uint32_t a1, uint32_t a2, uint32_t a3,
    uint32_t b0, uint32_t b1)
{
    asm volatile(
        "mma.sync.aligned.m16n8k16.row.col.f32.bf16.bf16.f32 "
        "{%0,%1,%2,%3}, {%4,%5,%6,%7}, {%8,%9}, {%0,%1,%2,%3};"
        : "+f"(d0), "+f"(d1), "+f"(d2), "+f"(d3)
        : "r"(a0), "r"(a1), "r"(a2), "r"(a3), "r"(b0), "r"(b1));
}

template<bool RELU>
__global__ __launch_bounds__(256) void gemm_bf16_kernel(
    const __nv_bfloat16* __restrict__ Ah, const __nv_bfloat16* __restrict__ Al,
    const __nv_bfloat16* __restrict__ Bh, const __nv_bfloat16* __restrict__ Bl,
    const float* __restrict__ bias, float* __restrict__ C,
    int M, int N, int K)
{
    __shared__ __nv_bfloat16 sAh[128 * GS];
    __shared__ __nv_bfloat16 sAl[128 * GS];
    __shared__ __nv_bfloat16 sBh[128 * GS];
    __shared__ __nv_bfloat16 sBl[128 * GS];

    const int tid  = threadIdx.x;
    const int lane = tid & 31;
    const int warp = tid >> 5;
    const int wm = (warp & 1) * 64;   // warp m-offset in tile
    const int wn = (warp >> 1) * 32;  // warp n-offset in tile
    const int m0 = blockIdx.y * 128;
    const int n0 = blockIdx.x * 128;

    // global load mapping: 2 threads per row, 16 bf16 each
    const int lrow = tid >> 1;
    const int lch  = (tid & 1) * 16;

    const __nv_bfloat16* gAh = Ah + (size_t)(m0 + lrow) * K + lch;
    const __nv_bfloat16* gAl = Al + (size_t)(m0 + lrow) * K + lch;
    const __nv_bfloat16* gBh = Bh + (size_t)(n0 + lrow) * K + lch;
    const __nv_bfloat16* gBl = Bl + (size_t)(n0 + lrow) * K + lch;

    float acc[4][4][4];
#pragma unroll
    for (int mi = 0; mi < 4; ++mi)
#pragma unroll
        for (int ni = 0; ni < 4; ++ni)
#pragma unroll
            for (int r = 0; r < 4; ++r) acc[mi][ni][r] = 0.f;

    int4 rAh0 = *(const int4*)(gAh),     rAh1 = *(const int4*)(gAh + 8);
    int4 rAl0 = *(const int4*)(gAl),     rAl1 = *(const int4*)(gAl + 8);
    int4 rBh0 = *(const int4*)(gBh),     rBh1 = *(const int4*)(gBh + 8);
    int4 rBl0 = *(const int4*)(gBl),     rBl1 = *(const int4*)(gBl + 8);

    const int arow = (lane >> 2);
    const int acol = 2 * (lane & 3);

    for (int k0 = 0; k0 < K; k0 += 32) {
        __syncthreads();
        {
            const int so = lrow * GS + lch;
            *(int4*)&sAh[so] = rAh0; *(int4*)&sAh[so + 8] = rAh1;
            *(int4*)&sAl[so] = rAl0; *(int4*)&sAl[so + 8] = rAl1;
            *(int4*)&sBh[so] = rBh0; *(int4*)&sBh[so + 8] = rBh1;
            *(int4*)&sBl[so] = rBl0; *(int4*)&sBl[so + 8] = rBl1;
        }
        __syncthreads();
        if (k0 + 32 < K) {
            const int go = k0 + 32;
            rAh0 = *(const int4*)(gAh + go); rAh1 = *(const int4*)(gAh + go + 8);
            rAl0 = *(const int4*)(gAl + go); rAl1 = *(const int4*)(gAl + go + 8);
            rBh0 = *(const int4*)(gBh + go); rBh1 = *(const int4*)(gBh + go + 8);
            rBl0 = *(const int4*)(gBl + go); rBl1 = *(const int4*)(gBl + go + 8);
        }

#pragma unroll
        for (int ks = 0; ks < 2; ++ks) {
            const int kc = ks * 16 + acol;
            uint32_t aH[4][4], aL[4][4], bH[4][2], bL[4][2];
#pragma unroll
            for (int mi = 0; mi < 4; ++mi) {
                const int off = (wm + mi * 16 + arow) * GS + kc;
                aH[mi][0] = *(const uint32_t*)&sAh[off];
                aH[mi][1] = *(const uint32_t*)&sAh[off + 8 * GS];
                aH[mi][2] = *(const uint32_t*)&sAh[off + 8];
                aH[mi][3] = *(const uint32_t*)&sAh[off + 8 * GS + 8];
                aL[mi][0] = *(const uint32_t*)&sAl[off];
                aL[mi][1] = *(const uint32_t*)&sAl[off + 8 * GS];
                aL[mi][2] = *(const uint32_t*)&sAl[off + 8];
                aL[mi][3] = *(const uint32_t*)&sAl[off + 8 * GS + 8];
            }
#pragma unroll
            for (int ni = 0; ni < 4; ++ni) {
                const int off = (wn + ni * 8 + arow) * GS + kc;
                bH[ni][0] = *(const uint32_t*)&sBh[off];
                bH[ni][1] = *(const uint32_t*)&sBh[off + 8];
                bL[ni][0] = *(const uint32_t*)&sBl[off];
                bL[ni][1] = *(const uint32_t*)&sBl[off + 8];
            }
#pragma unroll
            for (int mi = 0; mi < 4; ++mi)
#pragma unroll
                for (int ni = 0; ni < 4; ++ni) {
                    float* d = acc[mi][ni];
                    mma_bf16(d[0], d[1], d[2], d[3],
                             aH[mi][0], aH[mi][1], aH[mi][2], aH[mi][3],
                             bH[ni][0], bH[ni][1]);
                    mma_bf16(d[0], d[1], d[2], d[3],
                             aH[mi][0], aH[mi][1], aH[mi][2], aH[mi][3],
                             bL[ni][0], bL[ni][1]);
                    mma_bf16(d[0], d[1], d[2], d[3],
                             aL[mi][0], aL[mi][1], aL[mi][2], aL[mi][3],
                             bH[ni][0], bH[ni][1]);
                }
        }
    }

    // epilogue: bias (+ReLU), direct stores (rows m, m+8; cols nc, nc+1)
#pragma unroll
    for (int mi = 0; mi < 4; ++mi) {
        const int m = m0 + wm + mi * 16 + (lane >> 2);
#pragma unroll
        for (int ni = 0; ni < 4; ++ni) {
            const int nc = n0 + wn + ni * 8 + 2 * (lane & 3);
            float b0 = bias[nc], b1 = bias[nc + 1];
            float c0 = acc[mi][ni][0] + b0, c1 = acc[mi][ni][1] + b1;
            float c2 = acc[mi][ni][2] + b0, c3 = acc[mi][ni][3] + b1;
            if (RELU) {
                c0 = fmaxf(c0, 0.f); c1 = fmaxf(c1, 0.f);
                c2 = fmaxf(c2, 0.f); c3 = fmaxf(c3, 0.f);
            }
            *(float2*)&C[(size_t)m * N + nc]       = make_float2(c0, c1);
            *(float2*)&C[(size_t)(m + 8) * N + nc] = make_float2(c2, c3);
        }
    }
}

// ---------------------------------------------------------------------------
// Causal flash attention: 128q x 64k tiles, 8x4 microtile, transposed smem.
// ---------------------------------------------------------------------------
#define BQ 128
#define BK 64
#define QS 132
#define KS 68

__global__ __launch_bounds__(256, 2) void attn_kernel(
    const float* __restrict__ Q, const float* __restrict__ K,
    const float* __restrict__ V, float* __restrict__ O)
{
    extern __shared__ float sm[];
    float* Qt = sm;
    float* Kt = Qt + 64 * QS;
    float* Vs = Kt + 64 * KS;
    float* Pt = Vs + 64 * KS;

    const int tid = threadIdx.x;
    const int tx = tid & 15;
    const int ty = tid >> 4;
    const int qt = blockIdx.x;
    const int h  = blockIdx.y;
    const int b  = blockIdx.z;
    const int q0 = qt * BQ;

    const size_t base = (size_t)b * SEQ_L * D_MODEL + (size_t)h * HEAD_E;

    {
        int qq = tid >> 1;
        int e0 = (tid & 1) * 32;
        const float* src = Q + base + (size_t)(q0 + qq) * D_MODEL + e0;
#pragma unroll
        for (int c = 0; c < 8; ++c) {
            float4 t = *(const float4*)(src + c * 4);
            int e = e0 + c * 4;
            Qt[(e + 0) * QS + qq] = t.x; Qt[(e + 1) * QS + qq] = t.y;
            Qt[(e + 2) * QS + qq] = t.z; Qt[(e + 3) * QS + qq] = t.w;
        }
    }

    float m_i[8], l_i[8], o[8][4];
#pragma unroll
    for (int i = 0; i < 8; ++i) {
        m_i[i] = -1e30f; l_i[i] = 0.f;
#pragma unroll
        for (int j = 0; j < 4; ++j) o[i][j] = 0.f;
    }

    const float scale = 0.125f;
    const int ktmax = 2 * qt + 1;

    for (int kt = 0; kt <= ktmax; ++kt) {
        const int k0 = kt * BK;
        __syncthreads();
        {
            int kk = tid >> 2;
            int e0 = (tid & 3) * 16;
            const float* ksrc = K + base + (size_t)(k0 + kk) * D_MODEL + e0;
            const float* vsrc = V + base + (size_t)(k0 + kk) * D_MODEL + e0;
#pragma unroll
            for (int c = 0; c < 4; ++c) {
                int e = e0 + c * 4;
                float4 tk = *(const float4*)(ksrc + c * 4);
                Kt[(e + 0) * KS + kk] = tk.x; Kt[(e + 1) * KS + kk] = tk.y;
                Kt[(e + 2) * KS + kk] = tk.z; Kt[(e + 3) * KS + kk] = tk.w;
                float4 tv = *(const float4*)(vsrc + c * 4);
                *(float4*)&Vs[kk * KS + e] = tv;
            }
        }
        __syncthreads();

        float s[8][4];
#pragma unroll
        for (int i = 0; i < 8; ++i)
#pragma unroll
            for (int j = 0; j < 4; ++j) s[i][j] = 0.f;

#pragma unroll 8
        for (int e = 0; e < 64; ++e) {
            float4 kv = *(const float4*)&Kt[e * KS + tx * 4];
            float4 qa = *(const float4*)&Qt[e * QS + ty * 8];
            float4 qb = *(const float4*)&Qt[e * QS + ty * 8 + 4];
            float qv[8] = {qa.x, qa.y, qa.z, qa.w, qb.x, qb.y, qb.z, qb.w};
            float kw[4] = {kv.x, kv.y, kv.z, kv.w};
#pragma unroll
            for (int i = 0; i < 8; ++i)
#pragma unroll
                for (int j = 0; j < 4; ++j)
                    s[i][j] = fmaf(qv[i], kw[j], s[i][j]);
        }

        if (kt >= 2 * qt) {
#pragma unroll
            for (int i = 0; i < 8; ++i) {
                int qg = q0 + ty * 8 + i;
#pragma unroll
                for (int j = 0; j < 4; ++j) {
                    int kg = k0 + tx * 4 + j;
                    float v = s[i][j] * scale;
                    s[i][j] = (kg > qg) ? -1e30f : v;
                }
            }
        } else {
#pragma unroll
            for (int i = 0; i < 8; ++i)
#pragma unroll
                for (int j = 0; j < 4; ++j) s[i][j] *= scale;
        }

#pragma unroll
        for (int i = 0; i < 8; ++i) {
            float mx = fmaxf(fmaxf(s[i][0], s[i][1]), fmaxf(s[i][2], s[i][3]));
#pragma unroll
            for (int off = 8; off >= 1; off >>= 1)
                mx = fmaxf(mx, __shfl_xor_sync(0xffffffffu, mx, off));
            float mnew = fmaxf(m_i[i], mx);
            float alpha = __expf(m_i[i] - mnew);
            m_i[i] = mnew;
            float sum = 0.f;
#pragma unroll
            for (int j = 0; j < 4; ++j) {
                s[i][j] = __expf(s[i][j] - mnew);
                sum += s[i][j];
            }
#pragma unroll
            for (int off = 8; off >= 1; off >>= 1)
                sum += __shfl_xor_sync(0xffffffffu, sum, off);
            l_i[i] = l_i[i] * alpha + sum;
#pragma unroll
            for (int j = 0; j < 4; ++j) o[i][j] *= alpha;
        }

#pragma unroll
        for (int j = 0; j < 4; ++j) {
            *(float4*)&Pt[(tx * 4 + j) * QS + ty * 8] =
                make_float4(s[0][j], s[1][j], s[2][j], s[3][j]);
            *(float4*)&Pt[(tx * 4 + j) * QS + ty * 8 + 4] =
                make_float4(s[4][j], s[5][j], s[6][j], s[7][j]);
        }
        __syncthreads();

#pragma unroll 8
        for (int kk = 0; kk < 64; ++kk) {
            float4 vv = *(const float4*)&Vs[kk * KS + tx * 4];
            float4 pa = *(const float4*)&Pt[kk * QS + ty * 8];
            float4 pb = *(const float4*)&Pt[kk * QS + ty * 8 + 4];
            float pv[8] = {pa.x, pa.y, pa.z, pa.w, pb.x, pb.y, pb.z, pb.w};
            float vw[4] = {vv.x, vv.y, vv.z, vv.w};
#pragma unroll
            for (int i = 0; i < 8; ++i)
#pragma unroll
                for (int j = 0; j < 4; ++j)
                    o[i][j] = fmaf(pv[i], vw[j], o[i][j]);
        }
    }

#pragma unroll
    for (int i = 0; i < 8; ++i) {
        float inv = 1.f / l_i[i];
        float4 r = make_float4(o[i][0] * inv, o[i][1] * inv,
                               o[i][2] * inv, o[i][3] * inv);
        *(float4*)&O[base + (size_t)(q0 + ty * 8 + i) * D_MODEL + tx * 4] = r;
    }
}

// ---------------------------------------------------------------------------
// Residual + LayerNorm over rows of 512.
// ---------------------------------------------------------------------------
__global__ __launch_bounds__(128) void residual_ln_kernel(
    const float* __restrict__ a, const float* __restrict__ b,
    const float* __restrict__ gamma, const float* __restrict__ beta,
    float* __restrict__ out)
{
    const int row = blockIdx.x;
    const int tid = threadIdx.x;
    const size_t base = (size_t)row * D_VALUE;

    float4 va = ((const float4*)(a + base))[tid];
    float4 vb = ((const float4*)(b + base))[tid];
    float4 v = make_float4(va.x + vb.x, va.y + vb.y, va.z + vb.z, va.w + vb.w);

    float s  = v.x + v.y + v.z + v.w;
    float ss = v.x * v.x + v.y * v.y + v.z * v.z + v.w * v.w;
#pragma unroll
    for (int off = 16; off >= 1; off >>= 1) {
        s  += __shfl_xor_sync(0xffffffffu, s, off);
        ss += __shfl_xor_sync(0xffffffffu, ss, off);
    }
    __shared__ float red[8];
    const int wid = tid >> 5;
    if ((tid & 31) == 0) { red[wid] = s; red[4 + wid] = ss; }
    __syncthreads();
    s  = red[0] + red[1] + red[2] + red[3];
    ss = red[4] + red[5] + red[6] + red[7];

    const float mu  = s * (1.f / (float)D_VALUE);
    float var = ss * (1.f / (float)D_VALUE) - mu * mu;
    const float rn = rsqrtf(var + 1e-5f);

    float4 g4 = ((const float4*)gamma)[tid];
    float4 b4 = ((const float4*)beta)[tid];
    float4 r;
    r.x = (v.x - mu) * rn * g4.x + b4.x;
    r.y = (v.y - mu) * rn * g4.y + b4.y;
    r.z = (v.z - mu) * rn * g4.z + b4.z;
    r.w = (v.w - mu) * rn * g4.w + b4.w;
    ((float4*)(out + base))[tid] = r;
}

// ---------------------------------------------------------------------------
// Launch
// ---------------------------------------------------------------------------
static inline void run_split(const float* x, __nv_bfloat16* hi, __nv_bfloat16* lo, int n)
{
    int n4 = n / 4;
    split_kernel<<<(n4 + 255) / 256, 256>>>(x, hi, lo, n4);
}

extern "C" void kernel_launch(void* const* d_in, const int* in_sizes, int n_in,
                              void* d_out, int out_size)
{
    const float* q   = (const float*)d_in[0];
    const float* k   = (const float*)d_in[1];
    const float* v   = (const float*)d_in[2];
    const float* Wq  = (const float*)d_in[3];
    const float* bq  = (const float*)d_in[4];
    const float* Wk  = (const float*)d_in[5];
    const float* bk  = (const float*)d_in[6];
    const float* Wv  = (const float*)d_in[7];
    const float* bv  = (const float*)d_in[8];
    const float* Wo  = (const float*)d_in[9];
    const float* bo  = (const float*)d_in[10];
    const float* Wc1 = (const float*)d_in[11];
    const float* bc1 = (const float*)d_in[12];
    const float* Wc2 = (const float*)d_in[13];
    const float* bc2 = (const float*)d_in[14];
    const float* g1  = (const float*)d_in[15];
    const float* b1  = (const float*)d_in[16];
    const float* g2  = (const float*)d_in[17];
    const float* b2  = (const float*)d_in[18];
    const float* Wl  = (const float*)d_in[19];
    const float* bl  = (const float*)d_in[20];
    float* out = (float*)d_out;

    float *Q, *K, *V, *Att, *Proj, *X, *Hh, *Y, *X2;
    __nv_bfloat16 *Ah, *Al, *Wh, *Wlo;
    cudaGetSymbolAddress((void**)&Q,    g_Q);
    cudaGetSymbolAddress((void**)&K,    g_K);
    cudaGetSymbolAddress((void**)&V,    g_V);
    cudaGetSymbolAddress((void**)&Att,  g_att);
    cudaGetSymbolAddress((void**)&Proj, g_proj);
    cudaGetSymbolAddress((void**)&X,    g_x);
    cudaGetSymbolAddress((void**)&Hh,   g_h);
    cudaGetSymbolAddress((void**)&Y,    g_y);
    cudaGetSymbolAddress((void**)&X2,   g_x2);
    cudaGetSymbolAddress((void**)&Ah,   g_Ah);
    cudaGetSymbolAddress((void**)&Al,   g_Al);
    cudaGetSymbolAddress((void**)&Wh,   g_Wh);
    cudaGetSymbolAddress((void**)&Wlo,  g_Wl);

    const dim3 blk(256);
    const dim3 grid512(D_MODEL / 128, M_ROWS / 128);   // (4, 64)
    const dim3 gridFF (D_FF   / 128, M_ROWS / 128);    // (16, 64)

    // ---- QKV projections (bf16 TC) ----
    run_split(q, Ah, Al, M_ROWS * D_MODEL);
    run_split(Wq, Wh, Wlo, D_MODEL * D_MODEL);
    gemm_bf16_kernel<false><<<grid512, blk>>>(Ah, Al, Wh, Wlo, bq, Q, M_ROWS, D_MODEL, D_MODEL);

    run_split(k, Ah, Al, M_ROWS * D_MODEL);
    run_split(Wk, Wh, Wlo, D_MODEL * D_MODEL);
    gemm_bf16_kernel<false><<<grid512, blk>>>(Ah, Al, Wh, Wlo, bk, K, M_ROWS, D_MODEL, D_MODEL);

    run_split(v, Ah, Al, M_ROWS * D_MODEL);
    run_split(Wv, Wh, Wlo, D_MODEL * D_MODEL);
    gemm_bf16_kernel<false><<<grid512, blk>>>(Ah, Al, Wh, Wlo, bv, V, M_ROWS, D_MODEL, D_MODEL);

    // ---- causal attention (fp32) ----
    int smem = (64 * QS + 64 * KS + 64 * KS + 64 * QS) * (int)sizeof(float);
    cudaFuncSetAttribute(attn_kernel, cudaFuncAttributeMaxDynamicSharedMemorySize, smem);
    attn_kernel<<<dim3(SEQ_L / BQ, N_HEADS, B_BATCH), blk, smem>>>(Q, K, V, Att);

    // ---- output projection ----
    run_split(Att, Ah, Al, M_ROWS * D_MODEL);
    run_split(Wo, Wh, Wlo, D_MODEL * D_VALUE);
    gemm_bf16_kernel<false><<<grid512, blk>>>(Ah, Al, Wh, Wlo, bo, Proj, M_ROWS, D_MODEL, D_MODEL);

    // ---- residual + LN1 ----
    residual_ln_kernel<<<M_ROWS, 128>>>(v, Proj, g1, b1, X);

    // ---- FFN ----
    run_split(X, Ah, Al, M_ROWS * D_VALUE);
    run_split(Wc1, Wh, Wlo, D_FF * D_VALUE);
    gemm_bf16_kernel<true><<<gridFF, blk>>>(Ah, Al, Wh, Wlo, bc1, Hh, M_ROWS, D_FF, D_VALUE);

    run_split(Hh, Ah, Al, M_ROWS * D_FF);
    run_split(Wc2, Wh, Wlo, D_VALUE * D_FF);
    gemm_bf16_kernel<false><<<grid512, blk>>>(Ah, Al, Wh, Wlo, bc2, Y, M_ROWS, D_VALUE, D_FF);

    // ---- residual + LN2 ----
    residual_ln_kernel<<<M_ROWS, 128>>>(X, Y, g2, b2, X2);

    // ---- final projection ----
    run_split(X2, Ah, Al, M_ROWS * D_VALUE);
    run_split(Wl, Wh, Wlo, D_MODEL * D_VALUE);
    gemm_bf16_kernel<false><<<grid512, blk>>>(Ah, Al, Wh, Wlo, bl, out, M_ROWS, D_MODEL, D_VALUE);
}

// round 7
// speedup vs baseline: 2.0219x; 1.4098x over previous
#include <cuda_runtime.h>
#include <cuda_bf16.h>
#include <cstdint>

// ---------------------------------------------------------------------------
// Problem constants
// ---------------------------------------------------------------------------
#define B_BATCH 4
#define SEQ_L   2048
#define D_MODEL 512
#define D_VALUE 512
#define N_HEADS 8
#define HEAD_E  64
#define D_FF    2048
#define M_ROWS  (B_BATCH * SEQ_L)   // 8192

// ---------------------------------------------------------------------------
// Scratch (static device allocations)
// ---------------------------------------------------------------------------
__device__ float g_proj[M_ROWS * D_MODEL];
__device__ float g_x   [M_ROWS * D_VALUE];
__device__ float g_y   [M_ROWS * D_VALUE];

__device__ __nv_bfloat16 g_Ah [M_ROWS * D_MODEL];
__device__ __nv_bfloat16 g_Al [M_ROWS * D_MODEL];
__device__ __nv_bfloat16 g_Wh [D_FF * D_VALUE];
__device__ __nv_bfloat16 g_Wl [D_FF * D_VALUE];

__device__ __nv_bfloat16 g_Qh [M_ROWS * D_MODEL];
__device__ __nv_bfloat16 g_Ql [M_ROWS * D_MODEL];
__device__ __nv_bfloat16 g_Kh [M_ROWS * D_MODEL];
__device__ __nv_bfloat16 g_Kl [M_ROWS * D_MODEL];
__device__ __nv_bfloat16 g_Vh [M_ROWS * D_MODEL];
__device__ __nv_bfloat16 g_Vl [M_ROWS * D_MODEL];
__device__ __nv_bfloat16 g_Vth[M_ROWS * D_MODEL];   // [B][H][E][L]
__device__ __nv_bfloat16 g_Vtl[M_ROWS * D_MODEL];
__device__ __nv_bfloat16 g_Oh [M_ROWS * D_MODEL];
__device__ __nv_bfloat16 g_Ol [M_ROWS * D_MODEL];
__device__ __nv_bfloat16 g_Xh [M_ROWS * D_VALUE];
__device__ __nv_bfloat16 g_Xl [M_ROWS * D_VALUE];
__device__ __nv_bfloat16 g_Fh [M_ROWS * D_FF];
__device__ __nv_bfloat16 g_Fl [M_ROWS * D_FF];
__device__ __nv_bfloat16 g_X2h[M_ROWS * D_VALUE];
__device__ __nv_bfloat16 g_X2l[M_ROWS * D_VALUE];

// ---------------------------------------------------------------------------
// helpers
// ---------------------------------------------------------------------------
__device__ __forceinline__ void split2(float x, float y, uint32_t& hi, uint32_t& lo)
{
    __nv_bfloat16 hx = __float2bfloat16_rn(x);
    __nv_bfloat16 hy = __float2bfloat16_rn(y);
    __nv_bfloat162 h2 = __halves2bfloat162(hx, hy);
    __nv_bfloat162 l2 = __halves2bfloat162(
        __float2bfloat16_rn(x - __bfloat162float(hx)),
        __float2bfloat16_rn(y - __bfloat162float(hy)));
    hi = *reinterpret_cast<uint32_t*>(&h2);
    lo = *reinterpret_cast<uint32_t*>(&l2);
}

__device__ __forceinline__ void mma_bf16(
    float& d0, float& d1, float& d2, float& d3,
    uint32_t a0, uint32_t a1, uint32_t a2, uint32_t a3,
    uint32_t b0, uint32_t b1)
{
    asm volatile(
        "mma.sync.aligned.m16n8k16.row.col.f32.bf16.bf16.f32 "
        "{%0,%1,%2,%3}, {%4,%5,%6,%7}, {%8,%9}, {%0,%1,%2,%3};"
        : "+f"(d0), "+f"(d1), "+f"(d2), "+f"(d3)
        : "r"(a0), "r"(a1), "r"(a2), "r"(a3), "r"(b0), "r"(b1));
}

// ---------------------------------------------------------------------------
// Split fp32 -> bf16 hi + bf16 lo
// ---------------------------------------------------------------------------
__global__ __launch_bounds__(256) void split_kernel(
    const float* __restrict__ x,
    __nv_bfloat16* __restrict__ hi, __nv_bfloat16* __restrict__ lo, int n4)
{
    int i = blockIdx.x * 256 + threadIdx.x;
    if (i >= n4) return;
    float4 v = ((const float4*)x)[i];
    uint32_t h0, l0, h1, l1;
    split2(v.x, v.y, h0, l0);
    split2(v.z, v.w, h1, l1);
    ((uint32_t*)hi)[2 * i]     = h0;
    ((uint32_t*)hi)[2 * i + 1] = h1;
    ((uint32_t*)lo)[2 * i]     = l0;
    ((uint32_t*)lo)[2 * i + 1] = l1;
}

// ---------------------------------------------------------------------------
// bf16 TC GEMM with hi/lo compensation: C = A @ W^T + bias (opt ReLU)
// SPLIT: false -> fp32 C; true -> bf16 hi/lo pair Ch/Cl
// ---------------------------------------------------------------------------
#define GS 40

template<bool RELU, bool SPLIT>
__global__ __launch_bounds__(256) void gemm_bf16_kernel(
    const __nv_bfloat16* __restrict__ Ah, const __nv_bfloat16* __restrict__ Al,
    const __nv_bfloat16* __restrict__ Bh, const __nv_bfloat16* __restrict__ Bl,
    const float* __restrict__ bias, float* __restrict__ C,
    __nv_bfloat16* __restrict__ Ch, __nv_bfloat16* __restrict__ Cl,
    int M, int N, int K)
{
    __shared__ __nv_bfloat16 sAh[128 * GS];
    __shared__ __nv_bfloat16 sAl[128 * GS];
    __shared__ __nv_bfloat16 sBh[128 * GS];
    __shared__ __nv_bfloat16 sBl[128 * GS];

    const int tid  = threadIdx.x;
    const int lane = tid & 31;
    const int warp = tid >> 5;
    const int wm = (warp & 1) * 64;
    const int wn = (warp >> 1) * 32;
    const int m0 = blockIdx.y * 128;
    const int n0 = blockIdx.x * 128;

    const int lrow = tid >> 1;
    const int lch  = (tid & 1) * 16;

    const __nv_bfloat16* gAh = Ah + (size_t)(m0 + lrow) * K + lch;
    const __nv_bfloat16* gAl = Al + (size_t)(m0 + lrow) * K + lch;
    const __nv_bfloat16* gBh = Bh + (size_t)(n0 + lrow) * K + lch;
    const __nv_bfloat16* gBl = Bl + (size_t)(n0 + lrow) * K + lch;

    float acc[4][4][4];
#pragma unroll
    for (int mi = 0; mi < 4; ++mi)
#pragma unroll
        for (int ni = 0; ni < 4; ++ni)
#pragma unroll
            for (int r = 0; r < 4; ++r) acc[mi][ni][r] = 0.f;

    int4 rAh0 = *(const int4*)(gAh),     rAh1 = *(const int4*)(gAh + 8);
    int4 rAl0 = *(const int4*)(gAl),     rAl1 = *(const int4*)(gAl + 8);
    int4 rBh0 = *(const int4*)(gBh),     rBh1 = *(const int4*)(gBh + 8);
    int4 rBl0 = *(const int4*)(gBl),     rBl1 = *(const int4*)(gBl + 8);

    const int arow = (lane >> 2);
    const int acol = 2 * (lane & 3);

    for (int k0 = 0; k0 < K; k0 += 32) {
        __syncthreads();
        {
            const int so = lrow * GS + lch;
            *(int4*)&sAh[so] = rAh0; *(int4*)&sAh[so + 8] = rAh1;
            *(int4*)&sAl[so] = rAl0; *(int4*)&sAl[so + 8] = rAl1;
            *(int4*)&sBh[so] = rBh0; *(int4*)&sBh[so + 8] = rBh1;
            *(int4*)&sBl[so] = rBl0; *(int4*)&sBl[so + 8] = rBl1;
        }
        __syncthreads();
        if (k0 + 32 < K) {
            const int go = k0 + 32;
            rAh0 = *(const int4*)(gAh + go); rAh1 = *(const int4*)(gAh + go + 8);
            rAl0 = *(const int4*)(gAl + go); rAl1 = *(const int4*)(gAl + go + 8);
            rBh0 = *(const int4*)(gBh + go); rBh1 = *(const int4*)(gBh + go + 8);
            rBl0 = *(const int4*)(gBl + go); rBl1 = *(const int4*)(gBl + go + 8);
        }

#pragma unroll
        for (int ks = 0; ks < 2; ++ks) {
            const int kc = ks * 16 + acol;
            uint32_t aH[4][4], aL[4][4], bH[4][2], bL[4][2];
#pragma unroll
            for (int mi = 0; mi < 4; ++mi) {
                const int off = (wm + mi * 16 + arow) * GS + kc;
                aH[mi][0] = *(const uint32_t*)&sAh[off];
                aH[mi][1] = *(const uint32_t*)&sAh[off + 8 * GS];
                aH[mi][2] = *(const uint32_t*)&sAh[off + 8];
                aH[mi][3] = *(const uint32_t*)&sAh[off + 8 * GS + 8];
                aL[mi][0] = *(const uint32_t*)&sAl[off];
                aL[mi][1] = *(const uint32_t*)&sAl[off + 8 * GS];
                aL[mi][2] = *(const uint32_t*)&sAl[off + 8];
                aL[mi][3] = *(const uint32_t*)&sAl[off + 8 * GS + 8];
            }
#pragma unroll
            for (int ni = 0; ni < 4; ++ni) {
                const int off = (wn + ni * 8 + arow) * GS + kc;
                bH[ni][0] = *(const uint32_t*)&sBh[off];
                bH[ni][1] = *(const uint32_t*)&sBh[off + 8];
                bL[ni][0] = *(const uint32_t*)&sBl[off];
                bL[ni][1] = *(const uint32_t*)&sBl[off + 8];
            }
#pragma unroll
            for (int mi = 0; mi < 4; ++mi)
#pragma unroll
                for (int ni = 0; ni < 4; ++ni) {
                    float* d = acc[mi][ni];
                    mma_bf16(d[0], d[1], d[2], d[3],
                             aH[mi][0], aH[mi][1], aH[mi][2], aH[mi][3],
                             bH[ni][0], bH[ni][1]);
                    mma_bf16(d[0], d[1], d[2], d[3],
                             aH[mi][0], aH[mi][1], aH[mi][2], aH[mi][3],
                             bL[ni][0], bL[ni][1]);
                    mma_bf16(d[0], d[1], d[2], d[3],
                             aL[mi][0], aL[mi][1], aL[mi][2], aL[mi][3],
                             bH[ni][0], bH[ni][1]);
                }
        }
    }

#pragma unroll
    for (int mi = 0; mi < 4; ++mi) {
        const int m = m0 + wm + mi * 16 + (lane >> 2);
#pragma unroll
        for (int ni = 0; ni < 4; ++ni) {
            const int nc = n0 + wn + ni * 8 + 2 * (lane & 3);
            float b0 = bias[nc], b1 = bias[nc + 1];
            float c0 = acc[mi][ni][0] + b0, c1 = acc[mi][ni][1] + b1;
            float c2 = acc[mi][ni][2] + b0, c3 = acc[mi][ni][3] + b1;
            if (RELU) {
                c0 = fmaxf(c0, 0.f); c1 = fmaxf(c1, 0.f);
                c2 = fmaxf(c2, 0.f); c3 = fmaxf(c3, 0.f);
            }
            if (!SPLIT) {
                *(float2*)&C[(size_t)m * N + nc]       = make_float2(c0, c1);
                *(float2*)&C[(size_t)(m + 8) * N + nc] = make_float2(c2, c3);
            } else {
                uint32_t h0, l0, h1, l1;
                split2(c0, c1, h0, l0);
                split2(c2, c3, h1, l1);
                *(uint32_t*)&Ch[(size_t)m * N + nc]       = h0;
                *(uint32_t*)&Cl[(size_t)m * N + nc]       = l0;
                *(uint32_t*)&Ch[(size_t)(m + 8) * N + nc] = h1;
                *(uint32_t*)&Cl[(size_t)(m + 8) * N + nc] = l1;
            }
        }
    }
}

// ---------------------------------------------------------------------------
// V transpose: Vh/Vl [token][512] -> Vth/Vtl [B][H][E=64][L=2048]
// Each thread handles one 64x64 tile row-segment of 16 elems.
// ---------------------------------------------------------------------------
__global__ __launch_bounds__(256) void vtrans_kernel(
    const __nv_bfloat16* __restrict__ Vh, const __nv_bfloat16* __restrict__ Vl,
    __nv_bfloat16* __restrict__ Vth, __nv_bfloat16* __restrict__ Vtl)
{
    __shared__ __nv_bfloat16 th[64][72];
    __shared__ __nv_bfloat16 tl[64][72];
    const int lt = blockIdx.x, h = blockIdx.y, b = blockIdx.z;
    const int t = threadIdx.x;
    {
        int l = t >> 2, e0 = (t & 3) * 16;
        size_t g = ((size_t)(b * SEQ_L + lt * 64 + l)) * D_MODEL + h * 64 + e0;
        int4 a0 = *(const int4*)(Vh + g);
        int4 a1 = *(const int4*)(Vh + g + 8);
        *(int4*)&th[l][e0]     = a0;
        *(int4*)&th[l][e0 + 8] = a1;
        int4 c0 = *(const int4*)(Vl + g);
        int4 c1 = *(const int4*)(Vl + g + 8);
        *(int4*)&tl[l][e0]     = c0;
        *(int4*)&tl[l][e0 + 8] = c1;
    }
    __syncthreads();
    {
        int e = t >> 2, l0 = (t & 3) * 16;
        __align__(16) __nv_bfloat16 buf[16], buf2[16];
#pragma unroll
        for (int i = 0; i < 16; ++i) { buf[i] = th[l0 + i][e]; buf2[i] = tl[l0 + i][e]; }
        size_t g = ((size_t)((b * N_HEADS + h) * 64 + e)) * SEQ_L + lt * 64 + l0;
        ((int4*)(Vth + g))[0] = ((int4*)buf)[0];
        ((int4*)(Vth + g))[1] = ((int4*)buf)[1];
        ((int4*)(Vtl + g))[0] = ((int4*)buf2)[0];
        ((int4*)(Vtl + g))[1] = ((int4*)buf2)[1];
    }
}

// ---------------------------------------------------------------------------
// Tensor-core causal flash attention, hi/lo compensated bf16.
// 128q x 64k tile, 8 warps, m16n8k16. Output written as bf16 hi/lo.
// ---------------------------------------------------------------------------
#define AT_S 72

__global__ __launch_bounds__(256, 1) void attn_mma_kernel(
    const __nv_bfloat16* __restrict__ Qh, const __nv_bfloat16* __restrict__ Ql,
    const __nv_bfloat16* __restrict__ Kh, const __nv_bfloat16* __restrict__ Kl,
    const __nv_bfloat16* __restrict__ Vth, const __nv_bfloat16* __restrict__ Vtl,
    __nv_bfloat16* __restrict__ Oh, __nv_bfloat16* __restrict__ Ol)
{
    extern __shared__ __nv_bfloat16 smb[];
    __nv_bfloat16* sQh = smb;
    __nv_bfloat16* sQl = sQh + 128 * AT_S;
    __nv_bfloat16* sKh = sQl + 128 * AT_S;
    __nv_bfloat16* sKl = sKh + 64 * AT_S;
    __nv_bfloat16* sVh = sKl + 64 * AT_S;
    __nv_bfloat16* sVl = sVh + 64 * AT_S;

    const int tid = threadIdx.x, lane = tid & 31, warp = tid >> 5;
    const int qt = blockIdx.x, h = blockIdx.y, b = blockIdx.z;
    const int q0 = qt * 128;
    const size_t qkBase = ((size_t)b * SEQ_L) * D_MODEL + (size_t)h * HEAD_E;
    const size_t vtBase = ((size_t)(b * N_HEADS + h)) * HEAD_E * SEQ_L;

    // ---- load Q tile to smem: 128 rows x 64 cols, 32 elems/thread ----
    {
        int row = tid >> 1, e0 = (tid & 1) * 32;
        size_t g = qkBase + (size_t)(q0 + row) * D_MODEL + e0;
        int4 a0 = *(const int4*)(Qh + g);
        int4 a1 = *(const int4*)(Qh + g + 8);
        int4 a2 = *(const int4*)(Qh + g + 16);
        int4 a3 = *(const int4*)(Qh + g + 24);
        int4* d = (int4*)(sQh + row * AT_S + e0);
        d[0] = a0; d[1] = a1; d[2] = a2; d[3] = a3;
        int4 c0 = *(const int4*)(Ql + g);
        int4 c1 = *(const int4*)(Ql + g + 8);
        int4 c2 = *(const int4*)(Ql + g + 16);
        int4 c3 = *(const int4*)(Ql + g + 24);
        int4* d2 = (int4*)(sQl + row * AT_S + e0);
        d2[0] = c0; d2[1] = c1; d2[2] = c2; d2[3] = c3;
    }

    // per-thread softmax state (rows gr = warp*16 + lane/4, gr+8)
    float m0 = -1e30f, m1 = -1e30f, l0s = 0.f, l1s = 0.f;
    float oacc[8][4];
#pragma unroll
    for (int nt = 0; nt < 8; ++nt)
#pragma unroll
        for (int r = 0; r < 4; ++r) oacc[nt][r] = 0.f;

    const int ldr = tid >> 2;            // tile load row (0..63)
    const int ldc = (tid & 3) * 16;      // tile load col (16 elems/thread)
    const int nkt = 2 * qt + 2;

    // prefetch tile 0 (K: [64k x 64e], V^T: [64e x 64k])
    int4 pKh0, pKh1, pKl0, pKl1, pVh0, pVh1, pVl0, pVl1;
    {
        size_t gk = qkBase + (size_t)(0 + ldr) * D_MODEL + ldc;
        pKh0 = *(const int4*)(Kh + gk);  pKh1 = *(const int4*)(Kh + gk + 8);
        pKl0 = *(const int4*)(Kl + gk);  pKl1 = *(const int4*)(Kl + gk + 8);
        size_t gv = vtBase + (size_t)ldr * SEQ_L + 0 + ldc;
        pVh0 = *(const int4*)(Vth + gv); pVh1 = *(const int4*)(Vth + gv + 8);
        pVl0 = *(const int4*)(Vtl + gv); pVl1 = *(const int4*)(Vtl + gv + 8);
    }

    const int gr  = warp * 16 + (lane >> 2);
    const int cc  = 2 * (lane & 3);

    for (int kt = 0; kt < nkt; ++kt) {
        const int k0 = kt * 64;
        __syncthreads();
        {
            int4* d;
            d = (int4*)(sKh + ldr * AT_S + ldc); d[0] = pKh0; d[1] = pKh1;
            d = (int4*)(sKl + ldr * AT_S + ldc); d[0] = pKl0; d[1] = pKl1;
            d = (int4*)(sVh + ldr * AT_S + ldc); d[0] = pVh0; d[1] = pVh1;
            d = (int4*)(sVl + ldr * AT_S + ldc); d[0] = pVl0; d[1] = pVl1;
        }
        __syncthreads();
        if (kt + 1 < nkt) {
            size_t gk = qkBase + (size_t)(k0 + 64 + ldr) * D_MODEL + ldc;
            pKh0 = *(const int4*)(Kh + gk);  pKh1 = *(const int4*)(Kh + gk + 8);
            pKl0 = *(const int4*)(Kl + gk);  pKl1 = *(const int4*)(Kl + gk + 8);
            size_t gv = vtBase + (size_t)ldr * SEQ_L + k0 + 64 + ldc;
            pVh0 = *(const int4*)(Vth + gv); pVh1 = *(const int4*)(Vth + gv + 8);
            pVl0 = *(const int4*)(Vtl + gv); pVl1 = *(const int4*)(Vtl + gv + 8);
        }

        // ---- S = Q K^T ----
        float sacc[8][4];
#pragma unroll
        for (int nt = 0; nt < 8; ++nt)
#pragma unroll
            for (int r = 0; r < 4; ++r) sacc[nt][r] = 0.f;

#pragma unroll
        for (int es = 0; es < 4; ++es) {
            const int e = es * 16 + cc;
            uint32_t ah0 = *(const uint32_t*)&sQh[gr * AT_S + e];
            uint32_t ah1 = *(const uint32_t*)&sQh[(gr + 8) * AT_S + e];
            uint32_t ah2 = *(const uint32_t*)&sQh[gr * AT_S + e + 8];
            uint32_t ah3 = *(const uint32_t*)&sQh[(gr + 8) * AT_S + e + 8];
            uint32_t al0 = *(const uint32_t*)&sQl[gr * AT_S + e];
            uint32_t al1 = *(const uint32_t*)&sQl[(gr + 8) * AT_S + e];
            uint32_t al2 = *(const uint32_t*)&sQl[gr * AT_S + e + 8];
            uint32_t al3 = *(const uint32_t*)&sQl[(gr + 8) * AT_S + e + 8];
#pragma unroll
            for (int nt = 0; nt < 8; ++nt) {
                const int n = nt * 8 + (lane >> 2);
                uint32_t bh0 = *(const uint32_t*)&sKh[n * AT_S + e];
                uint32_t bh1 = *(const uint32_t*)&sKh[n * AT_S + e + 8];
                uint32_t bl0 = *(const uint32_t*)&sKl[n * AT_S + e];
                uint32_t bl1 = *(const uint32_t*)&sKl[n * AT_S + e + 8];
                float* dd = sacc[nt];
                mma_bf16(dd[0], dd[1], dd[2], dd[3], ah0, ah1, ah2, ah3, bh0, bh1);
                mma_bf16(dd[0], dd[1], dd[2], dd[3], ah0, ah1, ah2, ah3, bl0, bl1);
                mma_bf16(dd[0], dd[1], dd[2], dd[3], al0, al1, al2, al3, bh0, bh1);
            }
        }

        // ---- scale + causal mask ----
        const float scl = 0.125f;
        if (kt >= 2 * qt) {
            const int qg0 = q0 + gr, qg1 = qg0 + 8;
#pragma unroll
            for (int nt = 0; nt < 8; ++nt) {
                const int kg = k0 + nt * 8 + cc;
                sacc[nt][0] = (kg     > qg0) ? -1e30f : sacc[nt][0] * scl;
                sacc[nt][1] = (kg + 1 > qg0) ? -1e30f : sacc[nt][1] * scl;
                sacc[nt][2] = (kg     > qg1) ? -1e30f : sacc[nt][2] * scl;
                sacc[nt][3] = (kg + 1 > qg1) ? -1e30f : sacc[nt][3] * scl;
            }
        } else {
#pragma unroll
            for (int nt = 0; nt < 8; ++nt) {
                sacc[nt][0] *= scl; sacc[nt][1] *= scl;
                sacc[nt][2] *= scl; sacc[nt][3] *= scl;
            }
        }

        // ---- online softmax (row groups of 4 lanes: xor 1, 2) ----
        float mx0 = -1e30f, mx1 = -1e30f;
#pragma unroll
        for (int nt = 0; nt < 8; ++nt) {
            mx0 = fmaxf(mx0, fmaxf(sacc[nt][0], sacc[nt][1]));
            mx1 = fmaxf(mx1, fmaxf(sacc[nt][2], sacc[nt][3]));
        }
        mx0 = fmaxf(mx0, __shfl_xor_sync(0xffffffffu, mx0, 1));
        mx0 = fmaxf(mx0, __shfl_xor_sync(0xffffffffu, mx0, 2));
        mx1 = fmaxf(mx1, __shfl_xor_sync(0xffffffffu, mx1, 1));
        mx1 = fmaxf(mx1, __shfl_xor_sync(0xffffffffu, mx1, 2));
        const float mn0 = fmaxf(m0, mx0), mn1 = fmaxf(m1, mx1);
        const float a0 = __expf(m0 - mn0), a1 = __expf(m1 - mn1);
        m0 = mn0; m1 = mn1;

        float s0 = 0.f, s1 = 0.f;
        uint32_t pH[4][4], pL[4][4];
#pragma unroll
        for (int ks = 0; ks < 4; ++ks) {
            const int n0t = 2 * ks, n1t = 2 * ks + 1;
            float p00 = __expf(sacc[n0t][0] - mn0);
            float p01 = __expf(sacc[n0t][1] - mn0);
            float p10 = __expf(sacc[n0t][2] - mn1);
            float p11 = __expf(sacc[n0t][3] - mn1);
            float p20 = __expf(sacc[n1t][0] - mn0);
            float p21 = __expf(sacc[n1t][1] - mn0);
            float p30 = __expf(sacc[n1t][2] - mn1);
            float p31 = __expf(sacc[n1t][3] - mn1);
            s0 += p00 + p01 + p20 + p21;
            s1 += p10 + p11 + p30 + p31;
            split2(p00, p01, pH[ks][0], pL[ks][0]);
            split2(p10, p11, pH[ks][1], pL[ks][1]);
            split2(p20, p21, pH[ks][2], pL[ks][2]);
            split2(p30, p31, pH[ks][3], pL[ks][3]);
        }
        s0 += __shfl_xor_sync(0xffffffffu, s0, 1);
        s0 += __shfl_xor_sync(0xffffffffu, s0, 2);
        s1 += __shfl_xor_sync(0xffffffffu, s1, 1);
        s1 += __shfl_xor_sync(0xffffffffu, s1, 2);
        l0s = l0s * a0 + s0;
        l1s = l1s * a1 + s1;
#pragma unroll
        for (int nt = 0; nt < 8; ++nt) {
            oacc[nt][0] *= a0; oacc[nt][1] *= a0;
            oacc[nt][2] *= a1; oacc[nt][3] *= a1;
        }

        // ---- O += P V ----
#pragma unroll
        for (int ks = 0; ks < 4; ++ks) {
            const int kk = ks * 16 + cc;
#pragma unroll
            for (int nt = 0; nt < 8; ++nt) {
                const int n = nt * 8 + (lane >> 2);
                uint32_t bh0 = *(const uint32_t*)&sVh[n * AT_S + kk];
                uint32_t bh1 = *(const uint32_t*)&sVh[n * AT_S + kk + 8];
                uint32_t bl0 = *(const uint32_t*)&sVl[n * AT_S + kk];
                uint32_t bl1 = *(const uint32_t*)&sVl[n * AT_S + kk + 8];
                float* dd = oacc[nt];
                mma_bf16(dd[0], dd[1], dd[2], dd[3],
                         pH[ks][0], pH[ks][1], pH[ks][2], pH[ks][3], bh0, bh1);
                mma_bf16(dd[0], dd[1], dd[2], dd[3],
                         pH[ks][0], pH[ks][1], pH[ks][2], pH[ks][3], bl0, bl1);
                mma_bf16(dd[0], dd[1], dd[2], dd[3],
                         pL[ks][0], pL[ks][1], pL[ks][2], pL[ks][3], bh0, bh1);
            }
        }
    }

    // ---- epilogue: normalize, split, store ----
    const float inv0 = 1.f / l0s, inv1 = 1.f / l1s;
    const size_t r0 = qkBase + (size_t)(q0 + gr) * D_MODEL + cc;
    const size_t r1 = r0 + 8 * D_MODEL;
#pragma unroll
    for (int nt = 0; nt < 8; ++nt) {
        uint32_t h0, lo0, h1, lo1;
        split2(oacc[nt][0] * inv0, oacc[nt][1] * inv0, h0, lo0);
        split2(oacc[nt][2] * inv1, oacc[nt][3] * inv1, h1, lo1);
        *(uint32_t*)&Oh[r0 + nt * 8] = h0;
        *(uint32_t*)&Ol[r0 + nt * 8] = lo0;
        *(uint32_t*)&Oh[r1 + nt * 8] = h1;
        *(uint32_t*)&Ol[r1 + nt * 8] = lo1;
    }
}

// ---------------------------------------------------------------------------
// Residual + LayerNorm (rows of 512); optional fp32 out + optional split out
// ---------------------------------------------------------------------------
template<bool F32OUT, bool SPLITOUT>
__global__ __launch_bounds__(128) void residual_ln_kernel(
    const float* __restrict__ a, const float* __restrict__ b,
    const float* __restrict__ gamma, const float* __restrict__ beta,
    float* __restrict__ out,
    __nv_bfloat16* __restrict__ outh, __nv_bfloat16* __restrict__ outl)
{
    const int row = blockIdx.x;
    const int tid = threadIdx.x;
    const size_t base = (size_t)row * D_VALUE;

    float4 va = ((const float4*)(a + base))[tid];
    float4 vb = ((const float4*)(b + base))[tid];
    float4 v = make_float4(va.x + vb.x, va.y + vb.y, va.z + vb.z, va.w + vb.w);

    float s  = v.x + v.y + v.z + v.w;
    float ss = v.x * v.x + v.y * v.y + v.z * v.z + v.w * v.w;
#pragma unroll
    for (int off = 16; off >= 1; off >>= 1) {
        s  += __shfl_xor_sync(0xffffffffu, s, off);
        ss += __shfl_xor_sync(0xffffffffu, ss, off);
    }
    __shared__ float red[8];
    const int wid = tid >> 5;
    if ((tid & 31) == 0) { red[wid] = s; red[4 + wid] = ss; }
    __syncthreads();
    s  = red[0] + red[1] + red[2] + red[3];
    ss = red[4] + red[5] + red[6] + red[7];

    const float mu = s * (1.f / (float)D_VALUE);
    float var = ss * (1.f / (float)D_VALUE) - mu * mu;
    const float rn = rsqrtf(var + 1e-5f);

    float4 g4 = ((const float4*)gamma)[tid];
    float4 b4 = ((const float4*)beta)[tid];
    float4 r;
    r.x = (v.x - mu) * rn * g4.x + b4.x;
    r.y = (v.y - mu) * rn * g4.y + b4.y;
    r.z = (v.z - mu) * rn * g4.z + b4.z;
    r.w = (v.w - mu) * rn * g4.w + b4.w;
    if (F32OUT) ((float4*)(out + base))[tid] = r;
    if (SPLITOUT) {
        uint32_t h0, l0, h1, l1;
        split2(r.x, r.y, h0, l0);
        split2(r.z, r.w, h1, l1);
        ((uint32_t*)(outh + base))[2 * tid]     = h0;
        ((uint32_t*)(outh + base))[2 * tid + 1] = h1;
        ((uint32_t*)(outl + base))[2 * tid]     = l0;
        ((uint32_t*)(outl + base))[2 * tid + 1] = l1;
    }
}

// ---------------------------------------------------------------------------
// Launch
// ---------------------------------------------------------------------------
static inline void run_split(const float* x, __nv_bfloat16* hi, __nv_bfloat16* lo, int n)
{
    int n4 = n / 4;
    split_kernel<<<(n4 + 255) / 256, 256>>>(x, hi, lo, n4);
}

extern "C" void kernel_launch(void* const* d_in, const int* in_sizes, int n_in,
                              void* d_out, int out_size)
{
    const float* q   = (const float*)d_in[0];
    const float* k   = (const float*)d_in[1];
    const float* v   = (const float*)d_in[2];
    const float* Wq  = (const float*)d_in[3];
    const float* bq  = (const float*)d_in[4];
    const float* Wk  = (const float*)d_in[5];
    const float* bk  = (const float*)d_in[6];
    const float* Wv  = (const float*)d_in[7];
    const float* bv  = (const float*)d_in[8];
    const float* Wo  = (const float*)d_in[9];
    const float* bo  = (const float*)d_in[10];
    const float* Wc1 = (const float*)d_in[11];
    const float* bc1 = (const float*)d_in[12];
    const float* Wc2 = (const float*)d_in[13];
    const float* bc2 = (const float*)d_in[14];
    const float* g1  = (const float*)d_in[15];
    const float* b1  = (const float*)d_in[16];
    const float* g2  = (const float*)d_in[17];
    const float* b2  = (const float*)d_in[18];
    const float* Wl  = (const float*)d_in[19];
    const float* bl  = (const float*)d_in[20];
    float* out = (float*)d_out;

    float *Proj, *X, *Y;
    __nv_bfloat16 *Ah, *Al, *Wh, *Wlo, *Qh, *Ql, *Kh, *Kl, *Vh, *Vl;
    __nv_bfloat16 *Vth, *Vtl, *Ohp, *Olp, *Xh, *Xl, *Fh, *Fl, *X2h, *X2l;
    cudaGetSymbolAddress((void**)&Proj, g_proj);
    cudaGetSymbolAddress((void**)&X,    g_x);
    cudaGetSymbolAddress((void**)&Y,    g_y);
    cudaGetSymbolAddress((void**)&Ah,   g_Ah);
    cudaGetSymbolAddress((void**)&Al,   g_Al);
    cudaGetSymbolAddress((void**)&Wh,   g_Wh);
    cudaGetSymbolAddress((void**)&Wlo,  g_Wl);
    cudaGetSymbolAddress((void**)&Qh,   g_Qh);
    cudaGetSymbolAddress((void**)&Ql,   g_Ql);
    cudaGetSymbolAddress((void**)&Kh,   g_Kh);
    cudaGetSymbolAddress((void**)&Kl,   g_Kl);
    cudaGetSymbolAddress((void**)&Vh,   g_Vh);
    cudaGetSymbolAddress((void**)&Vl,   g_Vl);
    cudaGetSymbolAddress((void**)&Vth,  g_Vth);
    cudaGetSymbolAddress((void**)&Vtl,  g_Vtl);
    cudaGetSymbolAddress((void**)&Ohp,  g_Oh);
    cudaGetSymbolAddress((void**)&Olp,  g_Ol);
    cudaGetSymbolAddress((void**)&Xh,   g_Xh);
    cudaGetSymbolAddress((void**)&Xl,   g_Xl);
    cudaGetSymbolAddress((void**)&Fh,   g_Fh);
    cudaGetSymbolAddress((void**)&Fl,   g_Fl);
    cudaGetSymbolAddress((void**)&X2h,  g_X2h);
    cudaGetSymbolAddress((void**)&X2l,  g_X2l);

    const dim3 blk(256);
    const dim3 grid512(D_MODEL / 128, M_ROWS / 128);   // (4, 64)
    const dim3 gridFF (D_FF   / 128, M_ROWS / 128);    // (16, 64)

    // ---- QKV projections -> split bf16 outputs ----
    run_split(q, Ah, Al, M_ROWS * D_MODEL);
    run_split(Wq, Wh, Wlo, D_MODEL * D_MODEL);
    gemm_bf16_kernel<false, true><<<grid512, blk>>>(Ah, Al, Wh, Wlo, bq,
        nullptr, Qh, Ql, M_ROWS, D_MODEL, D_MODEL);

    run_split(k, Ah, Al, M_ROWS * D_MODEL);
    run_split(Wk, Wh, Wlo, D_MODEL * D_MODEL);
    gemm_bf16_kernel<false, true><<<grid512, blk>>>(Ah, Al, Wh, Wlo, bk,
        nullptr, Kh, Kl, M_ROWS, D_MODEL, D_MODEL);

    run_split(v, Ah, Al, M_ROWS * D_MODEL);
    run_split(Wv, Wh, Wlo, D_MODEL * D_MODEL);
    gemm_bf16_kernel<false, true><<<grid512, blk>>>(Ah, Al, Wh, Wlo, bv,
        nullptr, Vh, Vl, M_ROWS, D_MODEL, D_MODEL);

    // ---- V transpose per head ----
    vtrans_kernel<<<dim3(SEQ_L / 64, N_HEADS, B_BATCH), blk>>>(Vh, Vl, Vth, Vtl);

    // ---- attention (tensor cores) ----
    {
        int smem = (2 * 128 + 4 * 64) * AT_S * 2;  // 73728 B
        cudaFuncSetAttribute(attn_mma_kernel,
                             cudaFuncAttributeMaxDynamicSharedMemorySize, smem);
        attn_mma_kernel<<<dim3(SEQ_L / 128, N_HEADS, B_BATCH), blk, smem>>>(
            Qh, Ql, Kh, Kl, Vth, Vtl, Ohp, Olp);
    }

    // ---- output projection (fp32 out) ----
    run_split(Wo, Wh, Wlo, D_MODEL * D_VALUE);
    gemm_bf16_kernel<false, false><<<grid512, blk>>>(Ohp, Olp, Wh, Wlo, bo,
        Proj, nullptr, nullptr, M_ROWS, D_MODEL, D_MODEL);

    // ---- residual + LN1 (fp32 X + split) ----
    residual_ln_kernel<true, true><<<M_ROWS, 128>>>(v, Proj, g1, b1, X, Xh, Xl);

    // ---- FFN ----
    run_split(Wc1, Wh, Wlo, D_FF * D_VALUE);
    gemm_bf16_kernel<true, true><<<gridFF, blk>>>(Xh, Xl, Wh, Wlo, bc1,
        nullptr, Fh, Fl, M_ROWS, D_FF, D_VALUE);

    run_split(Wc2, Wh, Wlo, D_VALUE * D_FF);
    gemm_bf16_kernel<false, false><<<grid512, blk>>>(Fh, Fl, Wh, Wlo, bc2,
        Y, nullptr, nullptr, M_ROWS, D_VALUE, D_FF);

    // ---- residual + LN2 (split only) ----
    residual_ln_kernel<false, true><<<M_ROWS, 128>>>(X, Y, g2, b2, nullptr, X2h, X2l);

    // ---- final projection ----
    run_split(Wl, Wh, Wlo, D_MODEL * D_VALUE);
    gemm_bf16_kernel<false, false><<<grid512, blk>>>(X2h, X2l, Wh, Wlo, bl,
        out, nullptr, nullptr, M_ROWS, D_MODEL, D_VALUE);
}

// round 11
// speedup vs baseline: 2.1687x; 1.0726x over previous
#include <cuda_runtime.h>
#include <cuda_bf16.h>
#include <cstdint>

// ---------------------------------------------------------------------------
// Problem constants
// ---------------------------------------------------------------------------
#define B_BATCH 4
#define SEQ_L   2048
#define D_MODEL 512
#define D_VALUE 512
#define N_HEADS 8
#define HEAD_E  64
#define D_FF    2048
#define M_ROWS  (B_BATCH * SEQ_L)   // 8192

// ---------------------------------------------------------------------------
// Scratch (static device allocations)
// ---------------------------------------------------------------------------
__device__ float g_proj[M_ROWS * D_MODEL];
__device__ float g_x   [M_ROWS * D_VALUE];
__device__ float g_y   [M_ROWS * D_VALUE];

__device__ __nv_bfloat16 g_Ah [M_ROWS * D_MODEL];
__device__ __nv_bfloat16 g_Al [M_ROWS * D_MODEL];
__device__ __nv_bfloat16 g_Wh [D_FF * D_VALUE];
__device__ __nv_bfloat16 g_Wl [D_FF * D_VALUE];

__device__ __nv_bfloat16 g_Qh [M_ROWS * D_MODEL];
__device__ __nv_bfloat16 g_Ql [M_ROWS * D_MODEL];
__device__ __nv_bfloat16 g_Kh [M_ROWS * D_MODEL];
__device__ __nv_bfloat16 g_Kl [M_ROWS * D_MODEL];
__device__ __nv_bfloat16 g_Vh [M_ROWS * D_MODEL];
__device__ __nv_bfloat16 g_Vl [M_ROWS * D_MODEL];
__device__ __nv_bfloat16 g_Vth[M_ROWS * D_MODEL];   // [B][H][E][L]
__device__ __nv_bfloat16 g_Vtl[M_ROWS * D_MODEL];
__device__ __nv_bfloat16 g_Oh [M_ROWS * D_MODEL];
__device__ __nv_bfloat16 g_Ol [M_ROWS * D_MODEL];
__device__ __nv_bfloat16 g_Xh [M_ROWS * D_VALUE];
__device__ __nv_bfloat16 g_Xl [M_ROWS * D_VALUE];
__device__ __nv_bfloat16 g_Fh [M_ROWS * D_FF];
__device__ __nv_bfloat16 g_Fl [M_ROWS * D_FF];
__device__ __nv_bfloat16 g_X2h[M_ROWS * D_VALUE];
__device__ __nv_bfloat16 g_X2l[M_ROWS * D_VALUE];

// ---------------------------------------------------------------------------
// helpers
// ---------------------------------------------------------------------------
__device__ __forceinline__ void split2(float x, float y, uint32_t& hi, uint32_t& lo)
{
    __nv_bfloat16 hx = __float2bfloat16_rn(x);
    __nv_bfloat16 hy = __float2bfloat16_rn(y);
    __nv_bfloat162 h2 = __halves2bfloat162(hx, hy);
    __nv_bfloat162 l2 = __halves2bfloat162(
        __float2bfloat16_rn(x - __bfloat162float(hx)),
        __float2bfloat16_rn(y - __bfloat162float(hy)));
    hi = *reinterpret_cast<uint32_t*>(&h2);
    lo = *reinterpret_cast<uint32_t*>(&l2);
}

__device__ __forceinline__ void mma_bf16(
    float& d0, float& d1, float& d2, float& d3,
    uint32_t a0, uint32_t a1, uint32_t a2, uint32_t a3,
    uint32_t b0, uint32_t b1)
{
    asm volatile(
        "mma.sync.aligned.m16n8k16.row.col.f32.bf16.bf16.f32 "
        "{%0,%1,%2,%3}, {%4,%5,%6,%7}, {%8,%9}, {%0,%1,%2,%3};"
        : "+f"(d0), "+f"(d1), "+f"(d2), "+f"(d3)
        : "r"(a0), "r"(a1), "r"(a2), "r"(a3), "r"(b0), "r"(b1));
}

__device__ __forceinline__ uint32_t smem_u32(const void* p)
{
    uint32_t a;
    asm("{ .reg .u64 t; cvta.to.shared.u64 t, %1; cvt.u32.u64 %0, t; }"
        : "=r"(a) : "l"(p));
    return a;
}

__device__ __forceinline__ void ldsm_x4(
    uint32_t& r0, uint32_t& r1, uint32_t& r2, uint32_t& r3, uint32_t addr)
{
    asm volatile(
        "ldmatrix.sync.aligned.m8n8.x4.shared.b16 {%0,%1,%2,%3}, [%4];"
        : "=r"(r0), "=r"(r1), "=r"(r2), "=r"(r3) : "r"(addr));
}

#define CP_ASYNC16(dst, src) \
    asm volatile("cp.async.cg.shared.global [%0], [%1], 16;" \
                 :: "r"(dst), "l"(src) : "memory")
#define CP_COMMIT() asm volatile("cp.async.commit_group;" ::: "memory")
#define CP_WAIT1()  asm volatile("cp.async.wait_group 1;" ::: "memory")
#define CP_WAIT0()  asm volatile("cp.async.wait_group 0;" ::: "memory")

// ---------------------------------------------------------------------------
// Split fp32 -> bf16 hi + bf16 lo
// ---------------------------------------------------------------------------
__global__ __launch_bounds__(256) void split_kernel(
    const float* __restrict__ x,
    __nv_bfloat16* __restrict__ hi, __nv_bfloat16* __restrict__ lo, int n4)
{
    int i = blockIdx.x * 256 + threadIdx.x;
    if (i >= n4) return;
    float4 v = ((const float4*)x)[i];
    uint32_t h0, l0, h1, l1;
    split2(v.x, v.y, h0, l0);
    split2(v.z, v.w, h1, l1);
    ((uint32_t*)hi)[2 * i]     = h0;
    ((uint32_t*)hi)[2 * i + 1] = h1;
    ((uint32_t*)lo)[2 * i]     = l0;
    ((uint32_t*)lo)[2 * i + 1] = l1;
}

// ---------------------------------------------------------------------------
// HMMA bf16 hi/lo GEMM: C = A @ W^T + bias (opt ReLU / split output)
// CTA 128x128, BK=32, 2-stage cp.async, ldmatrix fragment loads.
// ---------------------------------------------------------------------------
#define GS 40                            // bf16 elems/row (32 data + 8 pad)
#define GA_BYTES (128 * GS * 2)          // 10240 per array
#define GSTAGE_BYTES (4 * GA_BYTES)      // 40960 per stage (Ah,Al,Bh,Bl)
#define GSMEM (2 * GSTAGE_BYTES)         // 81920 total

template<bool RELU, bool SPLIT>
__global__ __launch_bounds__(256) void gemm_bf16_kernel(
    const __nv_bfloat16* __restrict__ Ah, const __nv_bfloat16* __restrict__ Al,
    const __nv_bfloat16* __restrict__ Bh, const __nv_bfloat16* __restrict__ Bl,
    const float* __restrict__ bias, float* __restrict__ C,
    __nv_bfloat16* __restrict__ Ch, __nv_bfloat16* __restrict__ Cl,
    int M, int N, int K)
{
    extern __shared__ char smem[];
    const uint32_t su = smem_u32(smem);

    const int tid  = threadIdx.x;
    const int lane = tid & 31;
    const int warp = tid >> 5;
    const int wm = (warp & 1) * 64;
    const int wn = (warp >> 1) * 32;
    const int m0 = blockIdx.y * 128;
    const int n0 = blockIdx.x * 128;

    // cp.async mapping: 2 threads per row, 32B each (2 x 16B chunks)
    const int crow = tid >> 1;
    const uint32_t cc32 = (uint32_t)(tid & 1) * 32;
    const int ce = (tid & 1) * 16;

    const __nv_bfloat16* gAh = Ah + (size_t)(m0 + crow) * K + ce;
    const __nv_bfloat16* gAl = Al + (size_t)(m0 + crow) * K + ce;
    const __nv_bfloat16* gBh = Bh + (size_t)(n0 + crow) * K + ce;
    const __nv_bfloat16* gBl = Bl + (size_t)(n0 + crow) * K + ce;
    const uint32_t so = (uint32_t)crow * (GS * 2) + cc32;

    auto load_stage = [&](int i) {
        const uint32_t sb = su + (uint32_t)(i & 1) * GSTAGE_BYTES;
        const size_t kof = (size_t)i * 32;
        CP_ASYNC16(sb + 0 * GA_BYTES + so,      gAh + kof);
        CP_ASYNC16(sb + 0 * GA_BYTES + so + 16, gAh + kof + 8);
        CP_ASYNC16(sb + 1 * GA_BYTES + so,      gAl + kof);
        CP_ASYNC16(sb + 1 * GA_BYTES + so + 16, gAl + kof + 8);
        CP_ASYNC16(sb + 2 * GA_BYTES + so,      gBh + kof);
        CP_ASYNC16(sb + 2 * GA_BYTES + so + 16, gBh + kof + 8);
        CP_ASYNC16(sb + 3 * GA_BYTES + so,      gBl + kof);
        CP_ASYNC16(sb + 3 * GA_BYTES + so + 16, gBl + kof + 8);
        CP_COMMIT();
    };

    // ldmatrix lane address offsets (bytes)
    const int l8 = lane & 7, lq = lane >> 3;
    const uint32_t aOff = (uint32_t)(((wm + l8 + (lq & 1) * 8) * GS + (lq >> 1) * 8) * 2);
    const uint32_t bOff = (uint32_t)(((wn + l8 + (lq >> 1) * 8) * GS + (lq & 1) * 8) * 2);

    float acc[4][4][4];
#pragma unroll
    for (int mi = 0; mi < 4; ++mi)
#pragma unroll
        for (int ni = 0; ni < 4; ++ni)
#pragma unroll
            for (int r = 0; r < 4; ++r) acc[mi][ni][r] = 0.f;

    load_stage(0);
    load_stage(1);
    const int nch = K >> 5;

    for (int i = 0; i < nch; ++i) {
        if (i + 1 < nch) { CP_WAIT1(); } else { CP_WAIT0(); }
        __syncthreads();
        const uint32_t sb = su + (uint32_t)(i & 1) * GSTAGE_BYTES;
#pragma unroll
        for (int ks = 0; ks < 2; ++ks) {
            const uint32_t ko = (uint32_t)ks * 32;   // 16 elems * 2B
            uint32_t aH[4][4], aL[4][4], bH[4][2], bL[4][2];
#pragma unroll
            for (int mi = 0; mi < 4; ++mi) {
                const uint32_t ad = sb + 0 * GA_BYTES + aOff
                                  + (uint32_t)mi * (16 * GS * 2) + ko;
                ldsm_x4(aH[mi][0], aH[mi][1], aH[mi][2], aH[mi][3], ad);
                ldsm_x4(aL[mi][0], aL[mi][1], aL[mi][2], aL[mi][3], ad + GA_BYTES);
            }
#pragma unroll
            for (int np = 0; np < 2; ++np) {
                const uint32_t bd = sb + 2 * GA_BYTES + bOff
                                  + (uint32_t)np * (16 * GS * 2) + ko;
                ldsm_x4(bH[2 * np][0], bH[2 * np][1],
                        bH[2 * np + 1][0], bH[2 * np + 1][1], bd);
                ldsm_x4(bL[2 * np][0], bL[2 * np][1],
                        bL[2 * np + 1][0], bL[2 * np + 1][1], bd + GA_BYTES);
            }
#pragma unroll
            for (int mi = 0; mi < 4; ++mi)
#pragma unroll
                for (int ni = 0; ni < 4; ++ni) {
                    float* d = acc[mi][ni];
                    mma_bf16(d[0], d[1], d[2], d[3],
                             aH[mi][0], aH[mi][1], aH[mi][2], aH[mi][3],
                             bH[ni][0], bH[ni][1]);
                    mma_bf16(d[0], d[1], d[2], d[3],
                             aH[mi][0], aH[mi][1], aH[mi][2], aH[mi][3],
                             bL[ni][0], bL[ni][1]);
                    mma_bf16(d[0], d[1], d[2], d[3],
                             aL[mi][0], aL[mi][1], aL[mi][2], aL[mi][3],
                             bH[ni][0], bH[ni][1]);
                }
        }
        __syncthreads();
        if (i + 2 < nch) load_stage(i + 2);
    }

    // epilogue (layout identical to validated R5/R7 kernel)
#pragma unroll
    for (int mi = 0; mi < 4; ++mi) {
        const int m = m0 + wm + mi * 16 + (lane >> 2);
#pragma unroll
        for (int ni = 0; ni < 4; ++ni) {
            const int nc = n0 + wn + ni * 8 + 2 * (lane & 3);
            float b0 = bias[nc], b1 = bias[nc + 1];
            float c0 = acc[mi][ni][0] + b0, c1 = acc[mi][ni][1] + b1;
            float c2 = acc[mi][ni][2] + b0, c3 = acc[mi][ni][3] + b1;
            if (RELU) {
                c0 = fmaxf(c0, 0.f); c1 = fmaxf(c1, 0.f);
                c2 = fmaxf(c2, 0.f); c3 = fmaxf(c3, 0.f);
            }
            if (!SPLIT) {
                *(float2*)&C[(size_t)m * N + nc]       = make_float2(c0, c1);
                *(float2*)&C[(size_t)(m + 8) * N + nc] = make_float2(c2, c3);
            } else {
                uint32_t h0, l0, h1, l1;
                split2(c0, c1, h0, l0);
                split2(c2, c3, h1, l1);
                *(uint32_t*)&Ch[(size_t)m * N + nc]       = h0;
                *(uint32_t*)&Cl[(size_t)m * N + nc]       = l0;
                *(uint32_t*)&Ch[(size_t)(m + 8) * N + nc] = h1;
                *(uint32_t*)&Cl[(size_t)(m + 8) * N + nc] = l1;
            }
        }
    }
}

// ---------------------------------------------------------------------------
// V transpose: Vh/Vl [token][512] -> Vth/Vtl [B][H][E=64][L=2048]
// ---------------------------------------------------------------------------
__global__ __launch_bounds__(256) void vtrans_kernel(
    const __nv_bfloat16* __restrict__ Vh, const __nv_bfloat16* __restrict__ Vl,
    __nv_bfloat16* __restrict__ Vth, __nv_bfloat16* __restrict__ Vtl)
{
    __shared__ __nv_bfloat16 th[64][72];
    __shared__ __nv_bfloat16 tl[64][72];
    const int lt = blockIdx.x, h = blockIdx.y, b = blockIdx.z;
    const int t = threadIdx.x;
    {
        int l = t >> 2, e0 = (t & 3) * 16;
        size_t g = ((size_t)(b * SEQ_L + lt * 64 + l)) * D_MODEL + h * 64 + e0;
        int4 a0 = *(const int4*)(Vh + g);
        int4 a1 = *(const int4*)(Vh + g + 8);
        *(int4*)&th[l][e0]     = a0;
        *(int4*)&th[l][e0 + 8] = a1;
        int4 c0 = *(const int4*)(Vl + g);
        int4 c1 = *(const int4*)(Vl + g + 8);
        *(int4*)&tl[l][e0]     = c0;
        *(int4*)&tl[l][e0 + 8] = c1;
    }
    __syncthreads();
    {
        int e = t >> 2, l0 = (t & 3) * 16;
        __align__(16) __nv_bfloat16 buf[16], buf2[16];
#pragma unroll
        for (int i = 0; i < 16; ++i) { buf[i] = th[l0 + i][e]; buf2[i] = tl[l0 + i][e]; }
        size_t g = ((size_t)((b * N_HEADS + h) * 64 + e)) * SEQ_L + lt * 64 + l0;
        ((int4*)(Vth + g))[0] = ((int4*)buf)[0];
        ((int4*)(Vth + g))[1] = ((int4*)buf)[1];
        ((int4*)(Vtl + g))[0] = ((int4*)buf2)[0];
        ((int4*)(Vtl + g))[1] = ((int4*)buf2)[1];
    }
}

// ---------------------------------------------------------------------------
// Tensor-core causal flash attention, hi/lo compensated bf16 (HMMA path).
// ---------------------------------------------------------------------------
#define AT_S 72

__global__ __launch_bounds__(256, 1) void attn_mma_kernel(
    const __nv_bfloat16* __restrict__ Qh, const __nv_bfloat16* __restrict__ Ql,
    const __nv_bfloat16* __restrict__ Kh, const __nv_bfloat16* __restrict__ Kl,
    const __nv_bfloat16* __restrict__ Vth, const __nv_bfloat16* __restrict__ Vtl,
    __nv_bfloat16* __restrict__ Oh, __nv_bfloat16* __restrict__ Ol)
{
    extern __shared__ __nv_bfloat16 smb[];
    __nv_bfloat16* sQh = smb;
    __nv_bfloat16* sQl = sQh + 128 * AT_S;
    __nv_bfloat16* sKh = sQl + 128 * AT_S;
    __nv_bfloat16* sKl = sKh + 64 * AT_S;
    __nv_bfloat16* sVh = sKl + 64 * AT_S;
    __nv_bfloat16* sVl = sVh + 64 * AT_S;

    const int tid = threadIdx.x, lane = tid & 31, warp = tid >> 5;
    const int qt = blockIdx.x, h = blockIdx.y, b = blockIdx.z;
    const int q0 = qt * 128;
    const size_t qkBase = ((size_t)b * SEQ_L) * D_MODEL + (size_t)h * HEAD_E;
    const size_t vtBase = ((size_t)(b * N_HEADS + h)) * HEAD_E * SEQ_L;

    {
        int row = tid >> 1, e0 = (tid & 1) * 32;
        size_t g = qkBase + (size_t)(q0 + row) * D_MODEL + e0;
        int4 a0 = *(const int4*)(Qh + g);
        int4 a1 = *(const int4*)(Qh + g + 8);
        int4 a2 = *(const int4*)(Qh + g + 16);
        int4 a3 = *(const int4*)(Qh + g + 24);
        int4* d = (int4*)(sQh + row * AT_S + e0);
        d[0] = a0; d[1] = a1; d[2] = a2; d[3] = a3;
        int4 c0 = *(const int4*)(Ql + g);
        int4 c1 = *(const int4*)(Ql + g + 8);
        int4 c2 = *(const int4*)(Ql + g + 16);
        int4 c3 = *(const int4*)(Ql + g + 24);
        int4* d2 = (int4*)(sQl + row * AT_S + e0);
        d2[0] = c0; d2[1] = c1; d2[2] = c2; d2[3] = c3;
    }

    float m0 = -1e30f, m1 = -1e30f, l0s = 0.f, l1s = 0.f;
    float oacc[8][4];
#pragma unroll
    for (int nt = 0; nt < 8; ++nt)
#pragma unroll
        for (int r = 0; r < 4; ++r) oacc[nt][r] = 0.f;

    const int ldr = tid >> 2;
    const int ldc = (tid & 3) * 16;
    const int nkt = 2 * qt + 2;

    int4 pKh0, pKh1, pKl0, pKl1, pVh0, pVh1, pVl0, pVl1;
    {
        size_t gk = qkBase + (size_t)(0 + ldr) * D_MODEL + ldc;
        pKh0 = *(const int4*)(Kh + gk);  pKh1 = *(const int4*)(Kh + gk + 8);
        pKl0 = *(const int4*)(Kl + gk);  pKl1 = *(const int4*)(Kl + gk + 8);
        size_t gv = vtBase + (size_t)ldr * SEQ_L + 0 + ldc;
        pVh0 = *(const int4*)(Vth + gv); pVh1 = *(const int4*)(Vth + gv + 8);
        pVl0 = *(const int4*)(Vtl + gv); pVl1 = *(const int4*)(Vtl + gv + 8);
    }

    const int gr  = warp * 16 + (lane >> 2);
    const int cc  = 2 * (lane & 3);

    for (int kt = 0; kt < nkt; ++kt) {
        const int k0 = kt * 64;
        __syncthreads();
        {
            int4* d;
            d = (int4*)(sKh + ldr * AT_S + ldc); d[0] = pKh0; d[1] = pKh1;
            d = (int4*)(sKl + ldr * AT_S + ldc); d[0] = pKl0; d[1] = pKl1;
            d = (int4*)(sVh + ldr * AT_S + ldc); d[0] = pVh0; d[1] = pVh1;
            d = (int4*)(sVl + ldr * AT_S + ldc); d[0] = pVl0; d[1] = pVl1;
        }
        __syncthreads();
        if (kt + 1 < nkt) {
            size_t gk = qkBase + (size_t)(k0 + 64 + ldr) * D_MODEL + ldc;
            pKh0 = *(const int4*)(Kh + gk);  pKh1 = *(const int4*)(Kh + gk + 8);
            pKl0 = *(const int4*)(Kl + gk);  pKl1 = *(const int4*)(Kl + gk + 8);
            size_t gv = vtBase + (size_t)ldr * SEQ_L + k0 + 64 + ldc;
            pVh0 = *(const int4*)(Vth + gv); pVh1 = *(const int4*)(Vth + gv + 8);
            pVl0 = *(const int4*)(Vtl + gv); pVl1 = *(const int4*)(Vtl + gv + 8);
        }

        float sacc[8][4];
#pragma unroll
        for (int nt = 0; nt < 8; ++nt)
#pragma unroll
            for (int r = 0; r < 4; ++r) sacc[nt][r] = 0.f;

#pragma unroll
        for (int es = 0; es < 4; ++es) {
            const int e = es * 16 + cc;
            uint32_t ah0 = *(const uint32_t*)&sQh[gr * AT_S + e];
            uint32_t ah1 = *(const uint32_t*)&sQh[(gr + 8) * AT_S + e];
            uint32_t ah2 = *(const uint32_t*)&sQh[gr * AT_S + e + 8];
            uint32_t ah3 = *(const uint32_t*)&sQh[(gr + 8) * AT_S + e + 8];
            uint32_t al0 = *(const uint32_t*)&sQl[gr * AT_S + e];
            uint32_t al1 = *(const uint32_t*)&sQl[(gr + 8) * AT_S + e];
            uint32_t al2 = *(const uint32_t*)&sQl[gr * AT_S + e + 8];
            uint32_t al3 = *(const uint32_t*)&sQl[(gr + 8) * AT_S + e + 8];
#pragma unroll
            for (int nt = 0; nt < 8; ++nt) {
                const int n = nt * 8 + (lane >> 2);
                uint32_t bh0 = *(const uint32_t*)&sKh[n * AT_S + e];
                uint32_t bh1 = *(const uint32_t*)&sKh[n * AT_S + e + 8];
                uint32_t bl0 = *(const uint32_t*)&sKl[n * AT_S + e];
                uint32_t bl1 = *(const uint32_t*)&sKl[n * AT_S + e + 8];
                float* dd = sacc[nt];
                mma_bf16(dd[0], dd[1], dd[2], dd[3], ah0, ah1, ah2, ah3, bh0, bh1);
                mma_bf16(dd[0], dd[1], dd[2], dd[3], ah0, ah1, ah2, ah3, bl0, bl1);
                mma_bf16(dd[0], dd[1], dd[2], dd[3], al0, al1, al2, al3, bh0, bh1);
            }
        }

        const float scl = 0.125f;
        if (kt >= 2 * qt) {
            const int qg0 = q0 + gr, qg1 = qg0 + 8;
#pragma unroll
            for (int nt = 0; nt < 8; ++nt) {
                const int kg = k0 + nt * 8 + cc;
                sacc[nt][0] = (kg     > qg0) ? -1e30f : sacc[nt][0] * scl;
                sacc[nt][1] = (kg + 1 > qg0) ? -1e30f : sacc[nt][1] * scl;
                sacc[nt][2] = (kg     > qg1) ? -1e30f : sacc[nt][2] * scl;
                sacc[nt][3] = (kg + 1 > qg1) ? -1e30f : sacc[nt][3] * scl;
            }
        } else {
#pragma unroll
            for (int nt = 0; nt < 8; ++nt) {
                sacc[nt][0] *= scl; sacc[nt][1] *= scl;
                sacc[nt][2] *= scl; sacc[nt][3] *= scl;
            }
        }

        float mx0 = -1e30f, mx1 = -1e30f;
#pragma unroll
        for (int nt = 0; nt < 8; ++nt) {
            mx0 = fmaxf(mx0, fmaxf(sacc[nt][0], sacc[nt][1]));
            mx1 = fmaxf(mx1, fmaxf(sacc[nt][2], sacc[nt][3]));
        }
        mx0 = fmaxf(mx0, __shfl_xor_sync(0xffffffffu, mx0, 1));
        mx0 = fmaxf(mx0, __shfl_xor_sync(0xffffffffu, mx0, 2));
        mx1 = fmaxf(mx1, __shfl_xor_sync(0xffffffffu, mx1, 1));
        mx1 = fmaxf(mx1, __shfl_xor_sync(0xffffffffu, mx1, 2));
        const float mn0 = fmaxf(m0, mx0), mn1 = fmaxf(m1, mx1);
        const float a0 = __expf(m0 - mn0), a1 = __expf(m1 - mn1);
        m0 = mn0; m1 = mn1;

        float s0 = 0.f, s1 = 0.f;
        uint32_t pH[4][4], pL[4][4];
#pragma unroll
        for (int ks = 0; ks < 4; ++ks) {
            const int n0t = 2 * ks, n1t = 2 * ks + 1;
            float p00 = __expf(sacc[n0t][0] - mn0);
            float p01 = __expf(sacc[n0t][1] - mn0);
            float p10 = __expf(sacc[n0t][2] - mn1);
            float p11 = __expf(sacc[n0t][3] - mn1);
            float p20 = __expf(sacc[n1t][0] - mn0);
            float p21 = __expf(sacc[n1t][1] - mn0);
            float p30 = __expf(sacc[n1t][2] - mn1);
            float p31 = __expf(sacc[n1t][3] - mn1);
            s0 += p00 + p01 + p20 + p21;
            s1 += p10 + p11 + p30 + p31;
            split2(p00, p01, pH[ks][0], pL[ks][0]);
            split2(p10, p11, pH[ks][1], pL[ks][1]);
            split2(p20, p21, pH[ks][2], pL[ks][2]);
            split2(p30, p31, pH[ks][3], pL[ks][3]);
        }
        s0 += __shfl_xor_sync(0xffffffffu, s0, 1);
        s0 += __shfl_xor_sync(0xffffffffu, s0, 2);
        s1 += __shfl_xor_sync(0xffffffffu, s1, 1);
        s1 += __shfl_xor_sync(0xffffffffu, s1, 2);
        l0s = l0s * a0 + s0;
        l1s = l1s * a1 + s1;
#pragma unroll
        for (int nt = 0; nt < 8; ++nt) {
            oacc[nt][0] *= a0; oacc[nt][1] *= a0;
            oacc[nt][2] *= a1; oacc[nt][3] *= a1;
        }

#pragma unroll
        for (int ks = 0; ks < 4; ++ks) {
            const int kk = ks * 16 + cc;
#pragma unroll
            for (int nt = 0; nt < 8; ++nt) {
                const int n = nt * 8 + (lane >> 2);
                uint32_t bh0 = *(const uint32_t*)&sVh[n * AT_S + kk];
                uint32_t bh1 = *(const uint32_t*)&sVh[n * AT_S + kk + 8];
                uint32_t bl0 = *(const uint32_t*)&sVl[n * AT_S + kk];
                uint32_t bl1 = *(const uint32_t*)&sVl[n * AT_S + kk + 8];
                float* dd = oacc[nt];
                mma_bf16(dd[0], dd[1], dd[2], dd[3],
                         pH[ks][0], pH[ks][1], pH[ks][2], pH[ks][3], bh0, bh1);
                mma_bf16(dd[0], dd[1], dd[2], dd[3],
                         pH[ks][0], pH[ks][1], pH[ks][2], pH[ks][3], bl0, bl1);
                mma_bf16(dd[0], dd[1], dd[2], dd[3],
                         pL[ks][0], pL[ks][1], pL[ks][2], pL[ks][3], bh0, bh1);
            }
        }
    }

    const float inv0 = 1.f / l0s, inv1 = 1.f / l1s;
    const size_t r0 = qkBase + (size_t)(q0 + gr) * D_MODEL + cc;
    const size_t r1 = r0 + 8 * D_MODEL;
#pragma unroll
    for (int nt = 0; nt < 8; ++nt) {
        uint32_t h0, lo0, h1, lo1;
        split2(oacc[nt][0] * inv0, oacc[nt][1] * inv0, h0, lo0);
        split2(oacc[nt][2] * inv1, oacc[nt][3] * inv1, h1, lo1);
        *(uint32_t*)&Oh[r0 + nt * 8] = h0;
        *(uint32_t*)&Ol[r0 + nt * 8] = lo0;
        *(uint32_t*)&Oh[r1 + nt * 8] = h1;
        *(uint32_t*)&Ol[r1 + nt * 8] = lo1;
    }
}

// ---------------------------------------------------------------------------
// Residual + LayerNorm (rows of 512); optional fp32 out + optional split out
// ---------------------------------------------------------------------------
template<bool F32OUT, bool SPLITOUT>
__global__ __launch_bounds__(128) void residual_ln_kernel(
    const float* __restrict__ a, const float* __restrict__ b,
    const float* __restrict__ gamma, const float* __restrict__ beta,
    float* __restrict__ out,
    __nv_bfloat16* __restrict__ outh, __nv_bfloat16* __restrict__ outl)
{
    const int row = blockIdx.x;
    const int tid = threadIdx.x;
    const size_t base = (size_t)row * D_VALUE;

    float4 va = ((const float4*)(a + base))[tid];
    float4 vb = ((const float4*)(b + base))[tid];
    float4 v = make_float4(va.x + vb.x, va.y + vb.y, va.z + vb.z, va.w + vb.w);

    float s  = v.x + v.y + v.z + v.w;
    float ss = v.x * v.x + v.y * v.y + v.z * v.z + v.w * v.w;
#pragma unroll
    for (int off = 16; off >= 1; off >>= 1) {
        s  += __shfl_xor_sync(0xffffffffu, s, off);
        ss += __shfl_xor_sync(0xffffffffu, ss, off);
    }
    __shared__ float red[8];
    const int wid = tid >> 5;
    if ((tid & 31) == 0) { red[wid] = s; red[4 + wid] = ss; }
    __syncthreads();
    s  = red[0] + red[1] + red[2] + red[3];
    ss = red[4] + red[5] + red[6] + red[7];

    const float mu = s * (1.f / (float)D_VALUE);
    float var = ss * (1.f / (float)D_VALUE) - mu * mu;
    const float rn = rsqrtf(var + 1e-5f);

    float4 g4 = ((const float4*)gamma)[tid];
    float4 b4 = ((const float4*)beta)[tid];
    float4 r;
    r.x = (v.x - mu) * rn * g4.x + b4.x;
    r.y = (v.y - mu) * rn * g4.y + b4.y;
    r.z = (v.z - mu) * rn * g4.z + b4.z;
    r.w = (v.w - mu) * rn * g4.w + b4.w;
    if (F32OUT) ((float4*)(out + base))[tid] = r;
    if (SPLITOUT) {
        uint32_t h0, l0, h1, l1;
        split2(r.x, r.y, h0, l0);
        split2(r.z, r.w, h1, l1);
        ((uint32_t*)(outh + base))[2 * tid]     = h0;
        ((uint32_t*)(outh + base))[2 * tid + 1] = h1;
        ((uint32_t*)(outl + base))[2 * tid]     = l0;
        ((uint32_t*)(outl + base))[2 * tid + 1] = l1;
    }
}

// ---------------------------------------------------------------------------
// Launch
// ---------------------------------------------------------------------------
static inline void run_split(const float* x, __nv_bfloat16* hi, __nv_bfloat16* lo, int n)
{
    int n4 = n / 4;
    split_kernel<<<(n4 + 255) / 256, 256>>>(x, hi, lo, n4);
}

template<bool RELU, bool SPLIT>
static inline void run_gemm(
    const __nv_bfloat16* Ah, const __nv_bfloat16* Al,
    const __nv_bfloat16* Bh, const __nv_bfloat16* Bl,
    const float* bias, float* C, __nv_bfloat16* Ch, __nv_bfloat16* Cl,
    int M, int N, int K)
{
    cudaFuncSetAttribute(gemm_bf16_kernel<RELU, SPLIT>,
                         cudaFuncAttributeMaxDynamicSharedMemorySize, GSMEM);
    gemm_bf16_kernel<RELU, SPLIT><<<dim3(N / 128, M / 128), 256, GSMEM>>>(
        Ah, Al, Bh, Bl, bias, C, Ch, Cl, M, N, K);
}

extern "C" void kernel_launch(void* const* d_in, const int* in_sizes, int n_in,
                              void* d_out, int out_size)
{
    const float* q   = (const float*)d_in[0];
    const float* k   = (const float*)d_in[1];
    const float* v   = (const float*)d_in[2];
    const float* Wq  = (const float*)d_in[3];
    const float* bq  = (const float*)d_in[4];
    const float* Wk  = (const float*)d_in[5];
    const float* bk  = (const float*)d_in[6];
    const float* Wv  = (const float*)d_in[7];
    const float* bv  = (const float*)d_in[8];
    const float* Wo  = (const float*)d_in[9];
    const float* bo  = (const float*)d_in[10];
    const float* Wc1 = (const float*)d_in[11];
    const float* bc1 = (const float*)d_in[12];
    const float* Wc2 = (const float*)d_in[13];
    const float* bc2 = (const float*)d_in[14];
    const float* g1  = (const float*)d_in[15];
    const float* b1  = (const float*)d_in[16];
    const float* g2  = (const float*)d_in[17];
    const float* b2  = (const float*)d_in[18];
    const float* Wl  = (const float*)d_in[19];
    const float* bl  = (const float*)d_in[20];
    float* out = (float*)d_out;

    float *Proj, *X, *Y;
    __nv_bfloat16 *Ah, *Al, *Wh, *Wlo, *Qh, *Ql, *Kh, *Kl, *Vh, *Vl;
    __nv_bfloat16 *Vth, *Vtl, *Ohp, *Olp, *Xh, *Xl, *Fh, *Fl, *X2h, *X2l;
    cudaGetSymbolAddress((void**)&Proj, g_proj);
    cudaGetSymbolAddress((void**)&X,    g_x);
    cudaGetSymbolAddress((void**)&Y,    g_y);
    cudaGetSymbolAddress((void**)&Ah,   g_Ah);
    cudaGetSymbolAddress((void**)&Al,   g_Al);
    cudaGetSymbolAddress((void**)&Wh,   g_Wh);
    cudaGetSymbolAddress((void**)&Wlo,  g_Wl);
    cudaGetSymbolAddress((void**)&Qh,   g_Qh);
    cudaGetSymbolAddress((void**)&Ql,   g_Ql);
    cudaGetSymbolAddress((void**)&Kh,   g_Kh);
    cudaGetSymbolAddress((void**)&Kl,   g_Kl);
    cudaGetSymbolAddress((void**)&Vh,   g_Vh);
    cudaGetSymbolAddress((void**)&Vl,   g_Vl);
    cudaGetSymbolAddress((void**)&Vth,  g_Vth);
    cudaGetSymbolAddress((void**)&Vtl,  g_Vtl);
    cudaGetSymbolAddress((void**)&Ohp,  g_Oh);
    cudaGetSymbolAddress((void**)&Olp,  g_Ol);
    cudaGetSymbolAddress((void**)&Xh,   g_Xh);
    cudaGetSymbolAddress((void**)&Xl,   g_Xl);
    cudaGetSymbolAddress((void**)&Fh,   g_Fh);
    cudaGetSymbolAddress((void**)&Fl,   g_Fl);
    cudaGetSymbolAddress((void**)&X2h,  g_X2h);
    cudaGetSymbolAddress((void**)&X2l,  g_X2l);

    // ---- QKV projections -> split bf16 outputs ----
    run_split(q, Ah, Al, M_ROWS * D_MODEL);
    run_split(Wq, Wh, Wlo, D_MODEL * D_MODEL);
    run_gemm<false, true>(Ah, Al, Wh, Wlo, bq, nullptr, Qh, Ql,
                          M_ROWS, D_MODEL, D_MODEL);

    run_split(k, Ah, Al, M_ROWS * D_MODEL);
    run_split(Wk, Wh, Wlo, D_MODEL * D_MODEL);
    run_gemm<false, true>(Ah, Al, Wh, Wlo, bk, nullptr, Kh, Kl,
                          M_ROWS, D_MODEL, D_MODEL);

    run_split(v, Ah, Al, M_ROWS * D_MODEL);
    run_split(Wv, Wh, Wlo, D_MODEL * D_MODEL);
    run_gemm<false, true>(Ah, Al, Wh, Wlo, bv, nullptr, Vh, Vl,
                          M_ROWS, D_MODEL, D_MODEL);

    // ---- V transpose per head ----
    vtrans_kernel<<<dim3(SEQ_L / 64, N_HEADS, B_BATCH), 256>>>(Vh, Vl, Vth, Vtl);

    // ---- attention (HMMA tensor cores) ----
    {
        int smem = (2 * 128 + 4 * 64) * AT_S * 2;  // 73728 B
        cudaFuncSetAttribute(attn_mma_kernel,
                             cudaFuncAttributeMaxDynamicSharedMemorySize, smem);
        attn_mma_kernel<<<dim3(SEQ_L / 128, N_HEADS, B_BATCH), 256, smem>>>(
            Qh, Ql, Kh, Kl, Vth, Vtl, Ohp, Olp);
    }

    // ---- output projection (fp32 out) ----
    run_split(Wo, Wh, Wlo, D_MODEL * D_VALUE);
    run_gemm<false, false>(Ohp, Olp, Wh, Wlo, bo, Proj, nullptr, nullptr,
                           M_ROWS, D_MODEL, D_MODEL);

    // ---- residual + LN1 (fp32 X + split) ----
    residual_ln_kernel<true, true><<<M_ROWS, 128>>>(v, Proj, g1, b1, X, Xh, Xl);

    // ---- FFN ----
    run_split(Wc1, Wh, Wlo, D_FF * D_VALUE);
    run_gemm<true, true>(Xh, Xl, Wh, Wlo, bc1, nullptr, Fh, Fl,
                         M_ROWS, D_FF, D_VALUE);

    run_split(Wc2, Wh, Wlo, D_VALUE * D_FF);
    run_gemm<false, false>(Fh, Fl, Wh, Wlo, bc2, Y, nullptr, nullptr,
                           M_ROWS, D_VALUE, D_FF);

    // ---- residual + LN2 (split only) ----
    residual_ln_kernel<false, true><<<M_ROWS, 128>>>(X, Y, g2, b2, nullptr, X2h, X2l);

    // ---- final projection ----
    run_split(Wl, Wh, Wlo, D_MODEL * D_VALUE);
    run_gemm<false, false>(X2h, X2l, Wh, Wlo, bl, out, nullptr, nullptr,
                           M_ROWS, D_MODEL, D_VALUE);
}

// round 12
// speedup vs baseline: 2.8718x; 1.3242x over previous
#include <cuda_runtime.h>
#include <cuda_bf16.h>
#include <cuda_fp16.h>
#include <cstdint>

// ---------------------------------------------------------------------------
// Problem constants
// ---------------------------------------------------------------------------
#define B_BATCH 4
#define SEQ_L   2048
#define D_MODEL 512
#define D_VALUE 512
#define N_HEADS 8
#define HEAD_E  64
#define D_FF    2048
#define M_ROWS  (B_BATCH * SEQ_L)   // 8192

// ---------------------------------------------------------------------------
// Scratch (static device allocations)
// ---------------------------------------------------------------------------
__device__ float g_proj[M_ROWS * D_MODEL];
__device__ float g_x   [M_ROWS * D_VALUE];
__device__ float g_y   [M_ROWS * D_VALUE];

// fp16 GEMM operand staging
__device__ __half g_Ah [M_ROWS * D_MODEL];
__device__ __half g_Al [M_ROWS * D_MODEL];
__device__ __half g_W  [D_FF * D_VALUE];
__device__ __half g_Oh [M_ROWS * D_MODEL];
__device__ __half g_Ol [M_ROWS * D_MODEL];
__device__ __half g_Xh [M_ROWS * D_VALUE];
__device__ __half g_Xl [M_ROWS * D_VALUE];
__device__ __half g_Fh [M_ROWS * D_FF];
__device__ __half g_Fl [M_ROWS * D_FF];
__device__ __half g_X2h[M_ROWS * D_VALUE];
__device__ __half g_X2l[M_ROWS * D_VALUE];

// bf16 attention operands (3-term compensated path, unchanged)
__device__ __nv_bfloat16 g_Qh [M_ROWS * D_MODEL];
__device__ __nv_bfloat16 g_Ql [M_ROWS * D_MODEL];
__device__ __nv_bfloat16 g_Kh [M_ROWS * D_MODEL];
__device__ __nv_bfloat16 g_Kl [M_ROWS * D_MODEL];
__device__ __nv_bfloat16 g_Vh [M_ROWS * D_MODEL];
__device__ __nv_bfloat16 g_Vl [M_ROWS * D_MODEL];
__device__ __nv_bfloat16 g_Vth[M_ROWS * D_MODEL];   // [B][H][E][L]
__device__ __nv_bfloat16 g_Vtl[M_ROWS * D_MODEL];

// ---------------------------------------------------------------------------
// helpers
// ---------------------------------------------------------------------------
__device__ __forceinline__ void split2(float x, float y, uint32_t& hi, uint32_t& lo)
{
    __nv_bfloat16 hx = __float2bfloat16_rn(x);
    __nv_bfloat16 hy = __float2bfloat16_rn(y);
    __nv_bfloat162 h2 = __halves2bfloat162(hx, hy);
    __nv_bfloat162 l2 = __halves2bfloat162(
        __float2bfloat16_rn(x - __bfloat162float(hx)),
        __float2bfloat16_rn(y - __bfloat162float(hy)));
    hi = *reinterpret_cast<uint32_t*>(&h2);
    lo = *reinterpret_cast<uint32_t*>(&l2);
}

__device__ __forceinline__ void split2h(float x, float y, uint32_t& hi, uint32_t& lo)
{
    __half hx = __float2half_rn(x);
    __half hy = __float2half_rn(y);
    __half2 h2 = __halves2half2(hx, hy);
    __half2 l2 = __halves2half2(
        __float2half_rn(x - __half2float(hx)),
        __float2half_rn(y - __half2float(hy)));
    hi = *reinterpret_cast<uint32_t*>(&h2);
    lo = *reinterpret_cast<uint32_t*>(&l2);
}

__device__ __forceinline__ void mma_bf16(
    float& d0, float& d1, float& d2, float& d3,
    uint32_t a0, uint32_t a1, uint32_t a2, uint32_t a3,
    uint32_t b0, uint32_t b1)
{
    asm volatile(
        "mma.sync.aligned.m16n8k16.row.col.f32.bf16.bf16.f32 "
        "{%0,%1,%2,%3}, {%4,%5,%6,%7}, {%8,%9}, {%0,%1,%2,%3};"
        : "+f"(d0), "+f"(d1), "+f"(d2), "+f"(d3)
        : "r"(a0), "r"(a1), "r"(a2), "r"(a3), "r"(b0), "r"(b1));
}

__device__ __forceinline__ void mma_f16(
    float& d0, float& d1, float& d2, float& d3,
    uint32_t a0, uint32_t a1, uint32_t a2, uint32_t a3,
    uint32_t b0, uint32_t b1)
{
    asm volatile(
        "mma.sync.aligned.m16n8k16.row.col.f32.f16.f16.f32 "
        "{%0,%1,%2,%3}, {%4,%5,%6,%7}, {%8,%9}, {%0,%1,%2,%3};"
        : "+f"(d0), "+f"(d1), "+f"(d2), "+f"(d3)
        : "r"(a0), "r"(a1), "r"(a2), "r"(a3), "r"(b0), "r"(b1));
}

__device__ __forceinline__ uint32_t smem_u32(const void* p)
{
    uint32_t a;
    asm("{ .reg .u64 t; cvta.to.shared.u64 t, %1; cvt.u32.u64 %0, t; }"
        : "=r"(a) : "l"(p));
    return a;
}

__device__ __forceinline__ void ldsm_x4(
    uint32_t& r0, uint32_t& r1, uint32_t& r2, uint32_t& r3, uint32_t addr)
{
    asm volatile(
        "ldmatrix.sync.aligned.m8n8.x4.shared.b16 {%0,%1,%2,%3}, [%4];"
        : "=r"(r0), "=r"(r1), "=r"(r2), "=r"(r3) : "r"(addr));
}

#define CP_ASYNC16(dst, src) \
    asm volatile("cp.async.cg.shared.global [%0], [%1], 16;" \
                 :: "r"(dst), "l"(src) : "memory")
#define CP_COMMIT() asm volatile("cp.async.commit_group;" ::: "memory")
#define CP_WAIT1()  asm volatile("cp.async.wait_group 1;" ::: "memory")
#define CP_WAIT0()  asm volatile("cp.async.wait_group 0;" ::: "memory")

// ---------------------------------------------------------------------------
// Split fp32 -> fp16 hi + fp16 lo (activations)
// ---------------------------------------------------------------------------
__global__ __launch_bounds__(256) void split_f16_kernel(
    const float* __restrict__ x,
    __half* __restrict__ hi, __half* __restrict__ lo, int n4)
{
    int i = blockIdx.x * 256 + threadIdx.x;
    if (i >= n4) return;
    float4 v = ((const float4*)x)[i];
    uint32_t h0, l0, h1, l1;
    split2h(v.x, v.y, h0, l0);
    split2h(v.z, v.w, h1, l1);
    ((uint32_t*)hi)[2 * i]     = h0;
    ((uint32_t*)hi)[2 * i + 1] = h1;
    ((uint32_t*)lo)[2 * i]     = l0;
    ((uint32_t*)lo)[2 * i + 1] = l1;
}

// fp32 -> fp16 single (weights)
__global__ __launch_bounds__(256) void conv_f16_kernel(
    const float* __restrict__ x, __half* __restrict__ o, int n4)
{
    int i = blockIdx.x * 256 + threadIdx.x;
    if (i >= n4) return;
    float4 v = ((const float4*)x)[i];
    __half2 a = __halves2half2(__float2half_rn(v.x), __float2half_rn(v.y));
    __half2 b = __halves2half2(__float2half_rn(v.z), __float2half_rn(v.w));
    ((__half2*)o)[2 * i]     = a;
    ((__half2*)o)[2 * i + 1] = b;
}

// ---------------------------------------------------------------------------
// fp16 HMMA GEMM: C = (Ah+Al) @ W^T + bias.  A fp16 pair, B fp16 single.
// CTA 128x128, BK=32, 2-stage cp.async, ldmatrix, 2 mma terms.
// OUT: 0 = fp32 C, 1 = bf16 pair (attention operands), 2 = fp16 pair
// ---------------------------------------------------------------------------
#define GS 40                            // elems/row (32 data + 8 pad)
#define GA_BYTES (128 * GS * 2)          // 10240 per array
#define GSTAGE_BYTES (3 * GA_BYTES)      // 30720 per stage (Ah,Al,B)
#define GSMEM (2 * GSTAGE_BYTES)         // 61440 total

template<bool RELU, int OUT>
__global__ __launch_bounds__(256) void gemm_f16_kernel(
    const __half* __restrict__ Ah, const __half* __restrict__ Al,
    const __half* __restrict__ B,
    const float* __restrict__ bias, float* __restrict__ C,
    void* __restrict__ Chv, void* __restrict__ Clv,
    int M, int N, int K)
{
    extern __shared__ char smem[];
    const uint32_t su = smem_u32(smem);

    const int tid  = threadIdx.x;
    const int lane = tid & 31;
    const int warp = tid >> 5;
    const int wm = (warp & 1) * 64;
    const int wn = (warp >> 1) * 32;
    const int m0 = blockIdx.y * 128;
    const int n0 = blockIdx.x * 128;

    // cp.async mapping: 2 threads per row, 32B each
    const int crow = tid >> 1;
    const uint32_t cc32 = (uint32_t)(tid & 1) * 32;
    const int ce = (tid & 1) * 16;

    const __half* gAh = Ah + (size_t)(m0 + crow) * K + ce;
    const __half* gAl = Al + (size_t)(m0 + crow) * K + ce;
    const __half* gB  = B  + (size_t)(n0 + crow) * K + ce;
    const uint32_t so = (uint32_t)crow * (GS * 2) + cc32;

    auto load_stage = [&](int i) {
        const uint32_t sb = su + (uint32_t)(i & 1) * GSTAGE_BYTES;
        const size_t kof = (size_t)i * 32;
        CP_ASYNC16(sb + 0 * GA_BYTES + so,      gAh + kof);
        CP_ASYNC16(sb + 0 * GA_BYTES + so + 16, gAh + kof + 8);
        CP_ASYNC16(sb + 1 * GA_BYTES + so,      gAl + kof);
        CP_ASYNC16(sb + 1 * GA_BYTES + so + 16, gAl + kof + 8);
        CP_ASYNC16(sb + 2 * GA_BYTES + so,      gB + kof);
        CP_ASYNC16(sb + 2 * GA_BYTES + so + 16, gB + kof + 8);
        CP_COMMIT();
    };

    // ldmatrix lane address offsets (bytes)
    const int l8 = lane & 7, lq = lane >> 3;
    const uint32_t aOff = (uint32_t)(((wm + l8 + (lq & 1) * 8) * GS + (lq >> 1) * 8) * 2);
    const uint32_t bOff = (uint32_t)(((wn + l8 + (lq >> 1) * 8) * GS + (lq & 1) * 8) * 2);

    float acc[4][4][4];
#pragma unroll
    for (int mi = 0; mi < 4; ++mi)
#pragma unroll
        for (int ni = 0; ni < 4; ++ni)
#pragma unroll
            for (int r = 0; r < 4; ++r) acc[mi][ni][r] = 0.f;

    load_stage(0);
    load_stage(1);
    const int nch = K >> 5;

    for (int i = 0; i < nch; ++i) {
        if (i + 1 < nch) { CP_WAIT1(); } else { CP_WAIT0(); }
        __syncthreads();
        const uint32_t sb = su + (uint32_t)(i & 1) * GSTAGE_BYTES;
#pragma unroll
        for (int ks = 0; ks < 2; ++ks) {
            const uint32_t ko = (uint32_t)ks * 32;   // 16 elems * 2B
            uint32_t aH[4][4], aL[4][4], bH[4][2];
#pragma unroll
            for (int mi = 0; mi < 4; ++mi) {
                const uint32_t ad = sb + 0 * GA_BYTES + aOff
                                  + (uint32_t)mi * (16 * GS * 2) + ko;
                ldsm_x4(aH[mi][0], aH[mi][1], aH[mi][2], aH[mi][3], ad);
                ldsm_x4(aL[mi][0], aL[mi][1], aL[mi][2], aL[mi][3], ad + GA_BYTES);
            }
#pragma unroll
            for (int np = 0; np < 2; ++np) {
                const uint32_t bd = sb + 2 * GA_BYTES + bOff
                                  + (uint32_t)np * (16 * GS * 2) + ko;
                ldsm_x4(bH[2 * np][0], bH[2 * np][1],
                        bH[2 * np + 1][0], bH[2 * np + 1][1], bd);
            }
#pragma unroll
            for (int mi = 0; mi < 4; ++mi)
#pragma unroll
                for (int ni = 0; ni < 4; ++ni) {
                    float* d = acc[mi][ni];
                    mma_f16(d[0], d[1], d[2], d[3],
                            aH[mi][0], aH[mi][1], aH[mi][2], aH[mi][3],
                            bH[ni][0], bH[ni][1]);
                    mma_f16(d[0], d[1], d[2], d[3],
                            aL[mi][0], aL[mi][1], aL[mi][2], aL[mi][3],
                            bH[ni][0], bH[ni][1]);
                }
        }
        __syncthreads();
        if (i + 2 < nch) load_stage(i + 2);
    }

    // epilogue (same fragment->matrix mapping as validated kernels)
#pragma unroll
    for (int mi = 0; mi < 4; ++mi) {
        const int m = m0 + wm + mi * 16 + (lane >> 2);
#pragma unroll
        for (int ni = 0; ni < 4; ++ni) {
            const int nc = n0 + wn + ni * 8 + 2 * (lane & 3);
            float b0 = bias[nc], b1 = bias[nc + 1];
            float c0 = acc[mi][ni][0] + b0, c1 = acc[mi][ni][1] + b1;
            float c2 = acc[mi][ni][2] + b0, c3 = acc[mi][ni][3] + b1;
            if (RELU) {
                c0 = fmaxf(c0, 0.f); c1 = fmaxf(c1, 0.f);
                c2 = fmaxf(c2, 0.f); c3 = fmaxf(c3, 0.f);
            }
            if (OUT == 0) {
                *(float2*)&C[(size_t)m * N + nc]       = make_float2(c0, c1);
                *(float2*)&C[(size_t)(m + 8) * N + nc] = make_float2(c2, c3);
            } else if (OUT == 1) {
                __nv_bfloat16* Ch = (__nv_bfloat16*)Chv;
                __nv_bfloat16* Cl = (__nv_bfloat16*)Clv;
                uint32_t h0, l0, h1, l1;
                split2(c0, c1, h0, l0);
                split2(c2, c3, h1, l1);
                *(uint32_t*)&Ch[(size_t)m * N + nc]       = h0;
                *(uint32_t*)&Cl[(size_t)m * N + nc]       = l0;
                *(uint32_t*)&Ch[(size_t)(m + 8) * N + nc] = h1;
                *(uint32_t*)&Cl[(size_t)(m + 8) * N + nc] = l1;
            } else {
                __half* Ch = (__half*)Chv;
                __half* Cl = (__half*)Clv;
                uint32_t h0, l0, h1, l1;
                split2h(c0, c1, h0, l0);
                split2h(c2, c3, h1, l1);
                *(uint32_t*)&Ch[(size_t)m * N + nc]       = h0;
                *(uint32_t*)&Cl[(size_t)m * N + nc]       = l0;
                *(uint32_t*)&Ch[(size_t)(m + 8) * N + nc] = h1;
                *(uint32_t*)&Cl[(size_t)(m + 8) * N + nc] = l1;
            }
        }
    }
}

// ---------------------------------------------------------------------------
// V transpose: Vh/Vl [token][512] -> Vth/Vtl [B][H][E=64][L=2048]
// ---------------------------------------------------------------------------
__global__ __launch_bounds__(256) void vtrans_kernel(
    const __nv_bfloat16* __restrict__ Vh, const __nv_bfloat16* __restrict__ Vl,
    __nv_bfloat16* __restrict__ Vth, __nv_bfloat16* __restrict__ Vtl)
{
    __shared__ __nv_bfloat16 th[64][72];
    __shared__ __nv_bfloat16 tl[64][72];
    const int lt = blockIdx.x, h = blockIdx.y, b = blockIdx.z;
    const int t = threadIdx.x;
    {
        int l = t >> 2, e0 = (t & 3) * 16;
        size_t g = ((size_t)(b * SEQ_L + lt * 64 + l)) * D_MODEL + h * 64 + e0;
        int4 a0 = *(const int4*)(Vh + g);
        int4 a1 = *(const int4*)(Vh + g + 8);
        *(int4*)&th[l][e0]     = a0;
        *(int4*)&th[l][e0 + 8] = a1;
        int4 c0 = *(const int4*)(Vl + g);
        int4 c1 = *(const int4*)(Vl + g + 8);
        *(int4*)&tl[l][e0]     = c0;
        *(int4*)&tl[l][e0 + 8] = c1;
    }
    __syncthreads();
    {
        int e = t >> 2, l0 = (t & 3) * 16;
        __align__(16) __nv_bfloat16 buf[16], buf2[16];
#pragma unroll
        for (int i = 0; i < 16; ++i) { buf[i] = th[l0 + i][e]; buf2[i] = tl[l0 + i][e]; }
        size_t g = ((size_t)((b * N_HEADS + h) * 64 + e)) * SEQ_L + lt * 64 + l0;
        ((int4*)(Vth + g))[0] = ((int4*)buf)[0];
        ((int4*)(Vth + g))[1] = ((int4*)buf)[1];
        ((int4*)(Vtl + g))[0] = ((int4*)buf2)[0];
        ((int4*)(Vtl + g))[1] = ((int4*)buf2)[1];
    }
}

// ---------------------------------------------------------------------------
// Tensor-core causal flash attention, bf16 hi/lo 3-term (HMMA path).
// Output written as fp16 hi/lo pair (feeds Wo GEMM).
// ---------------------------------------------------------------------------
#define AT_S 72

__global__ __launch_bounds__(256, 1) void attn_mma_kernel(
    const __nv_bfloat16* __restrict__ Qh, const __nv_bfloat16* __restrict__ Ql,
    const __nv_bfloat16* __restrict__ Kh, const __nv_bfloat16* __restrict__ Kl,
    const __nv_bfloat16* __restrict__ Vth, const __nv_bfloat16* __restrict__ Vtl,
    __half* __restrict__ Oh, __half* __restrict__ Ol)
{
    extern __shared__ __nv_bfloat16 smb[];
    __nv_bfloat16* sQh = smb;
    __nv_bfloat16* sQl = sQh + 128 * AT_S;
    __nv_bfloat16* sKh = sQl + 128 * AT_S;
    __nv_bfloat16* sKl = sKh + 64 * AT_S;
    __nv_bfloat16* sVh = sKl + 64 * AT_S;
    __nv_bfloat16* sVl = sVh + 64 * AT_S;

    const int tid = threadIdx.x, lane = tid & 31, warp = tid >> 5;
    const int qt = blockIdx.x, h = blockIdx.y, b = blockIdx.z;
    const int q0 = qt * 128;
    const size_t qkBase = ((size_t)b * SEQ_L) * D_MODEL + (size_t)h * HEAD_E;
    const size_t vtBase = ((size_t)(b * N_HEADS + h)) * HEAD_E * SEQ_L;

    {
        int row = tid >> 1, e0 = (tid & 1) * 32;
        size_t g = qkBase + (size_t)(q0 + row) * D_MODEL + e0;
        int4 a0 = *(const int4*)(Qh + g);
        int4 a1 = *(const int4*)(Qh + g + 8);
        int4 a2 = *(const int4*)(Qh + g + 16);
        int4 a3 = *(const int4*)(Qh + g + 24);
        int4* d = (int4*)(sQh + row * AT_S + e0);
        d[0] = a0; d[1] = a1; d[2] = a2; d[3] = a3;
        int4 c0 = *(const int4*)(Ql + g);
        int4 c1 = *(const int4*)(Ql + g + 8);
        int4 c2 = *(const int4*)(Ql + g + 16);
        int4 c3 = *(const int4*)(Ql + g + 24);
        int4* d2 = (int4*)(sQl + row * AT_S + e0);
        d2[0] = c0; d2[1] = c1; d2[2] = c2; d2[3] = c3;
    }

    float m0 = -1e30f, m1 = -1e30f, l0s = 0.f, l1s = 0.f;
    float oacc[8][4];
#pragma unroll
    for (int nt = 0; nt < 8; ++nt)
#pragma unroll
        for (int r = 0; r < 4; ++r) oacc[nt][r] = 0.f;

    const int ldr = tid >> 2;
    const int ldc = (tid & 3) * 16;
    const int nkt = 2 * qt + 2;

    int4 pKh0, pKh1, pKl0, pKl1, pVh0, pVh1, pVl0, pVl1;
    {
        size_t gk = qkBase + (size_t)(0 + ldr) * D_MODEL + ldc;
        pKh0 = *(const int4*)(Kh + gk);  pKh1 = *(const int4*)(Kh + gk + 8);
        pKl0 = *(const int4*)(Kl + gk);  pKl1 = *(const int4*)(Kl + gk + 8);
        size_t gv = vtBase + (size_t)ldr * SEQ_L + 0 + ldc;
        pVh0 = *(const int4*)(Vth + gv); pVh1 = *(const int4*)(Vth + gv + 8);
        pVl0 = *(const int4*)(Vtl + gv); pVl1 = *(const int4*)(Vtl + gv + 8);
    }

    const int gr  = warp * 16 + (lane >> 2);
    const int cc  = 2 * (lane & 3);

    for (int kt = 0; kt < nkt; ++kt) {
        const int k0 = kt * 64;
        __syncthreads();
        {
            int4* d;
            d = (int4*)(sKh + ldr * AT_S + ldc); d[0] = pKh0; d[1] = pKh1;
            d = (int4*)(sKl + ldr * AT_S + ldc); d[0] = pKl0; d[1] = pKl1;
            d = (int4*)(sVh + ldr * AT_S + ldc); d[0] = pVh0; d[1] = pVh1;
            d = (int4*)(sVl + ldr * AT_S + ldc); d[0] = pVl0; d[1] = pVl1;
        }
        __syncthreads();
        if (kt + 1 < nkt) {
            size_t gk = qkBase + (size_t)(k0 + 64 + ldr) * D_MODEL + ldc;
            pKh0 = *(const int4*)(Kh + gk);  pKh1 = *(const int4*)(Kh + gk + 8);
            pKl0 = *(const int4*)(Kl + gk);  pKl1 = *(const int4*)(Kl + gk + 8);
            size_t gv = vtBase + (size_t)ldr * SEQ_L + k0 + 64 + ldc;
            pVh0 = *(const int4*)(Vth + gv); pVh1 = *(const int4*)(Vth + gv + 8);
            pVl0 = *(const int4*)(Vtl + gv); pVl1 = *(const int4*)(Vtl + gv + 8);
        }

        float sacc[8][4];
#pragma unroll
        for (int nt = 0; nt < 8; ++nt)
#pragma unroll
            for (int r = 0; r < 4; ++r) sacc[nt][r] = 0.f;

#pragma unroll
        for (int es = 0; es < 4; ++es) {
            const int e = es * 16 + cc;
            uint32_t ah0 = *(const uint32_t*)&sQh[gr * AT_S + e];
            uint32_t ah1 = *(const uint32_t*)&sQh[(gr + 8) * AT_S + e];
            uint32_t ah2 = *(const uint32_t*)&sQh[gr * AT_S + e + 8];
            uint32_t ah3 = *(const uint32_t*)&sQh[(gr + 8) * AT_S + e + 8];
            uint32_t al0 = *(const uint32_t*)&sQl[gr * AT_S + e];
            uint32_t al1 = *(const uint32_t*)&sQl[(gr + 8) * AT_S + e];
            uint32_t al2 = *(const uint32_t*)&sQl[gr * AT_S + e + 8];
            uint32_t al3 = *(const uint32_t*)&sQl[(gr + 8) * AT_S + e + 8];
#pragma unroll
            for (int nt = 0; nt < 8; ++nt) {
                const int n = nt * 8 + (lane >> 2);
                uint32_t bh0 = *(const uint32_t*)&sKh[n * AT_S + e];
                uint32_t bh1 = *(const uint32_t*)&sKh[n * AT_S + e + 8];
                uint32_t bl0 = *(const uint32_t*)&sKl[n * AT_S + e];
                uint32_t bl1 = *(const uint32_t*)&sKl[n * AT_S + e + 8];
                float* dd = sacc[nt];
                mma_bf16(dd[0], dd[1], dd[2], dd[3], ah0, ah1, ah2, ah3, bh0, bh1);
                mma_bf16(dd[0], dd[1], dd[2], dd[3], ah0, ah1, ah2, ah3, bl0, bl1);
                mma_bf16(dd[0], dd[1], dd[2], dd[3], al0, al1, al2, al3, bh0, bh1);
            }
        }

        const float scl = 0.125f;
        if (kt >= 2 * qt) {
            const int qg0 = q0 + gr, qg1 = qg0 + 8;
#pragma unroll
            for (int nt = 0; nt < 8; ++nt) {
                const int kg = k0 + nt * 8 + cc;
                sacc[nt][0] = (kg     > qg0) ? -1e30f : sacc[nt][0] * scl;
                sacc[nt][1] = (kg + 1 > qg0) ? -1e30f : sacc[nt][1] * scl;
                sacc[nt][2] = (kg     > qg1) ? -1e30f : sacc[nt][2] * scl;
                sacc[nt][3] = (kg + 1 > qg1) ? -1e30f : sacc[nt][3] * scl;
            }
        } else {
#pragma unroll
            for (int nt = 0; nt < 8; ++nt) {
                sacc[nt][0] *= scl; sacc[nt][1] *= scl;
                sacc[nt][2] *= scl; sacc[nt][3] *= scl;
            }
        }

        float mx0 = -1e30f, mx1 = -1e30f;
#pragma unroll
        for (int nt = 0; nt < 8; ++nt) {
            mx0 = fmaxf(mx0, fmaxf(sacc[nt][0], sacc[nt][1]));
            mx1 = fmaxf(mx1, fmaxf(sacc[nt][2], sacc[nt][3]));
        }
        mx0 = fmaxf(mx0, __shfl_xor_sync(0xffffffffu, mx0, 1));
        mx0 = fmaxf(mx0, __shfl_xor_sync(0xffffffffu, mx0, 2));
        mx1 = fmaxf(mx1, __shfl_xor_sync(0xffffffffu, mx1, 1));
        mx1 = fmaxf(mx1, __shfl_xor_sync(0xffffffffu, mx1, 2));
        const float mn0 = fmaxf(m0, mx0), mn1 = fmaxf(m1, mx1);
        const float a0 = __expf(m0 - mn0), a1 = __expf(m1 - mn1);
        m0 = mn0; m1 = mn1;

        float s0 = 0.f, s1 = 0.f;
        uint32_t pH[4][4], pL[4][4];
#pragma unroll
        for (int ks = 0; ks < 4; ++ks) {
            const int n0t = 2 * ks, n1t = 2 * ks + 1;
            float p00 = __expf(sacc[n0t][0] - mn0);
            float p01 = __expf(sacc[n0t][1] - mn0);
            float p10 = __expf(sacc[n0t][2] - mn1);
            float p11 = __expf(sacc[n0t][3] - mn1);
            float p20 = __expf(sacc[n1t][0] - mn0);
            float p21 = __expf(sacc[n1t][1] - mn0);
            float p30 = __expf(sacc[n1t][2] - mn1);
            float p31 = __expf(sacc[n1t][3] - mn1);
            s0 += p00 + p01 + p20 + p21;
            s1 += p10 + p11 + p30 + p31;
            split2(p00, p01, pH[ks][0], pL[ks][0]);
            split2(p10, p11, pH[ks][1], pL[ks][1]);
            split2(p20, p21, pH[ks][2], pL[ks][2]);
            split2(p30, p31, pH[ks][3], pL[ks][3]);
        }
        s0 += __shfl_xor_sync(0xffffffffu, s0, 1);
        s0 += __shfl_xor_sync(0xffffffffu, s0, 2);
        s1 += __shfl_xor_sync(0xffffffffu, s1, 1);
        s1 += __shfl_xor_sync(0xffffffffu, s1, 2);
        l0s = l0s * a0 + s0;
        l1s = l1s * a1 + s1;
#pragma unroll
        for (int nt = 0; nt < 8; ++nt) {
            oacc[nt][0] *= a0; oacc[nt][1] *= a0;
            oacc[nt][2] *= a1; oacc[nt][3] *= a1;
        }

#pragma unroll
        for (int ks = 0; ks < 4; ++ks) {
            const int kk = ks * 16 + cc;
#pragma unroll
            for (int nt = 0; nt < 8; ++nt) {
                const int n = nt * 8 + (lane >> 2);
                uint32_t bh0 = *(const uint32_t*)&sVh[n * AT_S + kk];
                uint32_t bh1 = *(const uint32_t*)&sVh[n * AT_S + kk + 8];
                uint32_t bl0 = *(const uint32_t*)&sVl[n * AT_S + kk];
                uint32_t bl1 = *(const uint32_t*)&sVl[n * AT_S + kk + 8];
                float* dd = oacc[nt];
                mma_bf16(dd[0], dd[1], dd[2], dd[3],
                         pH[ks][0], pH[ks][1], pH[ks][2], pH[ks][3], bh0, bh1);
                mma_bf16(dd[0], dd[1], dd[2], dd[3],
                         pH[ks][0], pH[ks][1], pH[ks][2], pH[ks][3], bl0, bl1);
                mma_bf16(dd[0], dd[1], dd[2], dd[3],
                         pL[ks][0], pL[ks][1], pL[ks][2], pL[ks][3], bh0, bh1);
            }
        }
    }

    const float inv0 = 1.f / l0s, inv1 = 1.f / l1s;
    const size_t r0 = qkBase + (size_t)(q0 + gr) * D_MODEL + cc;
    const size_t r1 = r0 + 8 * D_MODEL;
#pragma unroll
    for (int nt = 0; nt < 8; ++nt) {
        uint32_t h0, lo0, h1, lo1;
        split2h(oacc[nt][0] * inv0, oacc[nt][1] * inv0, h0, lo0);
        split2h(oacc[nt][2] * inv1, oacc[nt][3] * inv1, h1, lo1);
        *(uint32_t*)&Oh[r0 + nt * 8] = h0;
        *(uint32_t*)&Ol[r0 + nt * 8] = lo0;
        *(uint32_t*)&Oh[r1 + nt * 8] = h1;
        *(uint32_t*)&Ol[r1 + nt * 8] = lo1;
    }
}

// ---------------------------------------------------------------------------
// Residual + LayerNorm (rows of 512); optional fp32 out + fp16-pair split out
// ---------------------------------------------------------------------------
template<bool F32OUT, bool SPLITOUT>
__global__ __launch_bounds__(128) void residual_ln_kernel(
    const float* __restrict__ a, const float* __restrict__ b,
    const float* __restrict__ gamma, const float* __restrict__ beta,
    float* __restrict__ out,
    __half* __restrict__ outh, __half* __restrict__ outl)
{
    const int row = blockIdx.x;
    const int tid = threadIdx.x;
    const size_t base = (size_t)row * D_VALUE;

    float4 va = ((const float4*)(a + base))[tid];
    float4 vb = ((const float4*)(b + base))[tid];
    float4 v = make_float4(va.x + vb.x, va.y + vb.y, va.z + vb.z, va.w + vb.w);

    float s  = v.x + v.y + v.z + v.w;
    float ss = v.x * v.x + v.y * v.y + v.z * v.z + v.w * v.w;
#pragma unroll
    for (int off = 16; off >= 1; off >>= 1) {
        s  += __shfl_xor_sync(0xffffffffu, s, off);
        ss += __shfl_xor_sync(0xffffffffu, ss, off);
    }
    __shared__ float red[8];
    const int wid = tid >> 5;
    if ((tid & 31) == 0) { red[wid] = s; red[4 + wid] = ss; }
    __syncthreads();
    s  = red[0] + red[1] + red[2] + red[3];
    ss = red[4] + red[5] + red[6] + red[7];

    const float mu = s * (1.f / (float)D_VALUE);
    float var = ss * (1.f / (float)D_VALUE) - mu * mu;
    const float rn = rsqrtf(var + 1e-5f);

    float4 g4 = ((const float4*)gamma)[tid];
    float4 b4 = ((const float4*)beta)[tid];
    float4 r;
    r.x = (v.x - mu) * rn * g4.x + b4.x;
    r.y = (v.y - mu) * rn * g4.y + b4.y;
    r.z = (v.z - mu) * rn * g4.z + b4.z;
    r.w = (v.w - mu) * rn * g4.w + b4.w;
    if (F32OUT) ((float4*)(out + base))[tid] = r;
    if (SPLITOUT) {
        uint32_t h0, l0, h1, l1;
        split2h(r.x, r.y, h0, l0);
        split2h(r.z, r.w, h1, l1);
        ((uint32_t*)(outh + base))[2 * tid]     = h0;
        ((uint32_t*)(outh + base))[2 * tid + 1] = h1;
        ((uint32_t*)(outl + base))[2 * tid]     = l0;
        ((uint32_t*)(outl + base))[2 * tid + 1] = l1;
    }
}

// ---------------------------------------------------------------------------
// Launch
// ---------------------------------------------------------------------------
static inline void run_split_f16(const float* x, __half* hi, __half* lo, int n)
{
    int n4 = n / 4;
    split_f16_kernel<<<(n4 + 255) / 256, 256>>>(x, hi, lo, n4);
}

static inline void run_conv_f16(const float* x, __half* o, int n)
{
    int n4 = n / 4;
    conv_f16_kernel<<<(n4 + 255) / 256, 256>>>(x, o, n4);
}

template<bool RELU, int OUT>
static inline void run_gemm(
    const __half* Ah, const __half* Al, const __half* B,
    const float* bias, float* C, void* Ch, void* Cl,
    int M, int N, int K)
{
    cudaFuncSetAttribute(gemm_f16_kernel<RELU, OUT>,
                         cudaFuncAttributeMaxDynamicSharedMemorySize, GSMEM);
    gemm_f16_kernel<RELU, OUT><<<dim3(N / 128, M / 128), 256, GSMEM>>>(
        Ah, Al, B, bias, C, Ch, Cl, M, N, K);
}

extern "C" void kernel_launch(void* const* d_in, const int* in_sizes, int n_in,
                              void* d_out, int out_size)
{
    const float* q   = (const float*)d_in[0];
    const float* k   = (const float*)d_in[1];
    const float* v   = (const float*)d_in[2];
    const float* Wq  = (const float*)d_in[3];
    const float* bq  = (const float*)d_in[4];
    const float* Wk  = (const float*)d_in[5];
    const float* bk  = (const float*)d_in[6];
    const float* Wv  = (const float*)d_in[7];
    const float* bv  = (const float*)d_in[8];
    const float* Wo  = (const float*)d_in[9];
    const float* bo  = (const float*)d_in[10];
    const float* Wc1 = (const float*)d_in[11];
    const float* bc1 = (const float*)d_in[12];
    const float* Wc2 = (const float*)d_in[13];
    const float* bc2 = (const float*)d_in[14];
    const float* g1  = (const float*)d_in[15];
    const float* b1  = (const float*)d_in[16];
    const float* g2  = (const float*)d_in[17];
    const float* b2  = (const float*)d_in[18];
    const float* Wl  = (const float*)d_in[19];
    const float* bl  = (const float*)d_in[20];
    float* out = (float*)d_out;

    float *Proj, *X, *Y;
    __half *Ah, *Al, *W, *Ohp, *Olp, *Xh, *Xl, *Fh, *Fl, *X2h, *X2l;
    __nv_bfloat16 *Qh, *Ql, *Kh, *Kl, *Vh, *Vl, *Vth, *Vtl;
    cudaGetSymbolAddress((void**)&Proj, g_proj);
    cudaGetSymbolAddress((void**)&X,    g_x);
    cudaGetSymbolAddress((void**)&Y,    g_y);
    cudaGetSymbolAddress((void**)&Ah,   g_Ah);
    cudaGetSymbolAddress((void**)&Al,   g_Al);
    cudaGetSymbolAddress((void**)&W,    g_W);
    cudaGetSymbolAddress((void**)&Ohp,  g_Oh);
    cudaGetSymbolAddress((void**)&Olp,  g_Ol);
    cudaGetSymbolAddress((void**)&Xh,   g_Xh);
    cudaGetSymbolAddress((void**)&Xl,   g_Xl);
    cudaGetSymbolAddress((void**)&Fh,   g_Fh);
    cudaGetSymbolAddress((void**)&Fl,   g_Fl);
    cudaGetSymbolAddress((void**)&X2h,  g_X2h);
    cudaGetSymbolAddress((void**)&X2l,  g_X2l);
    cudaGetSymbolAddress((void**)&Qh,   g_Qh);
    cudaGetSymbolAddress((void**)&Ql,   g_Ql);
    cudaGetSymbolAddress((void**)&Kh,   g_Kh);
    cudaGetSymbolAddress((void**)&Kl,   g_Kl);
    cudaGetSymbolAddress((void**)&Vh,   g_Vh);
    cudaGetSymbolAddress((void**)&Vl,   g_Vl);
    cudaGetSymbolAddress((void**)&Vth,  g_Vth);
    cudaGetSymbolAddress((void**)&Vtl,  g_Vtl);

    // ---- QKV projections -> bf16-pair outputs for attention ----
    run_split_f16(q, Ah, Al, M_ROWS * D_MODEL);
    run_conv_f16(Wq, W, D_MODEL * D_MODEL);
    run_gemm<false, 1>(Ah, Al, W, bq, nullptr, Qh, Ql, M_ROWS, D_MODEL, D_MODEL);

    run_split_f16(k, Ah, Al, M_ROWS * D_MODEL);
    run_conv_f16(Wk, W, D_MODEL * D_MODEL);
    run_gemm<false, 1>(Ah, Al, W, bk, nullptr, Kh, Kl, M_ROWS, D_MODEL, D_MODEL);

    run_split_f16(v, Ah, Al, M_ROWS * D_MODEL);
    run_conv_f16(Wv, W, D_MODEL * D_MODEL);
    run_gemm<false, 1>(Ah, Al, W, bv, nullptr, Vh, Vl, M_ROWS, D_MODEL, D_MODEL);

    // ---- V transpose per head ----
    vtrans_kernel<<<dim3(SEQ_L / 64, N_HEADS, B_BATCH), 256>>>(Vh, Vl, Vth, Vtl);

    // ---- attention (bf16 3-term HMMA) -> fp16-pair O ----
    {
        int smem = (2 * 128 + 4 * 64) * AT_S * 2;  // 73728 B
        cudaFuncSetAttribute(attn_mma_kernel,
                             cudaFuncAttributeMaxDynamicSharedMemorySize, smem);
        attn_mma_kernel<<<dim3(SEQ_L / 128, N_HEADS, B_BATCH), 256, smem>>>(
            Qh, Ql, Kh, Kl, Vth, Vtl, Ohp, Olp);
    }

    // ---- output projection (fp32 out) ----
    run_conv_f16(Wo, W, D_MODEL * D_VALUE);
    run_gemm<false, 0>(Ohp, Olp, W, bo, Proj, nullptr, nullptr,
                       M_ROWS, D_MODEL, D_MODEL);

    // ---- residual + LN1 (fp32 X + fp16-pair split) ----
    residual_ln_kernel<true, true><<<M_ROWS, 128>>>(v, Proj, g1, b1, X, Xh, Xl);

    // ---- FFN ----
    run_conv_f16(Wc1, W, D_FF * D_VALUE);
    run_gemm<true, 2>(Xh, Xl, W, bc1, nullptr, Fh, Fl, M_ROWS, D_FF, D_VALUE);

    run_conv_f16(Wc2, W, D_VALUE * D_FF);
    run_gemm<false, 0>(Fh, Fl, W, bc2, Y, nullptr, nullptr,
                       M_ROWS, D_VALUE, D_FF);

    // ---- residual + LN2 (fp16-pair split only) ----
    residual_ln_kernel<false, true><<<M_ROWS, 128>>>(X, Y, g2, b2, nullptr, X2h, X2l);

    // ---- final projection ----
    run_conv_f16(Wl, W, D_MODEL * D_VALUE);
    run_gemm<false, 0>(X2h, X2l, W, bl, out, nullptr, nullptr,
                       M_ROWS, D_MODEL, D_VALUE);
}

// round 13
// speedup vs baseline: 3.2327x; 1.1257x over previous
#include <cuda_runtime.h>
#include <cuda_fp16.h>
#include <cstdint>

// ---------------------------------------------------------------------------
// Problem constants
// ---------------------------------------------------------------------------
#define B_BATCH 4
#define SEQ_L   2048
#define D_MODEL 512
#define D_VALUE 512
#define N_HEADS 8
#define HEAD_E  64
#define D_FF    2048
#define M_ROWS  (B_BATCH * SEQ_L)   // 8192

// ---------------------------------------------------------------------------
// Scratch (static device allocations)
// ---------------------------------------------------------------------------
__device__ float g_proj[M_ROWS * D_MODEL];
__device__ float g_x   [M_ROWS * D_VALUE];
__device__ float g_y   [M_ROWS * D_VALUE];

__device__ __half g_Ah [M_ROWS * D_MODEL];
__device__ __half g_Al [M_ROWS * D_MODEL];
__device__ __half g_W  [D_FF * D_VALUE];
__device__ __half g_Qh [M_ROWS * D_MODEL];
__device__ __half g_Ql [M_ROWS * D_MODEL];
__device__ __half g_K  [M_ROWS * D_MODEL];
__device__ __half g_V  [M_ROWS * D_MODEL];
__device__ __half g_Vt [M_ROWS * D_MODEL];   // [B][H][E][L]
__device__ __half g_Oh [M_ROWS * D_MODEL];
__device__ __half g_Ol [M_ROWS * D_MODEL];
__device__ __half g_Xh [M_ROWS * D_VALUE];
__device__ __half g_Xl [M_ROWS * D_VALUE];
__device__ __half g_Fh [M_ROWS * D_FF];
__device__ __half g_Fl [M_ROWS * D_FF];
__device__ __half g_X2h[M_ROWS * D_VALUE];
__device__ __half g_X2l[M_ROWS * D_VALUE];

// ---------------------------------------------------------------------------
// helpers
// ---------------------------------------------------------------------------
__device__ __forceinline__ void split2h(float x, float y, uint32_t& hi, uint32_t& lo)
{
    __half hx = __float2half_rn(x);
    __half hy = __float2half_rn(y);
    __half2 h2 = __halves2half2(hx, hy);
    __half2 l2 = __halves2half2(
        __float2half_rn(x - __half2float(hx)),
        __float2half_rn(y - __half2float(hy)));
    hi = *reinterpret_cast<uint32_t*>(&h2);
    lo = *reinterpret_cast<uint32_t*>(&l2);
}

__device__ __forceinline__ void mma_f16(
    float& d0, float& d1, float& d2, float& d3,
    uint32_t a0, uint32_t a1, uint32_t a2, uint32_t a3,
    uint32_t b0, uint32_t b1)
{
    asm volatile(
        "mma.sync.aligned.m16n8k16.row.col.f32.f16.f16.f32 "
        "{%0,%1,%2,%3}, {%4,%5,%6,%7}, {%8,%9}, {%0,%1,%2,%3};"
        : "+f"(d0), "+f"(d1), "+f"(d2), "+f"(d3)
        : "r"(a0), "r"(a1), "r"(a2), "r"(a3), "r"(b0), "r"(b1));
}

__device__ __forceinline__ uint32_t smem_u32(const void* p)
{
    uint32_t a;
    asm("{ .reg .u64 t; cvta.to.shared.u64 t, %1; cvt.u32.u64 %0, t; }"
        : "=r"(a) : "l"(p));
    return a;
}

__device__ __forceinline__ void ldsm_x4(
    uint32_t& r0, uint32_t& r1, uint32_t& r2, uint32_t& r3, uint32_t addr)
{
    asm volatile(
        "ldmatrix.sync.aligned.m8n8.x4.shared.b16 {%0,%1,%2,%3}, [%4];"
        : "=r"(r0), "=r"(r1), "=r"(r2), "=r"(r3) : "r"(addr));
}

#define CP_ASYNC16(dst, src) \
    asm volatile("cp.async.cg.shared.global [%0], [%1], 16;" \
                 :: "r"(dst), "l"(src) : "memory")
#define CP_COMMIT() asm volatile("cp.async.commit_group;" ::: "memory")
#define CP_WAIT1()  asm volatile("cp.async.wait_group 1;" ::: "memory")
#define CP_WAIT0()  asm volatile("cp.async.wait_group 0;" ::: "memory")

// ---------------------------------------------------------------------------
// Split fp32 -> fp16 hi + fp16 lo (activations)
// ---------------------------------------------------------------------------
__global__ __launch_bounds__(256) void split_f16_kernel(
    const float* __restrict__ x,
    __half* __restrict__ hi, __half* __restrict__ lo, int n4)
{
    int i = blockIdx.x * 256 + threadIdx.x;
    if (i >= n4) return;
    float4 v = ((const float4*)x)[i];
    uint32_t h0, l0, h1, l1;
    split2h(v.x, v.y, h0, l0);
    split2h(v.z, v.w, h1, l1);
    ((uint32_t*)hi)[2 * i]     = h0;
    ((uint32_t*)hi)[2 * i + 1] = h1;
    ((uint32_t*)lo)[2 * i]     = l0;
    ((uint32_t*)lo)[2 * i + 1] = l1;
}

// fp32 -> fp16 single (weights)
__global__ __launch_bounds__(256) void conv_f16_kernel(
    const float* __restrict__ x, __half* __restrict__ o, int n4)
{
    int i = blockIdx.x * 256 + threadIdx.x;
    if (i >= n4) return;
    float4 v = ((const float4*)x)[i];
    __half2 a = __halves2half2(__float2half_rn(v.x), __float2half_rn(v.y));
    __half2 b = __halves2half2(__float2half_rn(v.z), __float2half_rn(v.w));
    ((__half2*)o)[2 * i]     = a;
    ((__half2*)o)[2 * i + 1] = b;
}

// ---------------------------------------------------------------------------
// fp16 HMMA GEMM: C = (Ah+Al) @ W^T + bias.  A fp16 pair, B fp16 single.
// CTA 128x128, BK=32, 2-stage cp.async, ldmatrix, 2 mma terms.
// OUT: 0 = fp32 C, 2 = fp16 pair, 3 = fp16 single
// ---------------------------------------------------------------------------
#define GS 40
#define GA_BYTES (128 * GS * 2)          // 10240 per array
#define GSTAGE_BYTES (3 * GA_BYTES)      // 30720 per stage (Ah,Al,B)
#define GSMEM (2 * GSTAGE_BYTES)         // 61440 total

template<bool RELU, int OUT>
__global__ __launch_bounds__(256) void gemm_f16_kernel(
    const __half* __restrict__ Ah, const __half* __restrict__ Al,
    const __half* __restrict__ B,
    const float* __restrict__ bias, float* __restrict__ C,
    __half* __restrict__ Ch, __half* __restrict__ Cl,
    int M, int N, int K)
{
    extern __shared__ char smem[];
    const uint32_t su = smem_u32(smem);

    const int tid  = threadIdx.x;
    const int lane = tid & 31;
    const int warp = tid >> 5;
    const int wm = (warp & 1) * 64;
    const int wn = (warp >> 1) * 32;
    const int m0 = blockIdx.y * 128;
    const int n0 = blockIdx.x * 128;

    const int crow = tid >> 1;
    const uint32_t cc32 = (uint32_t)(tid & 1) * 32;
    const int ce = (tid & 1) * 16;

    const __half* gAh = Ah + (size_t)(m0 + crow) * K + ce;
    const __half* gAl = Al + (size_t)(m0 + crow) * K + ce;
    const __half* gB  = B  + (size_t)(n0 + crow) * K + ce;
    const uint32_t so = (uint32_t)crow * (GS * 2) + cc32;

    auto load_stage = [&](int i) {
        const uint32_t sb = su + (uint32_t)(i & 1) * GSTAGE_BYTES;
        const size_t kof = (size_t)i * 32;
        CP_ASYNC16(sb + 0 * GA_BYTES + so,      gAh + kof);
        CP_ASYNC16(sb + 0 * GA_BYTES + so + 16, gAh + kof + 8);
        CP_ASYNC16(sb + 1 * GA_BYTES + so,      gAl + kof);
        CP_ASYNC16(sb + 1 * GA_BYTES + so + 16, gAl + kof + 8);
        CP_ASYNC16(sb + 2 * GA_BYTES + so,      gB + kof);
        CP_ASYNC16(sb + 2 * GA_BYTES + so + 16, gB + kof + 8);
        CP_COMMIT();
    };

    const int l8 = lane & 7, lq = lane >> 3;
    const uint32_t aOff = (uint32_t)(((wm + l8 + (lq & 1) * 8) * GS + (lq >> 1) * 8) * 2);
    const uint32_t bOff = (uint32_t)(((wn + l8 + (lq >> 1) * 8) * GS + (lq & 1) * 8) * 2);

    float acc[4][4][4];
#pragma unroll
    for (int mi = 0; mi < 4; ++mi)
#pragma unroll
        for (int ni = 0; ni < 4; ++ni)
#pragma unroll
            for (int r = 0; r < 4; ++r) acc[mi][ni][r] = 0.f;

    load_stage(0);
    load_stage(1);
    const int nch = K >> 5;

    for (int i = 0; i < nch; ++i) {
        if (i + 1 < nch) { CP_WAIT1(); } else { CP_WAIT0(); }
        __syncthreads();
        const uint32_t sb = su + (uint32_t)(i & 1) * GSTAGE_BYTES;
#pragma unroll
        for (int ks = 0; ks < 2; ++ks) {
            const uint32_t ko = (uint32_t)ks * 32;
            uint32_t aH[4][4], aL[4][4], bH[4][2];
#pragma unroll
            for (int mi = 0; mi < 4; ++mi) {
                const uint32_t ad = sb + 0 * GA_BYTES + aOff
                                  + (uint32_t)mi * (16 * GS * 2) + ko;
                ldsm_x4(aH[mi][0], aH[mi][1], aH[mi][2], aH[mi][3], ad);
                ldsm_x4(aL[mi][0], aL[mi][1], aL[mi][2], aL[mi][3], ad + GA_BYTES);
            }
#pragma unroll
            for (int np = 0; np < 2; ++np) {
                const uint32_t bd = sb + 2 * GA_BYTES + bOff
                                  + (uint32_t)np * (16 * GS * 2) + ko;
                ldsm_x4(bH[2 * np][0], bH[2 * np][1],
                        bH[2 * np + 1][0], bH[2 * np + 1][1], bd);
            }
#pragma unroll
            for (int mi = 0; mi < 4; ++mi)
#pragma unroll
                for (int ni = 0; ni < 4; ++ni) {
                    float* d = acc[mi][ni];
                    mma_f16(d[0], d[1], d[2], d[3],
                            aH[mi][0], aH[mi][1], aH[mi][2], aH[mi][3],
                            bH[ni][0], bH[ni][1]);
                    mma_f16(d[0], d[1], d[2], d[3],
                            aL[mi][0], aL[mi][1], aL[mi][2], aL[mi][3],
                            bH[ni][0], bH[ni][1]);
                }
        }
        __syncthreads();
        if (i + 2 < nch) load_stage(i + 2);
    }

#pragma unroll
    for (int mi = 0; mi < 4; ++mi) {
        const int m = m0 + wm + mi * 16 + (lane >> 2);
#pragma unroll
        for (int ni = 0; ni < 4; ++ni) {
            const int nc = n0 + wn + ni * 8 + 2 * (lane & 3);
            float b0 = bias[nc], b1 = bias[nc + 1];
            float c0 = acc[mi][ni][0] + b0, c1 = acc[mi][ni][1] + b1;
            float c2 = acc[mi][ni][2] + b0, c3 = acc[mi][ni][3] + b1;
            if (RELU) {
                c0 = fmaxf(c0, 0.f); c1 = fmaxf(c1, 0.f);
                c2 = fmaxf(c2, 0.f); c3 = fmaxf(c3, 0.f);
            }
            if (OUT == 0) {
                *(float2*)&C[(size_t)m * N + nc]       = make_float2(c0, c1);
                *(float2*)&C[(size_t)(m + 8) * N + nc] = make_float2(c2, c3);
            } else if (OUT == 2) {
                uint32_t h0, l0, h1, l1;
                split2h(c0, c1, h0, l0);
                split2h(c2, c3, h1, l1);
                *(uint32_t*)&Ch[(size_t)m * N + nc]       = h0;
                *(uint32_t*)&Cl[(size_t)m * N + nc]       = l0;
                *(uint32_t*)&Ch[(size_t)(m + 8) * N + nc] = h1;
                *(uint32_t*)&Cl[(size_t)(m + 8) * N + nc] = l1;
            } else {
                __half2 h0 = __halves2half2(__float2half_rn(c0), __float2half_rn(c1));
                __half2 h1 = __halves2half2(__float2half_rn(c2), __float2half_rn(c3));
                *(__half2*)&Ch[(size_t)m * N + nc]       = h0;
                *(__half2*)&Ch[(size_t)(m + 8) * N + nc] = h1;
            }
        }
    }
}

// ---------------------------------------------------------------------------
// V transpose (fp16 single): V [token][512] -> Vt [B][H][E=64][L=2048]
// ---------------------------------------------------------------------------
__global__ __launch_bounds__(256) void vtrans_kernel(
    const __half* __restrict__ V, __half* __restrict__ Vt)
{
    __shared__ __half tile[64][72];
    const int lt = blockIdx.x, h = blockIdx.y, b = blockIdx.z;
    const int t = threadIdx.x;
    {
        int l = t >> 2, e0 = (t & 3) * 16;
        size_t g = ((size_t)(b * SEQ_L + lt * 64 + l)) * D_MODEL + h * 64 + e0;
        int4 a0 = *(const int4*)(V + g);
        int4 a1 = *(const int4*)(V + g + 8);
        *(int4*)&tile[l][e0]     = a0;
        *(int4*)&tile[l][e0 + 8] = a1;
    }
    __syncthreads();
    {
        int e = t >> 2, l0 = (t & 3) * 16;
        __align__(16) __half buf[16];
#pragma unroll
        for (int i = 0; i < 16; ++i) buf[i] = tile[l0 + i][e];
        size_t g = ((size_t)((b * N_HEADS + h) * 64 + e)) * SEQ_L + lt * 64 + l0;
        ((int4*)(Vt + g))[0] = ((int4*)buf)[0];
        ((int4*)(Vt + g))[1] = ((int4*)buf)[1];
    }
}

// ---------------------------------------------------------------------------
// fp16 tensor-core causal flash attention:
// Q = fp16 pair (2-term), K/V = fp16 single, P = fp16 pair (2-term).
// 128q x 64k tile, 8 warps. Output = fp16 pair.
// ---------------------------------------------------------------------------
#define AT_S 72
#define AT_SMEM ((2 * 128 + 2 * 64) * AT_S * 2)   // 55296 B

__global__ __launch_bounds__(256, 1) void attn_mma_kernel(
    const __half* __restrict__ Qh, const __half* __restrict__ Ql,
    const __half* __restrict__ K,  const __half* __restrict__ Vt,
    __half* __restrict__ Oh, __half* __restrict__ Ol)
{
    extern __shared__ __half smh[];
    __half* sQh = smh;
    __half* sQl = sQh + 128 * AT_S;
    __half* sK  = sQl + 128 * AT_S;
    __half* sV  = sK  + 64 * AT_S;

    const int tid = threadIdx.x, lane = tid & 31, warp = tid >> 5;
    const int qt = blockIdx.x, h = blockIdx.y, b = blockIdx.z;
    const int q0 = qt * 128;
    const size_t qkBase = ((size_t)b * SEQ_L) * D_MODEL + (size_t)h * HEAD_E;
    const size_t vtBase = ((size_t)(b * N_HEADS + h)) * HEAD_E * SEQ_L;

    // ---- load Q tile (pair): 128 rows x 64 cols, 32 elems/thread/array ----
    {
        int row = tid >> 1, e0 = (tid & 1) * 32;
        size_t g = qkBase + (size_t)(q0 + row) * D_MODEL + e0;
        int4 a0 = *(const int4*)(Qh + g);
        int4 a1 = *(const int4*)(Qh + g + 8);
        int4 a2 = *(const int4*)(Qh + g + 16);
        int4 a3 = *(const int4*)(Qh + g + 24);
        int4* d = (int4*)(sQh + row * AT_S + e0);
        d[0] = a0; d[1] = a1; d[2] = a2; d[3] = a3;
        int4 c0 = *(const int4*)(Ql + g);
        int4 c1 = *(const int4*)(Ql + g + 8);
        int4 c2 = *(const int4*)(Ql + g + 16);
        int4 c3 = *(const int4*)(Ql + g + 24);
        int4* d2 = (int4*)(sQl + row * AT_S + e0);
        d2[0] = c0; d2[1] = c1; d2[2] = c2; d2[3] = c3;
    }

    float m0 = -1e30f, m1 = -1e30f, l0s = 0.f, l1s = 0.f;
    float oacc[8][4];
#pragma unroll
    for (int nt = 0; nt < 8; ++nt)
#pragma unroll
        for (int r = 0; r < 4; ++r) oacc[nt][r] = 0.f;

    const int ldr = tid >> 2;            // 0..63
    const int ldc = (tid & 3) * 16;      // 16 elems/thread
    const int nkt = 2 * qt + 2;

    int4 pK0, pK1, pV0, pV1;
    {
        size_t gk = qkBase + (size_t)ldr * D_MODEL + ldc;
        pK0 = *(const int4*)(K + gk); pK1 = *(const int4*)(K + gk + 8);
        size_t gv = vtBase + (size_t)ldr * SEQ_L + ldc;
        pV0 = *(const int4*)(Vt + gv); pV1 = *(const int4*)(Vt + gv + 8);
    }

    const int gr = warp * 16 + (lane >> 2);
    const int cc = 2 * (lane & 3);

    for (int kt = 0; kt < nkt; ++kt) {
        const int k0 = kt * 64;
        __syncthreads();
        {
            int4* d;
            d = (int4*)(sK + ldr * AT_S + ldc); d[0] = pK0; d[1] = pK1;
            d = (int4*)(sV + ldr * AT_S + ldc); d[0] = pV0; d[1] = pV1;
        }
        __syncthreads();
        if (kt + 1 < nkt) {
            size_t gk = qkBase + (size_t)(k0 + 64 + ldr) * D_MODEL + ldc;
            pK0 = *(const int4*)(K + gk); pK1 = *(const int4*)(K + gk + 8);
            size_t gv = vtBase + (size_t)ldr * SEQ_L + k0 + 64 + ldc;
            pV0 = *(const int4*)(Vt + gv); pV1 = *(const int4*)(Vt + gv + 8);
        }

        // ---- S = (Qh + Ql) K^T : 2 mma terms ----
        float sacc[8][4];
#pragma unroll
        for (int nt = 0; nt < 8; ++nt)
#pragma unroll
            for (int r = 0; r < 4; ++r) sacc[nt][r] = 0.f;

#pragma unroll
        for (int es = 0; es < 4; ++es) {
            const int e = es * 16 + cc;
            uint32_t ah0 = *(const uint32_t*)&sQh[gr * AT_S + e];
            uint32_t ah1 = *(const uint32_t*)&sQh[(gr + 8) * AT_S + e];
            uint32_t ah2 = *(const uint32_t*)&sQh[gr * AT_S + e + 8];
            uint32_t ah3 = *(const uint32_t*)&sQh[(gr + 8) * AT_S + e + 8];
            uint32_t al0 = *(const uint32_t*)&sQl[gr * AT_S + e];
            uint32_t al1 = *(const uint32_t*)&sQl[(gr + 8) * AT_S + e];
            uint32_t al2 = *(const uint32_t*)&sQl[gr * AT_S + e + 8];
            uint32_t al3 = *(const uint32_t*)&sQl[(gr + 8) * AT_S + e + 8];
#pragma unroll
            for (int nt = 0; nt < 8; ++nt) {
                const int n = nt * 8 + (lane >> 2);
                uint32_t b0 = *(const uint32_t*)&sK[n * AT_S + e];
                uint32_t b1 = *(const uint32_t*)&sK[n * AT_S + e + 8];
                float* dd = sacc[nt];
                mma_f16(dd[0], dd[1], dd[2], dd[3], ah0, ah1, ah2, ah3, b0, b1);
                mma_f16(dd[0], dd[1], dd[2], dd[3], al0, al1, al2, al3, b0, b1);
            }
        }

        // ---- scale + causal mask ----
        const float scl = 0.125f;
        if (kt >= 2 * qt) {
            const int qg0 = q0 + gr, qg1 = qg0 + 8;
#pragma unroll
            for (int nt = 0; nt < 8; ++nt) {
                const int kg = k0 + nt * 8 + cc;
                sacc[nt][0] = (kg     > qg0) ? -1e30f : sacc[nt][0] * scl;
                sacc[nt][1] = (kg + 1 > qg0) ? -1e30f : sacc[nt][1] * scl;
                sacc[nt][2] = (kg     > qg1) ? -1e30f : sacc[nt][2] * scl;
                sacc[nt][3] = (kg + 1 > qg1) ? -1e30f : sacc[nt][3] * scl;
            }
        } else {
#pragma unroll
            for (int nt = 0; nt < 8; ++nt) {
                sacc[nt][0] *= scl; sacc[nt][1] *= scl;
                sacc[nt][2] *= scl; sacc[nt][3] *= scl;
            }
        }

        // ---- online softmax ----
        float mx0 = -1e30f, mx1 = -1e30f;
#pragma unroll
        for (int nt = 0; nt < 8; ++nt) {
            mx0 = fmaxf(mx0, fmaxf(sacc[nt][0], sacc[nt][1]));
            mx1 = fmaxf(mx1, fmaxf(sacc[nt][2], sacc[nt][3]));
        }
        mx0 = fmaxf(mx0, __shfl_xor_sync(0xffffffffu, mx0, 1));
        mx0 = fmaxf(mx0, __shfl_xor_sync(0xffffffffu, mx0, 2));
        mx1 = fmaxf(mx1, __shfl_xor_sync(0xffffffffu, mx1, 1));
        mx1 = fmaxf(mx1, __shfl_xor_sync(0xffffffffu, mx1, 2));
        const float mn0 = fmaxf(m0, mx0), mn1 = fmaxf(m1, mx1);
        const float a0 = __expf(m0 - mn0), a1 = __expf(m1 - mn1);
        m0 = mn0; m1 = mn1;

        float s0 = 0.f, s1 = 0.f;
        uint32_t pH[4][4], pL[4][4];
#pragma unroll
        for (int ks = 0; ks < 4; ++ks) {
            const int n0t = 2 * ks, n1t = 2 * ks + 1;
            float p00 = __expf(sacc[n0t][0] - mn0);
            float p01 = __expf(sacc[n0t][1] - mn0);
            float p10 = __expf(sacc[n0t][2] - mn1);
            float p11 = __expf(sacc[n0t][3] - mn1);
            float p20 = __expf(sacc[n1t][0] - mn0);
            float p21 = __expf(sacc[n1t][1] - mn0);
            float p30 = __expf(sacc[n1t][2] - mn1);
            float p31 = __expf(sacc[n1t][3] - mn1);
            s0 += p00 + p01 + p20 + p21;
            s1 += p10 + p11 + p30 + p31;
            split2h(p00, p01, pH[ks][0], pL[ks][0]);
            split2h(p10, p11, pH[ks][1], pL[ks][1]);
            split2h(p20, p21, pH[ks][2], pL[ks][2]);
            split2h(p30, p31, pH[ks][3], pL[ks][3]);
        }
        s0 += __shfl_xor_sync(0xffffffffu, s0, 1);
        s0 += __shfl_xor_sync(0xffffffffu, s0, 2);
        s1 += __shfl_xor_sync(0xffffffffu, s1, 1);
        s1 += __shfl_xor_sync(0xffffffffu, s1, 2);
        l0s = l0s * a0 + s0;
        l1s = l1s * a1 + s1;
#pragma unroll
        for (int nt = 0; nt < 8; ++nt) {
            oacc[nt][0] *= a0; oacc[nt][1] *= a0;
            oacc[nt][2] *= a1; oacc[nt][3] *= a1;
        }

        // ---- O += (Ph + Pl) V : 2 mma terms ----
#pragma unroll
        for (int ks = 0; ks < 4; ++ks) {
            const int kk = ks * 16 + cc;
#pragma unroll
            for (int nt = 0; nt < 8; ++nt) {
                const int n = nt * 8 + (lane >> 2);
                uint32_t b0 = *(const uint32_t*)&sV[n * AT_S + kk];
                uint32_t b1 = *(const uint32_t*)&sV[n * AT_S + kk + 8];
                float* dd = oacc[nt];
                mma_f16(dd[0], dd[1], dd[2], dd[3],
                        pH[ks][0], pH[ks][1], pH[ks][2], pH[ks][3], b0, b1);
                mma_f16(dd[0], dd[1], dd[2], dd[3],
                        pL[ks][0], pL[ks][1], pL[ks][2], pL[ks][3], b0, b1);
            }
        }
    }

    // ---- epilogue: normalize, fp16-pair split, store ----
    const float inv0 = 1.f / l0s, inv1 = 1.f / l1s;
    const size_t r0 = qkBase + (size_t)(q0 + gr) * D_MODEL + cc;
    const size_t r1 = r0 + 8 * D_MODEL;
#pragma unroll
    for (int nt = 0; nt < 8; ++nt) {
        uint32_t h0, lo0, h1, lo1;
        split2h(oacc[nt][0] * inv0, oacc[nt][1] * inv0, h0, lo0);
        split2h(oacc[nt][2] * inv1, oacc[nt][3] * inv1, h1, lo1);
        *(uint32_t*)&Oh[r0 + nt * 8] = h0;
        *(uint32_t*)&Ol[r0 + nt * 8] = lo0;
        *(uint32_t*)&Oh[r1 + nt * 8] = h1;
        *(uint32_t*)&Ol[r1 + nt * 8] = lo1;
    }
}

// ---------------------------------------------------------------------------
// Residual + LayerNorm (rows of 512); optional fp32 out + fp16-pair split out
// ---------------------------------------------------------------------------
template<bool F32OUT, bool SPLITOUT>
__global__ __launch_bounds__(128) void residual_ln_kernel(
    const float* __restrict__ a, const float* __restrict__ b,
    const float* __restrict__ gamma, const float* __restrict__ beta,
    float* __restrict__ out,
    __half* __restrict__ outh, __half* __restrict__ outl)
{
    const int row = blockIdx.x;
    const int tid = threadIdx.x;
    const size_t base = (size_t)row * D_VALUE;

    float4 va = ((const float4*)(a + base))[tid];
    float4 vb = ((const float4*)(b + base))[tid];
    float4 v = make_float4(va.x + vb.x, va.y + vb.y, va.z + vb.z, va.w + vb.w);

    float s  = v.x + v.y + v.z + v.w;
    float ss = v.x * v.x + v.y * v.y + v.z * v.z + v.w * v.w;
#pragma unroll
    for (int off = 16; off >= 1; off >>= 1) {
        s  += __shfl_xor_sync(0xffffffffu, s, off);
        ss += __shfl_xor_sync(0xffffffffu, ss, off);
    }
    __shared__ float red[8];
    const int wid = tid >> 5;
    if ((tid & 31) == 0) { red[wid] = s; red[4 + wid] = ss; }
    __syncthreads();
    s  = red[0] + red[1] + red[2] + red[3];
    ss = red[4] + red[5] + red[6] + red[7];

    const float mu = s * (1.f / (float)D_VALUE);
    float var = ss * (1.f / (float)D_VALUE) - mu * mu;
    const float rn = rsqrtf(var + 1e-5f);

    float4 g4 = ((const float4*)gamma)[tid];
    float4 b4 = ((const float4*)beta)[tid];
    float4 r;
    r.x = (v.x - mu) * rn * g4.x + b4.x;
    r.y = (v.y - mu) * rn * g4.y + b4.y;
    r.z = (v.z - mu) * rn * g4.z + b4.z;
    r.w = (v.w - mu) * rn * g4.w + b4.w;
    if (F32OUT) ((float4*)(out + base))[tid] = r;
    if (SPLITOUT) {
        uint32_t h0, l0, h1, l1;
        split2h(r.x, r.y, h0, l0);
        split2h(r.z, r.w, h1, l1);
        ((uint32_t*)(outh + base))[2 * tid]     = h0;
        ((uint32_t*)(outh + base))[2 * tid + 1] = h1;
        ((uint32_t*)(outl + base))[2 * tid]     = l0;
        ((uint32_t*)(outl + base))[2 * tid + 1] = l1;
    }
}

// ---------------------------------------------------------------------------
// Launch
// ---------------------------------------------------------------------------
static inline void run_split_f16(const float* x, __half* hi, __half* lo, int n)
{
    int n4 = n / 4;
    split_f16_kernel<<<(n4 + 255) / 256, 256>>>(x, hi, lo, n4);
}

static inline void run_conv_f16(const float* x, __half* o, int n)
{
    int n4 = n / 4;
    conv_f16_kernel<<<(n4 + 255) / 256, 256>>>(x, o, n4);
}

template<bool RELU, int OUT>
static inline void run_gemm(
    const __half* Ah, const __half* Al, const __half* B,
    const float* bias, float* C, __half* Ch, __half* Cl,
    int M, int N, int K)
{
    cudaFuncSetAttribute(gemm_f16_kernel<RELU, OUT>,
                         cudaFuncAttributeMaxDynamicSharedMemorySize, GSMEM);
    gemm_f16_kernel<RELU, OUT><<<dim3(N / 128, M / 128), 256, GSMEM>>>(
        Ah, Al, B, bias, C, Ch, Cl, M, N, K);
}

extern "C" void kernel_launch(void* const* d_in, const int* in_sizes, int n_in,
                              void* d_out, int out_size)
{
    const float* q   = (const float*)d_in[0];
    const float* k   = (const float*)d_in[1];
    const float* v   = (const float*)d_in[2];
    const float* Wq  = (const float*)d_in[3];
    const float* bq  = (const float*)d_in[4];
    const float* Wk  = (const float*)d_in[5];
    const float* bk  = (const float*)d_in[6];
    const float* Wv  = (const float*)d_in[7];
    const float* bv  = (const float*)d_in[8];
    const float* Wo  = (const float*)d_in[9];
    const float* bo  = (const float*)d_in[10];
    const float* Wc1 = (const float*)d_in[11];
    const float* bc1 = (const float*)d_in[12];
    const float* Wc2 = (const float*)d_in[13];
    const float* bc2 = (const float*)d_in[14];
    const float* g1  = (const float*)d_in[15];
    const float* b1  = (const float*)d_in[16];
    const float* g2  = (const float*)d_in[17];
    const float* b2  = (const float*)d_in[18];
    const float* Wl  = (const float*)d_in[19];
    const float* bl  = (const float*)d_in[20];
    float* out = (float*)d_out;

    float *Proj, *X, *Y;
    __half *Ah, *Al, *W, *Qh, *Ql, *Kf, *Vf, *Vt;
    __half *Ohp, *Olp, *Xh, *Xl, *Fh, *Fl, *X2h, *X2l;
    cudaGetSymbolAddress((void**)&Proj, g_proj);
    cudaGetSymbolAddress((void**)&X,    g_x);
    cudaGetSymbolAddress((void**)&Y,    g_y);
    cudaGetSymbolAddress((void**)&Ah,   g_Ah);
    cudaGetSymbolAddress((void**)&Al,   g_Al);
    cudaGetSymbolAddress((void**)&W,    g_W);
    cudaGetSymbolAddress((void**)&Qh,   g_Qh);
    cudaGetSymbolAddress((void**)&Ql,   g_Ql);
    cudaGetSymbolAddress((void**)&Kf,   g_K);
    cudaGetSymbolAddress((void**)&Vf,   g_V);
    cudaGetSymbolAddress((void**)&Vt,   g_Vt);
    cudaGetSymbolAddress((void**)&Ohp,  g_Oh);
    cudaGetSymbolAddress((void**)&Olp,  g_Ol);
    cudaGetSymbolAddress((void**)&Xh,   g_Xh);
    cudaGetSymbolAddress((void**)&Xl,   g_Xl);
    cudaGetSymbolAddress((void**)&Fh,   g_Fh);
    cudaGetSymbolAddress((void**)&Fl,   g_Fl);
    cudaGetSymbolAddress((void**)&X2h,  g_X2h);
    cudaGetSymbolAddress((void**)&X2l,  g_X2l);

    // ---- QKV projections ----
    run_split_f16(q, Ah, Al, M_ROWS * D_MODEL);
    run_conv_f16(Wq, W, D_MODEL * D_MODEL);
    run_gemm<false, 2>(Ah, Al, W, bq, nullptr, Qh, Ql, M_ROWS, D_MODEL, D_MODEL);

    run_split_f16(k, Ah, Al, M_ROWS * D_MODEL);
    run_conv_f16(Wk, W, D_MODEL * D_MODEL);
    run_gemm<false, 3>(Ah, Al, W, bk, nullptr, Kf, nullptr, M_ROWS, D_MODEL, D_MODEL);

    run_split_f16(v, Ah, Al, M_ROWS * D_MODEL);
    run_conv_f16(Wv, W, D_MODEL * D_MODEL);
    run_gemm<false, 3>(Ah, Al, W, bv, nullptr, Vf, nullptr, M_ROWS, D_MODEL, D_MODEL);

    // ---- V transpose per head ----
    vtrans_kernel<<<dim3(SEQ_L / 64, N_HEADS, B_BATCH), 256>>>(Vf, Vt);

    // ---- attention (fp16 2-term HMMA) -> fp16-pair O ----
    cudaFuncSetAttribute(attn_mma_kernel,
                         cudaFuncAttributeMaxDynamicSharedMemorySize, AT_SMEM);
    attn_mma_kernel<<<dim3(SEQ_L / 128, N_HEADS, B_BATCH), 256, AT_SMEM>>>(
        Qh, Ql, Kf, Vt, Ohp, Olp);

    // ---- output projection (fp32 out) ----
    run_conv_f16(Wo, W, D_MODEL * D_VALUE);
    run_gemm<false, 0>(Ohp, Olp, W, bo, Proj, nullptr, nullptr,
                       M_ROWS, D_MODEL, D_MODEL);

    // ---- residual + LN1 (fp32 X + fp16-pair split) ----
    residual_ln_kernel<true, true><<<M_ROWS, 128>>>(v, Proj, g1, b1, X, Xh, Xl);

    // ---- FFN ----
    run_conv_f16(Wc1, W, D_FF * D_VALUE);
    run_gemm<true, 2>(Xh, Xl, W, bc1, nullptr, Fh, Fl, M_ROWS, D_FF, D_VALUE);

    run_conv_f16(Wc2, W, D_VALUE * D_FF);
    run_gemm<false, 0>(Fh, Fl, W, bc2, Y, nullptr, nullptr,
                       M_ROWS, D_VALUE, D_FF);

    // ---- residual + LN2 (fp16-pair split only) ----
    residual_ln_kernel<false, true><<<M_ROWS, 128>>>(X, Y, g2, b2, nullptr, X2h, X2l);

    // ---- final projection ----
    run_conv_f16(Wl, W, D_MODEL * D_VALUE);
    run_gemm<false, 0>(X2h, X2l, W, bl, out, nullptr, nullptr,
                       M_ROWS, D_MODEL, D_VALUE);
}

// round 14
// speedup vs baseline: 3.2455x; 1.0040x over previous
#include <cuda_runtime.h>
#include <cuda_fp16.h>
#include <cstdint>

// ---------------------------------------------------------------------------
// Problem constants
// ---------------------------------------------------------------------------
#define B_BATCH 4
#define SEQ_L   2048
#define D_MODEL 512
#define D_VALUE 512
#define N_HEADS 8
#define HEAD_E  64
#define D_FF    2048
#define M_ROWS  (B_BATCH * SEQ_L)   // 8192

// ---------------------------------------------------------------------------
// Scratch (static device allocations)
// ---------------------------------------------------------------------------
__device__ float g_proj[M_ROWS * D_MODEL];
__device__ float g_x   [M_ROWS * D_VALUE];
__device__ float g_y   [M_ROWS * D_VALUE];

// input splits (separate buffers so all splits can run up front)
__device__ __half g_Aqh[M_ROWS * D_MODEL];
__device__ __half g_Aql[M_ROWS * D_MODEL];
__device__ __half g_Akh[M_ROWS * D_MODEL];
__device__ __half g_Akl[M_ROWS * D_MODEL];
__device__ __half g_Avh[M_ROWS * D_MODEL];
__device__ __half g_Avl[M_ROWS * D_MODEL];
// weights fp16 (separate buffers, converted up front)
__device__ __half g_Wq16[D_MODEL * D_MODEL];
__device__ __half g_Wk16[D_MODEL * D_MODEL];
__device__ __half g_Wv16[D_MODEL * D_MODEL];
__device__ __half g_Wo16[D_MODEL * D_VALUE];
__device__ __half g_Wc116[D_FF * D_VALUE];
__device__ __half g_Wc216[D_VALUE * D_FF];
__device__ __half g_Wl16[D_MODEL * D_VALUE];
// intermediates
__device__ __half g_Qh [M_ROWS * D_MODEL];
__device__ __half g_Ql [M_ROWS * D_MODEL];
__device__ __half g_K  [M_ROWS * D_MODEL];
__device__ __half g_V  [M_ROWS * D_MODEL];
__device__ __half g_Vt [M_ROWS * D_MODEL];   // [B][H][E][L]
__device__ __half g_Oh [M_ROWS * D_MODEL];
__device__ __half g_Ol [M_ROWS * D_MODEL];
__device__ __half g_Xh [M_ROWS * D_VALUE];
__device__ __half g_Xl [M_ROWS * D_VALUE];
__device__ __half g_Fh [M_ROWS * D_FF];
__device__ __half g_Fl [M_ROWS * D_FF];
__device__ __half g_X2h[M_ROWS * D_VALUE];
__device__ __half g_X2l[M_ROWS * D_VALUE];

// ---------------------------------------------------------------------------
// helpers
// ---------------------------------------------------------------------------
__device__ __forceinline__ void split2h(float x, float y, uint32_t& hi, uint32_t& lo)
{
    __half hx = __float2half_rn(x);
    __half hy = __float2half_rn(y);
    __half2 h2 = __halves2half2(hx, hy);
    __half2 l2 = __halves2half2(
        __float2half_rn(x - __half2float(hx)),
        __float2half_rn(y - __half2float(hy)));
    hi = *reinterpret_cast<uint32_t*>(&h2);
    lo = *reinterpret_cast<uint32_t*>(&l2);
}

__device__ __forceinline__ void mma_f16(
    float& d0, float& d1, float& d2, float& d3,
    uint32_t a0, uint32_t a1, uint32_t a2, uint32_t a3,
    uint32_t b0, uint32_t b1)
{
    asm volatile(
        "mma.sync.aligned.m16n8k16.row.col.f32.f16.f16.f32 "
        "{%0,%1,%2,%3}, {%4,%5,%6,%7}, {%8,%9}, {%0,%1,%2,%3};"
        : "+f"(d0), "+f"(d1), "+f"(d2), "+f"(d3)
        : "r"(a0), "r"(a1), "r"(a2), "r"(a3), "r"(b0), "r"(b1));
}

__device__ __forceinline__ uint32_t smem_u32(const void* p)
{
    uint32_t a;
    asm("{ .reg .u64 t; cvta.to.shared.u64 t, %1; cvt.u32.u64 %0, t; }"
        : "=r"(a) : "l"(p));
    return a;
}

__device__ __forceinline__ void ldsm_x4(
    uint32_t& r0, uint32_t& r1, uint32_t& r2, uint32_t& r3, uint32_t addr)
{
    asm volatile(
        "ldmatrix.sync.aligned.m8n8.x4.shared.b16 {%0,%1,%2,%3}, [%4];"
        : "=r"(r0), "=r"(r1), "=r"(r2), "=r"(r3) : "r"(addr));
}

#define CP_ASYNC16(dst, src) \
    asm volatile("cp.async.cg.shared.global [%0], [%1], 16;" \
                 :: "r"(dst), "l"(src) : "memory")
#define CP_COMMIT() asm volatile("cp.async.commit_group;" ::: "memory")
#define CP_WAIT1()  asm volatile("cp.async.wait_group 1;" ::: "memory")
#define CP_WAIT0()  asm volatile("cp.async.wait_group 0;" ::: "memory")

// ---------------------------------------------------------------------------
// Split fp32 -> fp16 hi + fp16 lo (activations)
// ---------------------------------------------------------------------------
__global__ __launch_bounds__(256) void split_f16_kernel(
    const float* __restrict__ x,
    __half* __restrict__ hi, __half* __restrict__ lo, int n4)
{
    int i = blockIdx.x * 256 + threadIdx.x;
    if (i >= n4) return;
    float4 v = ((const float4*)x)[i];
    uint32_t h0, l0, h1, l1;
    split2h(v.x, v.y, h0, l0);
    split2h(v.z, v.w, h1, l1);
    ((uint32_t*)hi)[2 * i]     = h0;
    ((uint32_t*)hi)[2 * i + 1] = h1;
    ((uint32_t*)lo)[2 * i]     = l0;
    ((uint32_t*)lo)[2 * i + 1] = l1;
}

// fp32 -> fp16 single (weights)
__global__ __launch_bounds__(256) void conv_f16_kernel(
    const float* __restrict__ x, __half* __restrict__ o, int n4)
{
    int i = blockIdx.x * 256 + threadIdx.x;
    if (i >= n4) return;
    float4 v = ((const float4*)x)[i];
    __half2 a = __halves2half2(__float2half_rn(v.x), __float2half_rn(v.y));
    __half2 b = __halves2half2(__float2half_rn(v.z), __float2half_rn(v.w));
    ((__half2*)o)[2 * i]     = a;
    ((__half2*)o)[2 * i + 1] = b;
}

// ---------------------------------------------------------------------------
// fp16 HMMA GEMM: C = (Ah+Al) @ W^T + bias.  A fp16 pair, B fp16 single.
// CTA 128x128, BK=32, 3-stage cp.async, ldmatrix, 2 mma terms,
// ONE __syncthreads per k-chunk.
// OUT: 0 = fp32 C, 2 = fp16 pair, 3 = fp16 single
// ---------------------------------------------------------------------------
#define GS 40
#define GA_BYTES (128 * GS * 2)          // 10240 per array
#define GSTAGE_BYTES (3 * GA_BYTES)      // 30720 per stage (Ah,Al,B)
#define GSTAGES 3
#define GSMEM (GSTAGES * GSTAGE_BYTES)   // 92160 total

template<bool RELU, int OUT>
__global__ __launch_bounds__(256) void gemm_f16_kernel(
    const __half* __restrict__ Ah, const __half* __restrict__ Al,
    const __half* __restrict__ B,
    const float* __restrict__ bias, float* __restrict__ C,
    __half* __restrict__ Ch, __half* __restrict__ Cl,
    int M, int N, int K)
{
    extern __shared__ char smem[];
    const uint32_t su = smem_u32(smem);

    const int tid  = threadIdx.x;
    const int lane = tid & 31;
    const int warp = tid >> 5;
    const int wm = (warp & 1) * 64;
    const int wn = (warp >> 1) * 32;
    const int m0 = blockIdx.y * 128;
    const int n0 = blockIdx.x * 128;

    const int crow = tid >> 1;
    const uint32_t cc32 = (uint32_t)(tid & 1) * 32;
    const int ce = (tid & 1) * 16;

    const __half* gAh = Ah + (size_t)(m0 + crow) * K + ce;
    const __half* gAl = Al + (size_t)(m0 + crow) * K + ce;
    const __half* gB  = B  + (size_t)(n0 + crow) * K + ce;
    const uint32_t so = (uint32_t)crow * (GS * 2) + cc32;

    auto load_stage = [&](int i) {
        const uint32_t sb = su + (uint32_t)(i % GSTAGES) * GSTAGE_BYTES;
        const size_t kof = (size_t)i * 32;
        CP_ASYNC16(sb + 0 * GA_BYTES + so,      gAh + kof);
        CP_ASYNC16(sb + 0 * GA_BYTES + so + 16, gAh + kof + 8);
        CP_ASYNC16(sb + 1 * GA_BYTES + so,      gAl + kof);
        CP_ASYNC16(sb + 1 * GA_BYTES + so + 16, gAl + kof + 8);
        CP_ASYNC16(sb + 2 * GA_BYTES + so,      gB + kof);
        CP_ASYNC16(sb + 2 * GA_BYTES + so + 16, gB + kof + 8);
        CP_COMMIT();
    };

    const int l8 = lane & 7, lq = lane >> 3;
    const uint32_t aOff = (uint32_t)(((wm + l8 + (lq & 1) * 8) * GS + (lq >> 1) * 8) * 2);
    const uint32_t bOff = (uint32_t)(((wn + l8 + (lq >> 1) * 8) * GS + (lq & 1) * 8) * 2);

    float acc[4][4][4];
#pragma unroll
    for (int mi = 0; mi < 4; ++mi)
#pragma unroll
        for (int ni = 0; ni < 4; ++ni)
#pragma unroll
            for (int r = 0; r < 4; ++r) acc[mi][ni][r] = 0.f;

    load_stage(0);
    load_stage(1);
    const int nch = K >> 5;

    for (int i = 0; i < nch; ++i) {
        if (i + 1 < nch) { CP_WAIT1(); } else { CP_WAIT0(); }
        __syncthreads();
        // stage (i+2)%3 == (i-1)%3: consumed at iter i-1, protected by the
        // sync above -> safe to overwrite; issue loads early, overlap mma.
        if (i + 2 < nch) load_stage(i + 2);
        const uint32_t sb = su + (uint32_t)(i % GSTAGES) * GSTAGE_BYTES;
#pragma unroll
        for (int ks = 0; ks < 2; ++ks) {
            const uint32_t ko = (uint32_t)ks * 32;
            uint32_t aH[4][4], aL[4][4], bH[4][2];
#pragma unroll
            for (int mi = 0; mi < 4; ++mi) {
                const uint32_t ad = sb + 0 * GA_BYTES + aOff
                                  + (uint32_t)mi * (16 * GS * 2) + ko;
                ldsm_x4(aH[mi][0], aH[mi][1], aH[mi][2], aH[mi][3], ad);
                ldsm_x4(aL[mi][0], aL[mi][1], aL[mi][2], aL[mi][3], ad + GA_BYTES);
            }
#pragma unroll
            for (int np = 0; np < 2; ++np) {
                const uint32_t bd = sb + 2 * GA_BYTES + bOff
                                  + (uint32_t)np * (16 * GS * 2) + ko;
                ldsm_x4(bH[2 * np][0], bH[2 * np][1],
                        bH[2 * np + 1][0], bH[2 * np + 1][1], bd);
            }
#pragma unroll
            for (int mi = 0; mi < 4; ++mi)
#pragma unroll
                for (int ni = 0; ni < 4; ++ni) {
                    float* d = acc[mi][ni];
                    mma_f16(d[0], d[1], d[2], d[3],
                            aH[mi][0], aH[mi][1], aH[mi][2], aH[mi][3],
                            bH[ni][0], bH[ni][1]);
                    mma_f16(d[0], d[1], d[2], d[3],
                            aL[mi][0], aL[mi][1], aL[mi][2], aL[mi][3],
                            bH[ni][0], bH[ni][1]);
                }
        }
    }

#pragma unroll
    for (int mi = 0; mi < 4; ++mi) {
        const int m = m0 + wm + mi * 16 + (lane >> 2);
#pragma unroll
        for (int ni = 0; ni < 4; ++ni) {
            const int nc = n0 + wn + ni * 8 + 2 * (lane & 3);
            float b0 = bias[nc], b1 = bias[nc + 1];
            float c0 = acc[mi][ni][0] + b0, c1 = acc[mi][ni][1] + b1;
            float c2 = acc[mi][ni][2] + b0, c3 = acc[mi][ni][3] + b1;
            if (RELU) {
                c0 = fmaxf(c0, 0.f); c1 = fmaxf(c1, 0.f);
                c2 = fmaxf(c2, 0.f); c3 = fmaxf(c3, 0.f);
            }
            if (OUT == 0) {
                *(float2*)&C[(size_t)m * N + nc]       = make_float2(c0, c1);
                *(float2*)&C[(size_t)(m + 8) * N + nc] = make_float2(c2, c3);
            } else if (OUT == 2) {
                uint32_t h0, l0, h1, l1;
                split2h(c0, c1, h0, l0);
                split2h(c2, c3, h1, l1);
                *(uint32_t*)&Ch[(size_t)m * N + nc]       = h0;
                *(uint32_t*)&Cl[(size_t)m * N + nc]       = l0;
                *(uint32_t*)&Ch[(size_t)(m + 8) * N + nc] = h1;
                *(uint32_t*)&Cl[(size_t)(m + 8) * N + nc] = l1;
            } else {
                __half2 h0 = __halves2half2(__float2half_rn(c0), __float2half_rn(c1));
                __half2 h1 = __halves2half2(__float2half_rn(c2), __float2half_rn(c3));
                *(__half2*)&Ch[(size_t)m * N + nc]       = h0;
                *(__half2*)&Ch[(size_t)(m + 8) * N + nc] = h1;
            }
        }
    }
}

// ---------------------------------------------------------------------------
// V transpose (fp16 single): V [token][512] -> Vt [B][H][E=64][L=2048]
// ---------------------------------------------------------------------------
__global__ __launch_bounds__(256) void vtrans_kernel(
    const __half* __restrict__ V, __half* __restrict__ Vt)
{
    __shared__ __half tile[64][72];
    const int lt = blockIdx.x, h = blockIdx.y, b = blockIdx.z;
    const int t = threadIdx.x;
    {
        int l = t >> 2, e0 = (t & 3) * 16;
        size_t g = ((size_t)(b * SEQ_L + lt * 64 + l)) * D_MODEL + h * 64 + e0;
        int4 a0 = *(const int4*)(V + g);
        int4 a1 = *(const int4*)(V + g + 8);
        *(int4*)&tile[l][e0]     = a0;
        *(int4*)&tile[l][e0 + 8] = a1;
    }
    __syncthreads();
    {
        int e = t >> 2, l0 = (t & 3) * 16;
        __align__(16) __half buf[16];
#pragma unroll
        for (int i = 0; i < 16; ++i) buf[i] = tile[l0 + i][e];
        size_t g = ((size_t)((b * N_HEADS + h) * 64 + e)) * SEQ_L + lt * 64 + l0;
        ((int4*)(Vt + g))[0] = ((int4*)buf)[0];
        ((int4*)(Vt + g))[1] = ((int4*)buf)[1];
    }
}

// ---------------------------------------------------------------------------
// fp16 tensor-core causal flash attention:
// Q = fp16 pair (2-term), K/V = fp16 single, P = fp16 pair (2-term).
// 128q x 64k tile, 8 warps. Output = fp16 pair.
// ---------------------------------------------------------------------------
#define AT_S 72
#define AT_SMEM ((2 * 128 + 2 * 64) * AT_S * 2)   // 55296 B

__global__ __launch_bounds__(256, 1) void attn_mma_kernel(
    const __half* __restrict__ Qh, const __half* __restrict__ Ql,
    const __half* __restrict__ K,  const __half* __restrict__ Vt,
    __half* __restrict__ Oh, __half* __restrict__ Ol)
{
    extern __shared__ __half smh[];
    __half* sQh = smh;
    __half* sQl = sQh + 128 * AT_S;
    __half* sK  = sQl + 128 * AT_S;
    __half* sV  = sK  + 64 * AT_S;

    const int tid = threadIdx.x, lane = tid & 31, warp = tid >> 5;
    const int qt = blockIdx.x, h = blockIdx.y, b = blockIdx.z;
    const int q0 = qt * 128;
    const size_t qkBase = ((size_t)b * SEQ_L) * D_MODEL + (size_t)h * HEAD_E;
    const size_t vtBase = ((size_t)(b * N_HEADS + h)) * HEAD_E * SEQ_L;

    {
        int row = tid >> 1, e0 = (tid & 1) * 32;
        size_t g = qkBase + (size_t)(q0 + row) * D_MODEL + e0;
        int4 a0 = *(const int4*)(Qh + g);
        int4 a1 = *(const int4*)(Qh + g + 8);
        int4 a2 = *(const int4*)(Qh + g + 16);
        int4 a3 = *(const int4*)(Qh + g + 24);
        int4* d = (int4*)(sQh + row * AT_S + e0);
        d[0] = a0; d[1] = a1; d[2] = a2; d[3] = a3;
        int4 c0 = *(const int4*)(Ql + g);
        int4 c1 = *(const int4*)(Ql + g + 8);
        int4 c2 = *(const int4*)(Ql + g + 16);
        int4 c3 = *(const int4*)(Ql + g + 24);
        int4* d2 = (int4*)(sQl + row * AT_S + e0);
        d2[0] = c0; d2[1] = c1; d2[2] = c2; d2[3] = c3;
    }

    float m0 = -1e30f, m1 = -1e30f, l0s = 0.f, l1s = 0.f;
    float oacc[8][4];
#pragma unroll
    for (int nt = 0; nt < 8; ++nt)
#pragma unroll
        for (int r = 0; r < 4; ++r) oacc[nt][r] = 0.f;

    const int ldr = tid >> 2;
    const int ldc = (tid & 3) * 16;
    const int nkt = 2 * qt + 2;

    int4 pK0, pK1, pV0, pV1;
    {
        size_t gk = qkBase + (size_t)ldr * D_MODEL + ldc;
        pK0 = *(const int4*)(K + gk); pK1 = *(const int4*)(K + gk + 8);
        size_t gv = vtBase + (size_t)ldr * SEQ_L + ldc;
        pV0 = *(const int4*)(Vt + gv); pV1 = *(const int4*)(Vt + gv + 8);
    }

    const int gr = warp * 16 + (lane >> 2);
    const int cc = 2 * (lane & 3);

    for (int kt = 0; kt < nkt; ++kt) {
        const int k0 = kt * 64;
        __syncthreads();
        {
            int4* d;
            d = (int4*)(sK + ldr * AT_S + ldc); d[0] = pK0; d[1] = pK1;
            d = (int4*)(sV + ldr * AT_S + ldc); d[0] = pV0; d[1] = pV1;
        }
        __syncthreads();
        if (kt + 1 < nkt) {
            size_t gk = qkBase + (size_t)(k0 + 64 + ldr) * D_MODEL + ldc;
            pK0 = *(const int4*)(K + gk); pK1 = *(const int4*)(K + gk + 8);
            size_t gv = vtBase + (size_t)ldr * SEQ_L + k0 + 64 + ldc;
            pV0 = *(const int4*)(Vt + gv); pV1 = *(const int4*)(Vt + gv + 8);
        }

        float sacc[8][4];
#pragma unroll
        for (int nt = 0; nt < 8; ++nt)
#pragma unroll
            for (int r = 0; r < 4; ++r) sacc[nt][r] = 0.f;

#pragma unroll
        for (int es = 0; es < 4; ++es) {
            const int e = es * 16 + cc;
            uint32_t ah0 = *(const uint32_t*)&sQh[gr * AT_S + e];
            uint32_t ah1 = *(const uint32_t*)&sQh[(gr + 8) * AT_S + e];
            uint32_t ah2 = *(const uint32_t*)&sQh[gr * AT_S + e + 8];
            uint32_t ah3 = *(const uint32_t*)&sQh[(gr + 8) * AT_S + e + 8];
            uint32_t al0 = *(const uint32_t*)&sQl[gr * AT_S + e];
            uint32_t al1 = *(const uint32_t*)&sQl[(gr + 8) * AT_S + e];
            uint32_t al2 = *(const uint32_t*)&sQl[gr * AT_S + e + 8];
            uint32_t al3 = *(const uint32_t*)&sQl[(gr + 8) * AT_S + e + 8];
#pragma unroll
            for (int nt = 0; nt < 8; ++nt) {
                const int n = nt * 8 + (lane >> 2);
                uint32_t b0 = *(const uint32_t*)&sK[n * AT_S + e];
                uint32_t b1 = *(const uint32_t*)&sK[n * AT_S + e + 8];
                float* dd = sacc[nt];
                mma_f16(dd[0], dd[1], dd[2], dd[3], ah0, ah1, ah2, ah3, b0, b1);
                mma_f16(dd[0], dd[1], dd[2], dd[3], al0, al1, al2, al3, b0, b1);
            }
        }

        const float scl = 0.125f;
        if (kt >= 2 * qt) {
            const int qg0 = q0 + gr, qg1 = qg0 + 8;
#pragma unroll
            for (int nt = 0; nt < 8; ++nt) {
                const int kg = k0 + nt * 8 + cc;
                sacc[nt][0] = (kg     > qg0) ? -1e30f : sacc[nt][0] * scl;
                sacc[nt][1] = (kg + 1 > qg0) ? -1e30f : sacc[nt][1] * scl;
                sacc[nt][2] = (kg     > qg1) ? -1e30f : sacc[nt][2] * scl;
                sacc[nt][3] = (kg + 1 > qg1) ? -1e30f : sacc[nt][3] * scl;
            }
        } else {
#pragma unroll
            for (int nt = 0; nt < 8; ++nt) {
                sacc[nt][0] *= scl; sacc[nt][1] *= scl;
                sacc[nt][2] *= scl; sacc[nt][3] *= scl;
            }
        }

        float mx0 = -1e30f, mx1 = -1e30f;
#pragma unroll
        for (int nt = 0; nt < 8; ++nt) {
            mx0 = fmaxf(mx0, fmaxf(sacc[nt][0], sacc[nt][1]));
            mx1 = fmaxf(mx1, fmaxf(sacc[nt][2], sacc[nt][3]));
        }
        mx0 = fmaxf(mx0, __shfl_xor_sync(0xffffffffu, mx0, 1));
        mx0 = fmaxf(mx0, __shfl_xor_sync(0xffffffffu, mx0, 2));
        mx1 = fmaxf(mx1, __shfl_xor_sync(0xffffffffu, mx1, 1));
        mx1 = fmaxf(mx1, __shfl_xor_sync(0xffffffffu, mx1, 2));
        const float mn0 = fmaxf(m0, mx0), mn1 = fmaxf(m1, mx1);
        const float a0 = __expf(m0 - mn0), a1 = __expf(m1 - mn1);
        m0 = mn0; m1 = mn1;

        float s0 = 0.f, s1 = 0.f;
        uint32_t pH[4][4], pL[4][4];
#pragma unroll
        for (int ks = 0; ks < 4; ++ks) {
            const int n0t = 2 * ks, n1t = 2 * ks + 1;
            float p00 = __expf(sacc[n0t][0] - mn0);
            float p01 = __expf(sacc[n0t][1] - mn0);
            float p10 = __expf(sacc[n0t][2] - mn1);
            float p11 = __expf(sacc[n0t][3] - mn1);
            float p20 = __expf(sacc[n1t][0] - mn0);
            float p21 = __expf(sacc[n1t][1] - mn0);
            float p30 = __expf(sacc[n1t][2] - mn1);
            float p31 = __expf(sacc[n1t][3] - mn1);
            s0 += p00 + p01 + p20 + p21;
            s1 += p10 + p11 + p30 + p31;
            split2h(p00, p01, pH[ks][0], pL[ks][0]);
            split2h(p10, p11, pH[ks][1], pL[ks][1]);
            split2h(p20, p21, pH[ks][2], pL[ks][2]);
            split2h(p30, p31, pH[ks][3], pL[ks][3]);
        }
        s0 += __shfl_xor_sync(0xffffffffu, s0, 1);
        s0 += __shfl_xor_sync(0xffffffffu, s0, 2);
        s1 += __shfl_xor_sync(0xffffffffu, s1, 1);
        s1 += __shfl_xor_sync(0xffffffffu, s1, 2);
        l0s = l0s * a0 + s0;
        l1s = l1s * a1 + s1;
#pragma unroll
        for (int nt = 0; nt < 8; ++nt) {
            oacc[nt][0] *= a0; oacc[nt][1] *= a0;
            oacc[nt][2] *= a1; oacc[nt][3] *= a1;
        }

#pragma unroll
        for (int ks = 0; ks < 4; ++ks) {
            const int kk = ks * 16 + cc;
#pragma unroll
            for (int nt = 0; nt < 8; ++nt) {
                const int n = nt * 8 + (lane >> 2);
                uint32_t b0 = *(const uint32_t*)&sV[n * AT_S + kk];
                uint32_t b1 = *(const uint32_t*)&sV[n * AT_S + kk + 8];
                float* dd = oacc[nt];
                mma_f16(dd[0], dd[1], dd[2], dd[3],
                        pH[ks][0], pH[ks][1], pH[ks][2], pH[ks][3], b0, b1);
                mma_f16(dd[0], dd[1], dd[2], dd[3],
                        pL[ks][0], pL[ks][1], pL[ks][2], pL[ks][3], b0, b1);
            }
        }
    }

    const float inv0 = 1.f / l0s, inv1 = 1.f / l1s;
    const size_t r0 = qkBase + (size_t)(q0 + gr) * D_MODEL + cc;
    const size_t r1 = r0 + 8 * D_MODEL;
#pragma unroll
    for (int nt = 0; nt < 8; ++nt) {
        uint32_t h0, lo0, h1, lo1;
        split2h(oacc[nt][0] * inv0, oacc[nt][1] * inv0, h0, lo0);
        split2h(oacc[nt][2] * inv1, oacc[nt][3] * inv1, h1, lo1);
        *(uint32_t*)&Oh[r0 + nt * 8] = h0;
        *(uint32_t*)&Ol[r0 + nt * 8] = lo0;
        *(uint32_t*)&Oh[r1 + nt * 8] = h1;
        *(uint32_t*)&Ol[r1 + nt * 8] = lo1;
    }
}

// ---------------------------------------------------------------------------
// Residual + LayerNorm (rows of 512); optional fp32 out + fp16-pair split out
// ---------------------------------------------------------------------------
template<bool F32OUT, bool SPLITOUT>
__global__ __launch_bounds__(128) void residual_ln_kernel(
    const float* __restrict__ a, const float* __restrict__ b,
    const float* __restrict__ gamma, const float* __restrict__ beta,
    float* __restrict__ out,
    __half* __restrict__ outh, __half* __restrict__ outl)
{
    const int row = blockIdx.x;
    const int tid = threadIdx.x;
    const size_t base = (size_t)row * D_VALUE;

    float4 va = ((const float4*)(a + base))[tid];
    float4 vb = ((const float4*)(b + base))[tid];
    float4 v = make_float4(va.x + vb.x, va.y + vb.y, va.z + vb.z, va.w + vb.w);

    float s  = v.x + v.y + v.z + v.w;
    float ss = v.x * v.x + v.y * v.y + v.z * v.z + v.w * v.w;
#pragma unroll
    for (int off = 16; off >= 1; off >>= 1) {
        s  += __shfl_xor_sync(0xffffffffu, s, off);
        ss += __shfl_xor_sync(0xffffffffu, ss, off);
    }
    __shared__ float red[8];
    const int wid = tid >> 5;
    if ((tid & 31) == 0) { red[wid] = s; red[4 + wid] = ss; }
    __syncthreads();
    s  = red[0] + red[1] + red[2] + red[3];
    ss = red[4] + red[5] + red[6] + red[7];

    const float mu = s * (1.f / (float)D_VALUE);
    float var = ss * (1.f / (float)D_VALUE) - mu * mu;
    const float rn = rsqrtf(var + 1e-5f);

    float4 g4 = ((const float4*)gamma)[tid];
    float4 b4 = ((const float4*)beta)[tid];
    float4 r;
    r.x = (v.x - mu) * rn * g4.x + b4.x;
    r.y = (v.y - mu) * rn * g4.y + b4.y;
    r.z = (v.z - mu) * rn * g4.z + b4.z;
    r.w = (v.w - mu) * rn * g4.w + b4.w;
    if (F32OUT) ((float4*)(out + base))[tid] = r;
    if (SPLITOUT) {
        uint32_t h0, l0, h1, l1;
        split2h(r.x, r.y, h0, l0);
        split2h(r.z, r.w, h1, l1);
        ((uint32_t*)(outh + base))[2 * tid]     = h0;
        ((uint32_t*)(outh + base))[2 * tid + 1] = h1;
        ((uint32_t*)(outl + base))[2 * tid]     = l0;
        ((uint32_t*)(outl + base))[2 * tid + 1] = l1;
    }
}

// ---------------------------------------------------------------------------
// Launch
// ---------------------------------------------------------------------------
static inline void run_split_f16(const float* x, __half* hi, __half* lo, int n)
{
    int n4 = n / 4;
    split_f16_kernel<<<(n4 + 255) / 256, 256>>>(x, hi, lo, n4);
}

static inline void run_conv_f16(const float* x, __half* o, int n)
{
    int n4 = n / 4;
    conv_f16_kernel<<<(n4 + 255) / 256, 256>>>(x, o, n4);
}

template<bool RELU, int OUT>
static inline void run_gemm(
    const __half* Ah, const __half* Al, const __half* B,
    const float* bias, float* C, __half* Ch, __half* Cl,
    int M, int N, int K)
{
    cudaFuncSetAttribute(gemm_f16_kernel<RELU, OUT>,
                         cudaFuncAttributeMaxDynamicSharedMemorySize, GSMEM);
    gemm_f16_kernel<RELU, OUT><<<dim3(N / 128, M / 128), 256, GSMEM>>>(
        Ah, Al, B, bias, C, Ch, Cl, M, N, K);
}

extern "C" void kernel_launch(void* const* d_in, const int* in_sizes, int n_in,
                              void* d_out, int out_size)
{
    const float* q   = (const float*)d_in[0];
    const float* k   = (const float*)d_in[1];
    const float* v   = (const float*)d_in[2];
    const float* Wq  = (const float*)d_in[3];
    const float* bq  = (const float*)d_in[4];
    const float* Wk  = (const float*)d_in[5];
    const float* bk  = (const float*)d_in[6];
    const float* Wv  = (const float*)d_in[7];
    const float* bv  = (const float*)d_in[8];
    const float* Wo  = (const float*)d_in[9];
    const float* bo  = (const float*)d_in[10];
    const float* Wc1 = (const float*)d_in[11];
    const float* bc1 = (const float*)d_in[12];
    const float* Wc2 = (const float*)d_in[13];
    const float* bc2 = (const float*)d_in[14];
    const float* g1  = (const float*)d_in[15];
    const float* b1  = (const float*)d_in[16];
    const float* g2  = (const float*)d_in[17];
    const float* b2  = (const float*)d_in[18];
    const float* Wl  = (const float*)d_in[19];
    const float* bl  = (const float*)d_in[20];
    float* out = (float*)d_out;

    float *Proj, *X, *Y;
    __half *Aqh, *Aql, *Akh, *Akl, *Avh, *Avl;
    __half *Wq16, *Wk16, *Wv16, *Wo16, *Wc116, *Wc216, *Wl16;
    __half *Qh, *Ql, *Kf, *Vf, *Vt, *Ohp, *Olp, *Xh, *Xl, *Fh, *Fl, *X2h, *X2l;
    cudaGetSymbolAddress((void**)&Proj,  g_proj);
    cudaGetSymbolAddress((void**)&X,     g_x);
    cudaGetSymbolAddress((void**)&Y,     g_y);
    cudaGetSymbolAddress((void**)&Aqh,   g_Aqh);
    cudaGetSymbolAddress((void**)&Aql,   g_Aql);
    cudaGetSymbolAddress((void**)&Akh,   g_Akh);
    cudaGetSymbolAddress((void**)&Akl,   g_Akl);
    cudaGetSymbolAddress((void**)&Avh,   g_Avh);
    cudaGetSymbolAddress((void**)&Avl,   g_Avl);
    cudaGetSymbolAddress((void**)&Wq16,  g_Wq16);
    cudaGetSymbolAddress((void**)&Wk16,  g_Wk16);
    cudaGetSymbolAddress((void**)&Wv16,  g_Wv16);
    cudaGetSymbolAddress((void**)&Wo16,  g_Wo16);
    cudaGetSymbolAddress((void**)&Wc116, g_Wc116);
    cudaGetSymbolAddress((void**)&Wc216, g_Wc216);
    cudaGetSymbolAddress((void**)&Wl16,  g_Wl16);
    cudaGetSymbolAddress((void**)&Qh,    g_Qh);
    cudaGetSymbolAddress((void**)&Ql,    g_Ql);
    cudaGetSymbolAddress((void**)&Kf,    g_K);
    cudaGetSymbolAddress((void**)&Vf,    g_V);
    cudaGetSymbolAddress((void**)&Vt,    g_Vt);
    cudaGetSymbolAddress((void**)&Ohp,   g_Oh);
    cudaGetSymbolAddress((void**)&Olp,   g_Ol);
    cudaGetSymbolAddress((void**)&Xh,    g_Xh);
    cudaGetSymbolAddress((void**)&Xl,    g_Xl);
    cudaGetSymbolAddress((void**)&Fh,    g_Fh);
    cudaGetSymbolAddress((void**)&Fl,    g_Fl);
    cudaGetSymbolAddress((void**)&X2h,   g_X2h);
    cudaGetSymbolAddress((void**)&X2l,   g_X2l);

    // ---- all input splits + weight conversions up front ----
    run_split_f16(q, Aqh, Aql, M_ROWS * D_MODEL);
    run_split_f16(k, Akh, Akl, M_ROWS * D_MODEL);
    run_split_f16(v, Avh, Avl, M_ROWS * D_MODEL);
    run_conv_f16(Wq,  Wq16,  D_MODEL * D_MODEL);
    run_conv_f16(Wk,  Wk16,  D_MODEL * D_MODEL);
    run_conv_f16(Wv,  Wv16,  D_MODEL * D_MODEL);
    run_conv_f16(Wo,  Wo16,  D_MODEL * D_VALUE);
    run_conv_f16(Wc1, Wc116, D_FF * D_VALUE);
    run_conv_f16(Wc2, Wc216, D_VALUE * D_FF);
    run_conv_f16(Wl,  Wl16,  D_MODEL * D_VALUE);

    // ---- QKV projections (back-to-back) ----
    run_gemm<false, 2>(Aqh, Aql, Wq16, bq, nullptr, Qh, Ql, M_ROWS, D_MODEL, D_MODEL);
    run_gemm<false, 3>(Akh, Akl, Wk16, bk, nullptr, Kf, nullptr, M_ROWS, D_MODEL, D_MODEL);
    run_gemm<false, 3>(Avh, Avl, Wv16, bv, nullptr, Vf, nullptr, M_ROWS, D_MODEL, D_MODEL);

    // ---- V transpose per head ----
    vtrans_kernel<<<dim3(SEQ_L / 64, N_HEADS, B_BATCH), 256>>>(Vf, Vt);

    // ---- attention (fp16 2-term HMMA) -> fp16-pair O ----
    cudaFuncSetAttribute(attn_mma_kernel,
                         cudaFuncAttributeMaxDynamicSharedMemorySize, AT_SMEM);
    attn_mma_kernel<<<dim3(SEQ_L / 128, N_HEADS, B_BATCH), 256, AT_SMEM>>>(
        Qh, Ql, Kf, Vt, Ohp, Olp);

    // ---- output projection (fp32 out) ----
    run_gemm<false, 0>(Ohp, Olp, Wo16, bo, Proj, nullptr, nullptr,
                       M_ROWS, D_MODEL, D_MODEL);

    // ---- residual + LN1 (fp32 X + fp16-pair split) ----
    residual_ln_kernel<true, true><<<M_ROWS, 128>>>(v, Proj, g1, b1, X, Xh, Xl);

    // ---- FFN ----
    run_gemm<true, 2>(Xh, Xl, Wc116, bc1, nullptr, Fh, Fl, M_ROWS, D_FF, D_VALUE);
    run_gemm<false, 0>(Fh, Fl, Wc216, bc2, Y, nullptr, nullptr,
                       M_ROWS, D_VALUE, D_FF);

    // ---- residual + LN2 (fp16-pair split only) ----
    residual_ln_kernel<false, true><<<M_ROWS, 128>>>(X, Y, g2, b2, nullptr, X2h, X2l);

    // ---- final projection ----
    run_gemm<false, 0>(X2h, X2l, Wl16, bl, out, nullptr, nullptr,
                       M_ROWS, D_MODEL, D_VALUE);
}

// round 15
// speedup vs baseline: 3.4674x; 1.0684x over previous
#include <cuda_runtime.h>
#include <cuda_fp16.h>
#include <cstdint>

// ---------------------------------------------------------------------------
// Problem constants
// ---------------------------------------------------------------------------
#define B_BATCH 4
#define SEQ_L   2048
#define D_MODEL 512
#define D_VALUE 512
#define N_HEADS 8
#define HEAD_E  64
#define D_FF    2048
#define M_ROWS  (B_BATCH * SEQ_L)   // 8192

// ---------------------------------------------------------------------------
// Scratch (static device allocations)
// ---------------------------------------------------------------------------
__device__ float g_proj[M_ROWS * D_MODEL];
__device__ float g_x   [M_ROWS * D_VALUE];
__device__ float g_y   [M_ROWS * D_VALUE];

__device__ __half g_Aqh[M_ROWS * D_MODEL];
__device__ __half g_Aql[M_ROWS * D_MODEL];
__device__ __half g_Akh[M_ROWS * D_MODEL];
__device__ __half g_Akl[M_ROWS * D_MODEL];
__device__ __half g_Avh[M_ROWS * D_MODEL];
__device__ __half g_Avl[M_ROWS * D_MODEL];
__device__ __half g_Wq16[D_MODEL * D_MODEL];
__device__ __half g_Wk16[D_MODEL * D_MODEL];
__device__ __half g_Wv16[D_MODEL * D_MODEL];
__device__ __half g_Wo16[D_MODEL * D_VALUE];
__device__ __half g_Wc116[D_FF * D_VALUE];
__device__ __half g_Wc216[D_VALUE * D_FF];
__device__ __half g_Wl16[D_MODEL * D_VALUE];
__device__ __half g_Q  [M_ROWS * D_MODEL];   // single fp16
__device__ __half g_K  [M_ROWS * D_MODEL];
__device__ __half g_V  [M_ROWS * D_MODEL];
__device__ __half g_Vt [M_ROWS * D_MODEL];   // [B][H][E][L]
__device__ __half g_Oh [M_ROWS * D_MODEL];
__device__ __half g_Ol [M_ROWS * D_MODEL];
__device__ __half g_Xh [M_ROWS * D_VALUE];
__device__ __half g_Xl [M_ROWS * D_VALUE];
__device__ __half g_Fh [M_ROWS * D_FF];
__device__ __half g_Fl [M_ROWS * D_FF];
__device__ __half g_X2h[M_ROWS * D_VALUE];
__device__ __half g_X2l[M_ROWS * D_VALUE];

// ---------------------------------------------------------------------------
// helpers
// ---------------------------------------------------------------------------
__device__ __forceinline__ void split2h(float x, float y, uint32_t& hi, uint32_t& lo)
{
    __half hx = __float2half_rn(x);
    __half hy = __float2half_rn(y);
    __half2 h2 = __halves2half2(hx, hy);
    __half2 l2 = __halves2half2(
        __float2half_rn(x - __half2float(hx)),
        __float2half_rn(y - __half2float(hy)));
    hi = *reinterpret_cast<uint32_t*>(&h2);
    lo = *reinterpret_cast<uint32_t*>(&l2);
}

__device__ __forceinline__ uint32_t pack2h(float x, float y)
{
    __half2 h2 = __halves2half2(__float2half_rn(x), __float2half_rn(y));
    return *reinterpret_cast<uint32_t*>(&h2);
}

__device__ __forceinline__ void mma_f16(
    float& d0, float& d1, float& d2, float& d3,
    uint32_t a0, uint32_t a1, uint32_t a2, uint32_t a3,
    uint32_t b0, uint32_t b1)
{
    asm volatile(
        "mma.sync.aligned.m16n8k16.row.col.f32.f16.f16.f32 "
        "{%0,%1,%2,%3}, {%4,%5,%6,%7}, {%8,%9}, {%0,%1,%2,%3};"
        : "+f"(d0), "+f"(d1), "+f"(d2), "+f"(d3)
        : "r"(a0), "r"(a1), "r"(a2), "r"(a3), "r"(b0), "r"(b1));
}

__device__ __forceinline__ uint32_t smem_u32(const void* p)
{
    uint32_t a;
    asm("{ .reg .u64 t; cvta.to.shared.u64 t, %1; cvt.u32.u64 %0, t; }"
        : "=r"(a) : "l"(p));
    return a;
}

__device__ __forceinline__ void ldsm_x4(
    uint32_t& r0, uint32_t& r1, uint32_t& r2, uint32_t& r3, uint32_t addr)
{
    asm volatile(
        "ldmatrix.sync.aligned.m8n8.x4.shared.b16 {%0,%1,%2,%3}, [%4];"
        : "=r"(r0), "=r"(r1), "=r"(r2), "=r"(r3) : "r"(addr));
}

#define CP_ASYNC16(dst, src) \
    asm volatile("cp.async.cg.shared.global [%0], [%1], 16;" \
                 :: "r"(dst), "l"(src) : "memory")
#define CP_COMMIT() asm volatile("cp.async.commit_group;" ::: "memory")
#define CP_WAIT1()  asm volatile("cp.async.wait_group 1;" ::: "memory")
#define CP_WAIT0()  asm volatile("cp.async.wait_group 0;" ::: "memory")

// ---------------------------------------------------------------------------
// Split fp32 -> fp16 hi + fp16 lo (activations)
// ---------------------------------------------------------------------------
__global__ __launch_bounds__(256) void split_f16_kernel(
    const float* __restrict__ x,
    __half* __restrict__ hi, __half* __restrict__ lo, int n4)
{
    int i = blockIdx.x * 256 + threadIdx.x;
    if (i >= n4) return;
    float4 v = ((const float4*)x)[i];
    uint32_t h0, l0, h1, l1;
    split2h(v.x, v.y, h0, l0);
    split2h(v.z, v.w, h1, l1);
    ((uint32_t*)hi)[2 * i]     = h0;
    ((uint32_t*)hi)[2 * i + 1] = h1;
    ((uint32_t*)lo)[2 * i]     = l0;
    ((uint32_t*)lo)[2 * i + 1] = l1;
}

// fp32 -> fp16 single (weights)
__global__ __launch_bounds__(256) void conv_f16_kernel(
    const float* __restrict__ x, __half* __restrict__ o, int n4)
{
    int i = blockIdx.x * 256 + threadIdx.x;
    if (i >= n4) return;
    float4 v = ((const float4*)x)[i];
    ((uint32_t*)o)[2 * i]     = pack2h(v.x, v.y);
    ((uint32_t*)o)[2 * i + 1] = pack2h(v.z, v.w);
}

// ---------------------------------------------------------------------------
// fp16 HMMA GEMM: C = (Ah+Al) @ W^T + bias.  A fp16 pair, B fp16 single.
// CTA 128x128, BK=32, 3-stage cp.async, ldmatrix, 2 mma terms.
// OUT: 0 = fp32 C, 2 = fp16 pair, 3 = fp16 single
// ---------------------------------------------------------------------------
#define GS 40
#define GA_BYTES (128 * GS * 2)
#define GSTAGE_BYTES (3 * GA_BYTES)
#define GSTAGES 3
#define GSMEM (GSTAGES * GSTAGE_BYTES)   // 92160

template<bool RELU, int OUT>
__global__ __launch_bounds__(256) void gemm_f16_kernel(
    const __half* __restrict__ Ah, const __half* __restrict__ Al,
    const __half* __restrict__ B,
    const float* __restrict__ bias, float* __restrict__ C,
    __half* __restrict__ Ch, __half* __restrict__ Cl,
    int M, int N, int K)
{
    extern __shared__ char smem[];
    const uint32_t su = smem_u32(smem);

    const int tid  = threadIdx.x;
    const int lane = tid & 31;
    const int warp = tid >> 5;
    const int wm = (warp & 1) * 64;
    const int wn = (warp >> 1) * 32;
    const int m0 = blockIdx.y * 128;
    const int n0 = blockIdx.x * 128;

    const int crow = tid >> 1;
    const uint32_t cc32 = (uint32_t)(tid & 1) * 32;
    const int ce = (tid & 1) * 16;

    const __half* gAh = Ah + (size_t)(m0 + crow) * K + ce;
    const __half* gAl = Al + (size_t)(m0 + crow) * K + ce;
    const __half* gB  = B  + (size_t)(n0 + crow) * K + ce;
    const uint32_t so = (uint32_t)crow * (GS * 2) + cc32;

    auto load_stage = [&](int i) {
        const uint32_t sb = su + (uint32_t)(i % GSTAGES) * GSTAGE_BYTES;
        const size_t kof = (size_t)i * 32;
        CP_ASYNC16(sb + 0 * GA_BYTES + so,      gAh + kof);
        CP_ASYNC16(sb + 0 * GA_BYTES + so + 16, gAh + kof + 8);
        CP_ASYNC16(sb + 1 * GA_BYTES + so,      gAl + kof);
        CP_ASYNC16(sb + 1 * GA_BYTES + so + 16, gAl + kof + 8);
        CP_ASYNC16(sb + 2 * GA_BYTES + so,      gB + kof);
        CP_ASYNC16(sb + 2 * GA_BYTES + so + 16, gB + kof + 8);
        CP_COMMIT();
    };

    const int l8 = lane & 7, lq = lane >> 3;
    const uint32_t aOff = (uint32_t)(((wm + l8 + (lq & 1) * 8) * GS + (lq >> 1) * 8) * 2);
    const uint32_t bOff = (uint32_t)(((wn + l8 + (lq >> 1) * 8) * GS + (lq & 1) * 8) * 2);

    float acc[4][4][4];
#pragma unroll
    for (int mi = 0; mi < 4; ++mi)
#pragma unroll
        for (int ni = 0; ni < 4; ++ni)
#pragma unroll
            for (int r = 0; r < 4; ++r) acc[mi][ni][r] = 0.f;

    load_stage(0);
    load_stage(1);
    const int nch = K >> 5;

    for (int i = 0; i < nch; ++i) {
        if (i + 1 < nch) { CP_WAIT1(); } else { CP_WAIT0(); }
        __syncthreads();
        if (i + 2 < nch) load_stage(i + 2);
        const uint32_t sb = su + (uint32_t)(i % GSTAGES) * GSTAGE_BYTES;
#pragma unroll
        for (int ks = 0; ks < 2; ++ks) {
            const uint32_t ko = (uint32_t)ks * 32;
            uint32_t aH[4][4], aL[4][4], bH[4][2];
#pragma unroll
            for (int mi = 0; mi < 4; ++mi) {
                const uint32_t ad = sb + 0 * GA_BYTES + aOff
                                  + (uint32_t)mi * (16 * GS * 2) + ko;
                ldsm_x4(aH[mi][0], aH[mi][1], aH[mi][2], aH[mi][3], ad);
                ldsm_x4(aL[mi][0], aL[mi][1], aL[mi][2], aL[mi][3], ad + GA_BYTES);
            }
#pragma unroll
            for (int np = 0; np < 2; ++np) {
                const uint32_t bd = sb + 2 * GA_BYTES + bOff
                                  + (uint32_t)np * (16 * GS * 2) + ko;
                ldsm_x4(bH[2 * np][0], bH[2 * np][1],
                        bH[2 * np + 1][0], bH[2 * np + 1][1], bd);
            }
#pragma unroll
            for (int mi = 0; mi < 4; ++mi)
#pragma unroll
                for (int ni = 0; ni < 4; ++ni) {
                    float* d = acc[mi][ni];
                    mma_f16(d[0], d[1], d[2], d[3],
                            aH[mi][0], aH[mi][1], aH[mi][2], aH[mi][3],
                            bH[ni][0], bH[ni][1]);
                    mma_f16(d[0], d[1], d[2], d[3],
                            aL[mi][0], aL[mi][1], aL[mi][2], aL[mi][3],
                            bH[ni][0], bH[ni][1]);
                }
        }
    }

#pragma unroll
    for (int mi = 0; mi < 4; ++mi) {
        const int m = m0 + wm + mi * 16 + (lane >> 2);
#pragma unroll
        for (int ni = 0; ni < 4; ++ni) {
            const int nc = n0 + wn + ni * 8 + 2 * (lane & 3);
            float b0 = bias[nc], b1 = bias[nc + 1];
            float c0 = acc[mi][ni][0] + b0, c1 = acc[mi][ni][1] + b1;
            float c2 = acc[mi][ni][2] + b0, c3 = acc[mi][ni][3] + b1;
            if (RELU) {
                c0 = fmaxf(c0, 0.f); c1 = fmaxf(c1, 0.f);
                c2 = fmaxf(c2, 0.f); c3 = fmaxf(c3, 0.f);
            }
            if (OUT == 0) {
                *(float2*)&C[(size_t)m * N + nc]       = make_float2(c0, c1);
                *(float2*)&C[(size_t)(m + 8) * N + nc] = make_float2(c2, c3);
            } else if (OUT == 2) {
                uint32_t h0, l0, h1, l1;
                split2h(c0, c1, h0, l0);
                split2h(c2, c3, h1, l1);
                *(uint32_t*)&Ch[(size_t)m * N + nc]       = h0;
                *(uint32_t*)&Cl[(size_t)m * N + nc]       = l0;
                *(uint32_t*)&Ch[(size_t)(m + 8) * N + nc] = h1;
                *(uint32_t*)&Cl[(size_t)(m + 8) * N + nc] = l1;
            } else {
                *(uint32_t*)&Ch[(size_t)m * N + nc]       = pack2h(c0, c1);
                *(uint32_t*)&Ch[(size_t)(m + 8) * N + nc] = pack2h(c2, c3);
            }
        }
    }
}

// ---------------------------------------------------------------------------
// V transpose (fp16 single): V [token][512] -> Vt [B][H][E=64][L=2048]
// ---------------------------------------------------------------------------
__global__ __launch_bounds__(256) void vtrans_kernel(
    const __half* __restrict__ V, __half* __restrict__ Vt)
{
    __shared__ __half tile[64][72];
    const int lt = blockIdx.x, h = blockIdx.y, b = blockIdx.z;
    const int t = threadIdx.x;
    {
        int l = t >> 2, e0 = (t & 3) * 16;
        size_t g = ((size_t)(b * SEQ_L + lt * 64 + l)) * D_MODEL + h * 64 + e0;
        int4 a0 = *(const int4*)(V + g);
        int4 a1 = *(const int4*)(V + g + 8);
        *(int4*)&tile[l][e0]     = a0;
        *(int4*)&tile[l][e0 + 8] = a1;
    }
    __syncthreads();
    {
        int e = t >> 2, l0 = (t & 3) * 16;
        __align__(16) __half buf[16];
#pragma unroll
        for (int i = 0; i < 16; ++i) buf[i] = tile[l0 + i][e];
        size_t g = ((size_t)((b * N_HEADS + h) * 64 + e)) * SEQ_L + lt * 64 + l0;
        ((int4*)(Vt + g))[0] = ((int4*)buf)[0];
        ((int4*)(Vt + g))[1] = ((int4*)buf)[1];
    }
}

// ---------------------------------------------------------------------------
// fp16 tensor-core causal flash attention — ALL single fp16 operands:
// Q, K, V, P single (1 mma per phase). Output = fp16 pair (feeds Wo).
// 128q x 64k tile, 8 warps.
// ---------------------------------------------------------------------------
#define AT_S 72
#define AT_SMEM ((128 + 2 * 64) * AT_S * 2)   // 36864 B

__global__ __launch_bounds__(256, 1) void attn_mma_kernel(
    const __half* __restrict__ Q, const __half* __restrict__ K,
    const __half* __restrict__ Vt,
    __half* __restrict__ Oh, __half* __restrict__ Ol)
{
    extern __shared__ __half smh[];
    __half* sQ = smh;
    __half* sK = sQ + 128 * AT_S;
    __half* sV = sK + 64 * AT_S;

    const int tid = threadIdx.x, lane = tid & 31, warp = tid >> 5;
    const int qt = blockIdx.x, h = blockIdx.y, b = blockIdx.z;
    const int q0 = qt * 128;
    const size_t qkBase = ((size_t)b * SEQ_L) * D_MODEL + (size_t)h * HEAD_E;
    const size_t vtBase = ((size_t)(b * N_HEADS + h)) * HEAD_E * SEQ_L;

    // ---- load Q tile (single): 128 rows x 64 cols ----
    {
        int row = tid >> 1, e0 = (tid & 1) * 32;
        size_t g = qkBase + (size_t)(q0 + row) * D_MODEL + e0;
        int4 a0 = *(const int4*)(Q + g);
        int4 a1 = *(const int4*)(Q + g + 8);
        int4 a2 = *(const int4*)(Q + g + 16);
        int4 a3 = *(const int4*)(Q + g + 24);
        int4* d = (int4*)(sQ + row * AT_S + e0);
        d[0] = a0; d[1] = a1; d[2] = a2; d[3] = a3;
    }

    float m0 = -1e30f, m1 = -1e30f, l0s = 0.f, l1s = 0.f;
    float oacc[8][4];
#pragma unroll
    for (int nt = 0; nt < 8; ++nt)
#pragma unroll
        for (int r = 0; r < 4; ++r) oacc[nt][r] = 0.f;

    const int ldr = tid >> 2;
    const int ldc = (tid & 3) * 16;
    const int nkt = 2 * qt + 2;

    int4 pK0, pK1, pV0, pV1;
    {
        size_t gk = qkBase + (size_t)ldr * D_MODEL + ldc;
        pK0 = *(const int4*)(K + gk); pK1 = *(const int4*)(K + gk + 8);
        size_t gv = vtBase + (size_t)ldr * SEQ_L + ldc;
        pV0 = *(const int4*)(Vt + gv); pV1 = *(const int4*)(Vt + gv + 8);
    }

    const int gr = warp * 16 + (lane >> 2);
    const int cc = 2 * (lane & 3);

    for (int kt = 0; kt < nkt; ++kt) {
        const int k0 = kt * 64;
        __syncthreads();
        {
            int4* d;
            d = (int4*)(sK + ldr * AT_S + ldc); d[0] = pK0; d[1] = pK1;
            d = (int4*)(sV + ldr * AT_S + ldc); d[0] = pV0; d[1] = pV1;
        }
        __syncthreads();
        if (kt + 1 < nkt) {
            size_t gk = qkBase + (size_t)(k0 + 64 + ldr) * D_MODEL + ldc;
            pK0 = *(const int4*)(K + gk); pK1 = *(const int4*)(K + gk + 8);
            size_t gv = vtBase + (size_t)ldr * SEQ_L + k0 + 64 + ldc;
            pV0 = *(const int4*)(Vt + gv); pV1 = *(const int4*)(Vt + gv + 8);
        }

        // ---- S = Q K^T : 1 mma per (es, nt) ----
        float sacc[8][4];
#pragma unroll
        for (int nt = 0; nt < 8; ++nt)
#pragma unroll
            for (int r = 0; r < 4; ++r) sacc[nt][r] = 0.f;

#pragma unroll
        for (int es = 0; es < 4; ++es) {
            const int e = es * 16 + cc;
            uint32_t a0 = *(const uint32_t*)&sQ[gr * AT_S + e];
            uint32_t a1 = *(const uint32_t*)&sQ[(gr + 8) * AT_S + e];
            uint32_t a2 = *(const uint32_t*)&sQ[gr * AT_S + e + 8];
            uint32_t a3 = *(const uint32_t*)&sQ[(gr + 8) * AT_S + e + 8];
#pragma unroll
            for (int nt = 0; nt < 8; ++nt) {
                const int n = nt * 8 + (lane >> 2);
                uint32_t b0 = *(const uint32_t*)&sK[n * AT_S + e];
                uint32_t b1 = *(const uint32_t*)&sK[n * AT_S + e + 8];
                float* dd = sacc[nt];
                mma_f16(dd[0], dd[1], dd[2], dd[3], a0, a1, a2, a3, b0, b1);
            }
        }

        // ---- scale + causal mask ----
        const float scl = 0.125f;
        if (kt >= 2 * qt) {
            const int qg0 = q0 + gr, qg1 = qg0 + 8;
#pragma unroll
            for (int nt = 0; nt < 8; ++nt) {
                const int kg = k0 + nt * 8 + cc;
                sacc[nt][0] = (kg     > qg0) ? -1e30f : sacc[nt][0] * scl;
                sacc[nt][1] = (kg + 1 > qg0) ? -1e30f : sacc[nt][1] * scl;
                sacc[nt][2] = (kg     > qg1) ? -1e30f : sacc[nt][2] * scl;
                sacc[nt][3] = (kg + 1 > qg1) ? -1e30f : sacc[nt][3] * scl;
            }
        } else {
#pragma unroll
            for (int nt = 0; nt < 8; ++nt) {
                sacc[nt][0] *= scl; sacc[nt][1] *= scl;
                sacc[nt][2] *= scl; sacc[nt][3] *= scl;
            }
        }

        // ---- online softmax ----
        float mx0 = -1e30f, mx1 = -1e30f;
#pragma unroll
        for (int nt = 0; nt < 8; ++nt) {
            mx0 = fmaxf(mx0, fmaxf(sacc[nt][0], sacc[nt][1]));
            mx1 = fmaxf(mx1, fmaxf(sacc[nt][2], sacc[nt][3]));
        }
        mx0 = fmaxf(mx0, __shfl_xor_sync(0xffffffffu, mx0, 1));
        mx0 = fmaxf(mx0, __shfl_xor_sync(0xffffffffu, mx0, 2));
        mx1 = fmaxf(mx1, __shfl_xor_sync(0xffffffffu, mx1, 1));
        mx1 = fmaxf(mx1, __shfl_xor_sync(0xffffffffu, mx1, 2));
        const float mn0 = fmaxf(m0, mx0), mn1 = fmaxf(m1, mx1);
        const float a0 = __expf(m0 - mn0), a1 = __expf(m1 - mn1);
        m0 = mn0; m1 = mn1;

        float s0 = 0.f, s1 = 0.f;
        uint32_t pP[4][4];
#pragma unroll
        for (int ks = 0; ks < 4; ++ks) {
            const int n0t = 2 * ks, n1t = 2 * ks + 1;
            float p00 = __expf(sacc[n0t][0] - mn0);
            float p01 = __expf(sacc[n0t][1] - mn0);
            float p10 = __expf(sacc[n0t][2] - mn1);
            float p11 = __expf(sacc[n0t][3] - mn1);
            float p20 = __expf(sacc[n1t][0] - mn0);
            float p21 = __expf(sacc[n1t][1] - mn0);
            float p30 = __expf(sacc[n1t][2] - mn1);
            float p31 = __expf(sacc[n1t][3] - mn1);
            s0 += p00 + p01 + p20 + p21;
            s1 += p10 + p11 + p30 + p31;
            pP[ks][0] = pack2h(p00, p01);
            pP[ks][1] = pack2h(p10, p11);
            pP[ks][2] = pack2h(p20, p21);
            pP[ks][3] = pack2h(p30, p31);
        }
        s0 += __shfl_xor_sync(0xffffffffu, s0, 1);
        s0 += __shfl_xor_sync(0xffffffffu, s0, 2);
        s1 += __shfl_xor_sync(0xffffffffu, s1, 1);
        s1 += __shfl_xor_sync(0xffffffffu, s1, 2);
        l0s = l0s * a0 + s0;
        l1s = l1s * a1 + s1;
#pragma unroll
        for (int nt = 0; nt < 8; ++nt) {
            oacc[nt][0] *= a0; oacc[nt][1] *= a0;
            oacc[nt][2] *= a1; oacc[nt][3] *= a1;
        }

        // ---- O += P V : 1 mma per (ks, nt) ----
#pragma unroll
        for (int ks = 0; ks < 4; ++ks) {
            const int kk = ks * 16 + cc;
#pragma unroll
            for (int nt = 0; nt < 8; ++nt) {
                const int n = nt * 8 + (lane >> 2);
                uint32_t b0 = *(const uint32_t*)&sV[n * AT_S + kk];
                uint32_t b1 = *(const uint32_t*)&sV[n * AT_S + kk + 8];
                float* dd = oacc[nt];
                mma_f16(dd[0], dd[1], dd[2], dd[3],
                        pP[ks][0], pP[ks][1], pP[ks][2], pP[ks][3], b0, b1);
            }
        }
    }

    // ---- epilogue: normalize, fp16-pair split, store ----
    const float inv0 = 1.f / l0s, inv1 = 1.f / l1s;
    const size_t r0 = qkBase + (size_t)(q0 + gr) * D_MODEL + cc;
    const size_t r1 = r0 + 8 * D_MODEL;
#pragma unroll
    for (int nt = 0; nt < 8; ++nt) {
        uint32_t h0, lo0, h1, lo1;
        split2h(oacc[nt][0] * inv0, oacc[nt][1] * inv0, h0, lo0);
        split2h(oacc[nt][2] * inv1, oacc[nt][3] * inv1, h1, lo1);
        *(uint32_t*)&Oh[r0 + nt * 8] = h0;
        *(uint32_t*)&Ol[r0 + nt * 8] = lo0;
        *(uint32_t*)&Oh[r1 + nt * 8] = h1;
        *(uint32_t*)&Ol[r1 + nt * 8] = lo1;
    }
}

// ---------------------------------------------------------------------------
// Residual + LayerNorm (rows of 512); optional fp32 out + fp16-pair split out
// ---------------------------------------------------------------------------
template<bool F32OUT, bool SPLITOUT>
__global__ __launch_bounds__(128) void residual_ln_kernel(
    const float* __restrict__ a, const float* __restrict__ b,
    const float* __restrict__ gamma, const float* __restrict__ beta,
    float* __restrict__ out,
    __half* __restrict__ outh, __half* __restrict__ outl)
{
    const int row = blockIdx.x;
    const int tid = threadIdx.x;
    const size_t base = (size_t)row * D_VALUE;

    float4 va = ((const float4*)(a + base))[tid];
    float4 vb = ((const float4*)(b + base))[tid];
    float4 v = make_float4(va.x + vb.x, va.y + vb.y, va.z + vb.z, va.w + vb.w);

    float s  = v.x + v.y + v.z + v.w;
    float ss = v.x * v.x + v.y * v.y + v.z * v.z + v.w * v.w;
#pragma unroll
    for (int off = 16; off >= 1; off >>= 1) {
        s  += __shfl_xor_sync(0xffffffffu, s, off);
        ss += __shfl_xor_sync(0xffffffffu, ss, off);
    }
    __shared__ float red[8];
    const int wid = tid >> 5;
    if ((tid & 31) == 0) { red[wid] = s; red[4 + wid] = ss; }
    __syncthreads();
    s  = red[0] + red[1] + red[2] + red[3];
    ss = red[4] + red[5] + red[6] + red[7];

    const float mu = s * (1.f / (float)D_VALUE);
    float var = ss * (1.f / (float)D_VALUE) - mu * mu;
    const float rn = rsqrtf(var + 1e-5f);

    float4 g4 = ((const float4*)gamma)[tid];
    float4 b4 = ((const float4*)beta)[tid];
    float4 r;
    r.x = (v.x - mu) * rn * g4.x + b4.x;
    r.y = (v.y - mu) * rn * g4.y + b4.y;
    r.z = (v.z - mu) * rn * g4.z + b4.z;
    r.w = (v.w - mu) * rn * g4.w + b4.w;
    if (F32OUT) ((float4*)(out + base))[tid] = r;
    if (SPLITOUT) {
        uint32_t h0, l0, h1, l1;
        split2h(r.x, r.y, h0, l0);
        split2h(r.z, r.w, h1, l1);
        ((uint32_t*)(outh + base))[2 * tid]     = h0;
        ((uint32_t*)(outh + base))[2 * tid + 1] = h1;
        ((uint32_t*)(outl + base))[2 * tid]     = l0;
        ((uint32_t*)(outl + base))[2 * tid + 1] = l1;
    }
}

// ---------------------------------------------------------------------------
// Launch
// ---------------------------------------------------------------------------
static inline void run_split_f16(const float* x, __half* hi, __half* lo, int n)
{
    int n4 = n / 4;
    split_f16_kernel<<<(n4 + 255) / 256, 256>>>(x, hi, lo, n4);
}

static inline void run_conv_f16(const float* x, __half* o, int n)
{
    int n4 = n / 4;
    conv_f16_kernel<<<(n4 + 255) / 256, 256>>>(x, o, n4);
}

template<bool RELU, int OUT>
static inline void run_gemm(
    const __half* Ah, const __half* Al, const __half* B,
    const float* bias, float* C, __half* Ch, __half* Cl,
    int M, int N, int K)
{
    cudaFuncSetAttribute(gemm_f16_kernel<RELU, OUT>,
                         cudaFuncAttributeMaxDynamicSharedMemorySize, GSMEM);
    gemm_f16_kernel<RELU, OUT><<<dim3(N / 128, M / 128), 256, GSMEM>>>(
        Ah, Al, B, bias, C, Ch, Cl, M, N, K);
}

extern "C" void kernel_launch(void* const* d_in, const int* in_sizes, int n_in,
                              void* d_out, int out_size)
{
    const float* q   = (const float*)d_in[0];
    const float* k   = (const float*)d_in[1];
    const float* v   = (const float*)d_in[2];
    const float* Wq  = (const float*)d_in[3];
    const float* bq  = (const float*)d_in[4];
    const float* Wk  = (const float*)d_in[5];
    const float* bk  = (const float*)d_in[6];
    const float* Wv  = (const float*)d_in[7];
    const float* bv  = (const float*)d_in[8];
    const float* Wo  = (const float*)d_in[9];
    const float* bo  = (const float*)d_in[10];
    const float* Wc1 = (const float*)d_in[11];
    const float* bc1 = (const float*)d_in[12];
    const float* Wc2 = (const float*)d_in[13];
    const float* bc2 = (const float*)d_in[14];
    const float* g1  = (const float*)d_in[15];
    const float* b1  = (const float*)d_in[16];
    const float* g2  = (const float*)d_in[17];
    const float* b2  = (const float*)d_in[18];
    const float* Wl  = (const float*)d_in[19];
    const float* bl  = (const float*)d_in[20];
    float* out = (float*)d_out;

    float *Proj, *X, *Y;
    __half *Aqh, *Aql, *Akh, *Akl, *Avh, *Avl;
    __half *Wq16, *Wk16, *Wv16, *Wo16, *Wc116, *Wc216, *Wl16;
    __half *Qf, *Kf, *Vf, *Vt, *Ohp, *Olp, *Xh, *Xl, *Fh, *Fl, *X2h, *X2l;
    cudaGetSymbolAddress((void**)&Proj,  g_proj);
    cudaGetSymbolAddress((void**)&X,     g_x);
    cudaGetSymbolAddress((void**)&Y,     g_y);
    cudaGetSymbolAddress((void**)&Aqh,   g_Aqh);
    cudaGetSymbolAddress((void**)&Aql,   g_Aql);
    cudaGetSymbolAddress((void**)&Akh,   g_Akh);
    cudaGetSymbolAddress((void**)&Akl,   g_Akl);
    cudaGetSymbolAddress((void**)&Avh,   g_Avh);
    cudaGetSymbolAddress((void**)&Avl,   g_Avl);
    cudaGetSymbolAddress((void**)&Wq16,  g_Wq16);
    cudaGetSymbolAddress((void**)&Wk16,  g_Wk16);
    cudaGetSymbolAddress((void**)&Wv16,  g_Wv16);
    cudaGetSymbolAddress((void**)&Wo16,  g_Wo16);
    cudaGetSymbolAddress((void**)&Wc116, g_Wc116);
    cudaGetSymbolAddress((void**)&Wc216, g_Wc216);
    cudaGetSymbolAddress((void**)&Wl16,  g_Wl16);
    cudaGetSymbolAddress((void**)&Qf,    g_Q);
    cudaGetSymbolAddress((void**)&Kf,    g_K);
    cudaGetSymbolAddress((void**)&Vf,    g_V);
    cudaGetSymbolAddress((void**)&Vt,    g_Vt);
    cudaGetSymbolAddress((void**)&Ohp,   g_Oh);
    cudaGetSymbolAddress((void**)&Olp,   g_Ol);
    cudaGetSymbolAddress((void**)&Xh,    g_Xh);
    cudaGetSymbolAddress((void**)&Xl,    g_Xl);
    cudaGetSymbolAddress((void**)&Fh,    g_Fh);
    cudaGetSymbolAddress((void**)&Fl,    g_Fl);
    cudaGetSymbolAddress((void**)&X2h,   g_X2h);
    cudaGetSymbolAddress((void**)&X2l,   g_X2l);

    // ---- all input splits + weight conversions up front ----
    run_split_f16(q, Aqh, Aql, M_ROWS * D_MODEL);
    run_split_f16(k, Akh, Akl, M_ROWS * D_MODEL);
    run_split_f16(v, Avh, Avl, M_ROWS * D_MODEL);
    run_conv_f16(Wq,  Wq16,  D_MODEL * D_MODEL);
    run_conv_f16(Wk,  Wk16,  D_MODEL * D_MODEL);
    run_conv_f16(Wv,  Wv16,  D_MODEL * D_MODEL);
    run_conv_f16(Wo,  Wo16,  D_MODEL * D_VALUE);
    run_conv_f16(Wc1, Wc116, D_FF * D_VALUE);
    run_conv_f16(Wc2, Wc216, D_VALUE * D_FF);
    run_conv_f16(Wl,  Wl16,  D_MODEL * D_VALUE);

    // ---- QKV projections (all fp16-single outputs) ----
    run_gemm<false, 3>(Aqh, Aql, Wq16, bq, nullptr, Qf, nullptr, M_ROWS, D_MODEL, D_MODEL);
    run_gemm<false, 3>(Akh, Akl, Wk16, bk, nullptr, Kf, nullptr, M_ROWS, D_MODEL, D_MODEL);
    run_gemm<false, 3>(Avh, Avl, Wv16, bv, nullptr, Vf, nullptr, M_ROWS, D_MODEL, D_MODEL);

    // ---- V transpose per head ----
    vtrans_kernel<<<dim3(SEQ_L / 64, N_HEADS, B_BATCH), 256>>>(Vf, Vt);

    // ---- attention (fp16 single, 1+1 mma) -> fp16-pair O ----
    cudaFuncSetAttribute(attn_mma_kernel,
                         cudaFuncAttributeMaxDynamicSharedMemorySize, AT_SMEM);
    attn_mma_kernel<<<dim3(SEQ_L / 128, N_HEADS, B_BATCH), 256, AT_SMEM>>>(
        Qf, Kf, Vt, Ohp, Olp);

    // ---- output projection (fp32 out) ----
    run_gemm<false, 0>(Ohp, Olp, Wo16, bo, Proj, nullptr, nullptr,
                       M_ROWS, D_MODEL, D_MODEL);

    // ---- residual + LN1 (fp32 X + fp16-pair split) ----
    residual_ln_kernel<true, true><<<M_ROWS, 128>>>(v, Proj, g1, b1, X, Xh, Xl);

    // ---- FFN ----
    run_gemm<true, 2>(Xh, Xl, Wc116, bc1, nullptr, Fh, Fl, M_ROWS, D_FF, D_VALUE);
    run_gemm<false, 0>(Fh, Fl, Wc216, bc2, Y, nullptr, nullptr,
                       M_ROWS, D_VALUE, D_FF);

    // ---- residual + LN2 (fp16-pair split only) ----
    residual_ln_kernel<false, true><<<M_ROWS, 128>>>(X, Y, g2, b2, nullptr, X2h, X2l);

    // ---- final projection ----
    run_gemm<false, 0>(X2h, X2l, Wl16, bl, out, nullptr, nullptr,
                       M_ROWS, D_MODEL, D_VALUE);
}

// round 16
// speedup vs baseline: 4.8639x; 1.4027x over previous
#include <cuda_runtime.h>
#include <cuda_fp16.h>
#include <cstdint>

// ---------------------------------------------------------------------------
// Problem constants
// ---------------------------------------------------------------------------
#define B_BATCH 4
#define SEQ_L   2048
#define D_MODEL 512
#define D_VALUE 512
#define N_HEADS 8
#define HEAD_E  64
#define D_FF    2048
#define M_ROWS  (B_BATCH * SEQ_L)   // 8192

// ---------------------------------------------------------------------------
// Scratch (static device allocations)
// ---------------------------------------------------------------------------
__device__ float g_proj[M_ROWS * D_MODEL];
__device__ float g_x   [M_ROWS * D_VALUE];
__device__ float g_y   [M_ROWS * D_VALUE];

__device__ __half g_q16[M_ROWS * D_MODEL];
__device__ __half g_k16[M_ROWS * D_MODEL];
__device__ __half g_v16[M_ROWS * D_MODEL];
__device__ __half g_Wq16[D_MODEL * D_MODEL];
__device__ __half g_Wk16[D_MODEL * D_MODEL];
__device__ __half g_Wv16[D_MODEL * D_MODEL];
__device__ __half g_Wo16[D_MODEL * D_VALUE];
__device__ __half g_Wc116[D_FF * D_VALUE];
__device__ __half g_Wc216[D_VALUE * D_FF];
__device__ __half g_Wl16[D_MODEL * D_VALUE];
__device__ __half g_Q  [M_ROWS * D_MODEL];
__device__ __half g_K  [M_ROWS * D_MODEL];
__device__ __half g_V  [M_ROWS * D_MODEL];
__device__ __half g_Vt [M_ROWS * D_MODEL];   // [B][H][E][L]
__device__ __half g_O  [M_ROWS * D_MODEL];
__device__ __half g_Xh [M_ROWS * D_VALUE];
__device__ __half g_F  [M_ROWS * D_FF];
__device__ __half g_X2h[M_ROWS * D_VALUE];

// ---------------------------------------------------------------------------
// helpers
// ---------------------------------------------------------------------------
__device__ __forceinline__ uint32_t pack2h(float x, float y)
{
    __half2 h2 = __halves2half2(__float2half_rn(x), __float2half_rn(y));
    return *reinterpret_cast<uint32_t*>(&h2);
}

__device__ __forceinline__ void mma_f16(
    float& d0, float& d1, float& d2, float& d3,
    uint32_t a0, uint32_t a1, uint32_t a2, uint32_t a3,
    uint32_t b0, uint32_t b1)
{
    asm volatile(
        "mma.sync.aligned.m16n8k16.row.col.f32.f16.f16.f32 "
        "{%0,%1,%2,%3}, {%4,%5,%6,%7}, {%8,%9}, {%0,%1,%2,%3};"
        : "+f"(d0), "+f"(d1), "+f"(d2), "+f"(d3)
        : "r"(a0), "r"(a1), "r"(a2), "r"(a3), "r"(b0), "r"(b1));
}

__device__ __forceinline__ uint32_t smem_u32(const void* p)
{
    uint32_t a;
    asm("{ .reg .u64 t; cvta.to.shared.u64 t, %1; cvt.u32.u64 %0, t; }"
        : "=r"(a) : "l"(p));
    return a;
}

__device__ __forceinline__ void ldsm_x4(
    uint32_t& r0, uint32_t& r1, uint32_t& r2, uint32_t& r3, uint32_t addr)
{
    asm volatile(
        "ldmatrix.sync.aligned.m8n8.x4.shared.b16 {%0,%1,%2,%3}, [%4];"
        : "=r"(r0), "=r"(r1), "=r"(r2), "=r"(r3) : "r"(addr));
}

#define CP_ASYNC16(dst, src) \
    asm volatile("cp.async.cg.shared.global [%0], [%1], 16;" \
                 :: "r"(dst), "l"(src) : "memory")
#define CP_COMMIT() asm volatile("cp.async.commit_group;" ::: "memory")
#define CP_WAIT1()  asm volatile("cp.async.wait_group 1;" ::: "memory")
#define CP_WAIT0()  asm volatile("cp.async.wait_group 0;" ::: "memory")

// ---------------------------------------------------------------------------
// fp32 -> fp16 single
// ---------------------------------------------------------------------------
__global__ __launch_bounds__(256) void conv_f16_kernel(
    const float* __restrict__ x, __half* __restrict__ o, int n4)
{
    int i = blockIdx.x * 256 + threadIdx.x;
    if (i >= n4) return;
    float4 v = ((const float4*)x)[i];
    ((uint32_t*)o)[2 * i]     = pack2h(v.x, v.y);
    ((uint32_t*)o)[2 * i + 1] = pack2h(v.z, v.w);
}

// ---------------------------------------------------------------------------
// fp16 HMMA GEMM (single x single): C = A @ W^T + bias.
// CTA 128x128, BK=32, 3-stage cp.async, ldmatrix, 1 mma term.
// OUT: 0 = fp32 C, 3 = fp16 single
// ---------------------------------------------------------------------------
#define GS 40
#define GA_BYTES (128 * GS * 2)          // 10240 per array
#define GSTAGE_BYTES (2 * GA_BYTES)      // 20480 per stage (A, B)
#define GSTAGES 3
#define GSMEM (GSTAGES * GSTAGE_BYTES)   // 61440

template<bool RELU, int OUT>
__global__ __launch_bounds__(256) void gemm_f16_kernel(
    const __half* __restrict__ A, const __half* __restrict__ B,
    const float* __restrict__ bias, float* __restrict__ C,
    __half* __restrict__ Ch,
    int M, int N, int K)
{
    extern __shared__ char smem[];
    const uint32_t su = smem_u32(smem);

    const int tid  = threadIdx.x;
    const int lane = tid & 31;
    const int warp = tid >> 5;
    const int wm = (warp & 1) * 64;
    const int wn = (warp >> 1) * 32;
    const int m0 = blockIdx.y * 128;
    const int n0 = blockIdx.x * 128;

    const int crow = tid >> 1;
    const uint32_t cc32 = (uint32_t)(tid & 1) * 32;
    const int ce = (tid & 1) * 16;

    const __half* gA = A + (size_t)(m0 + crow) * K + ce;
    const __half* gB = B + (size_t)(n0 + crow) * K + ce;
    const uint32_t so = (uint32_t)crow * (GS * 2) + cc32;

    auto load_stage = [&](int i) {
        const uint32_t sb = su + (uint32_t)(i % GSTAGES) * GSTAGE_BYTES;
        const size_t kof = (size_t)i * 32;
        CP_ASYNC16(sb + 0 * GA_BYTES + so,      gA + kof);
        CP_ASYNC16(sb + 0 * GA_BYTES + so + 16, gA + kof + 8);
        CP_ASYNC16(sb + 1 * GA_BYTES + so,      gB + kof);
        CP_ASYNC16(sb + 1 * GA_BYTES + so + 16, gB + kof + 8);
        CP_COMMIT();
    };

    const int l8 = lane & 7, lq = lane >> 3;
    const uint32_t aOff = (uint32_t)(((wm + l8 + (lq & 1) * 8) * GS + (lq >> 1) * 8) * 2);
    const uint32_t bOff = (uint32_t)(((wn + l8 + (lq >> 1) * 8) * GS + (lq & 1) * 8) * 2);

    float acc[4][4][4];
#pragma unroll
    for (int mi = 0; mi < 4; ++mi)
#pragma unroll
        for (int ni = 0; ni < 4; ++ni)
#pragma unroll
            for (int r = 0; r < 4; ++r) acc[mi][ni][r] = 0.f;

    load_stage(0);
    load_stage(1);
    const int nch = K >> 5;

    for (int i = 0; i < nch; ++i) {
        if (i + 1 < nch) { CP_WAIT1(); } else { CP_WAIT0(); }
        __syncthreads();
        if (i + 2 < nch) load_stage(i + 2);
        const uint32_t sb = su + (uint32_t)(i % GSTAGES) * GSTAGE_BYTES;
#pragma unroll
        for (int ks = 0; ks < 2; ++ks) {
            const uint32_t ko = (uint32_t)ks * 32;
            uint32_t aF[4][4], bF[4][2];
#pragma unroll
            for (int mi = 0; mi < 4; ++mi) {
                const uint32_t ad = sb + aOff + (uint32_t)mi * (16 * GS * 2) + ko;
                ldsm_x4(aF[mi][0], aF[mi][1], aF[mi][2], aF[mi][3], ad);
            }
#pragma unroll
            for (int np = 0; np < 2; ++np) {
                const uint32_t bd = sb + GA_BYTES + bOff
                                  + (uint32_t)np * (16 * GS * 2) + ko;
                ldsm_x4(bF[2 * np][0], bF[2 * np][1],
                        bF[2 * np + 1][0], bF[2 * np + 1][1], bd);
            }
#pragma unroll
            for (int mi = 0; mi < 4; ++mi)
#pragma unroll
                for (int ni = 0; ni < 4; ++ni) {
                    float* d = acc[mi][ni];
                    mma_f16(d[0], d[1], d[2], d[3],
                            aF[mi][0], aF[mi][1], aF[mi][2], aF[mi][3],
                            bF[ni][0], bF[ni][1]);
                }
        }
    }

#pragma unroll
    for (int mi = 0; mi < 4; ++mi) {
        const int m = m0 + wm + mi * 16 + (lane >> 2);
#pragma unroll
        for (int ni = 0; ni < 4; ++ni) {
            const int nc = n0 + wn + ni * 8 + 2 * (lane & 3);
            float b0 = bias[nc], b1 = bias[nc + 1];
            float c0 = acc[mi][ni][0] + b0, c1 = acc[mi][ni][1] + b1;
            float c2 = acc[mi][ni][2] + b0, c3 = acc[mi][ni][3] + b1;
            if (RELU) {
                c0 = fmaxf(c0, 0.f); c1 = fmaxf(c1, 0.f);
                c2 = fmaxf(c2, 0.f); c3 = fmaxf(c3, 0.f);
            }
            if (OUT == 0) {
                *(float2*)&C[(size_t)m * N + nc]       = make_float2(c0, c1);
                *(float2*)&C[(size_t)(m + 8) * N + nc] = make_float2(c2, c3);
            } else {
                *(uint32_t*)&Ch[(size_t)m * N + nc]       = pack2h(c0, c1);
                *(uint32_t*)&Ch[(size_t)(m + 8) * N + nc] = pack2h(c2, c3);
            }
        }
    }
}

// ---------------------------------------------------------------------------
// V transpose (fp16 single): V [token][512] -> Vt [B][H][E=64][L=2048]
// ---------------------------------------------------------------------------
__global__ __launch_bounds__(256) void vtrans_kernel(
    const __half* __restrict__ V, __half* __restrict__ Vt)
{
    __shared__ __half tile[64][72];
    const int lt = blockIdx.x, h = blockIdx.y, b = blockIdx.z;
    const int t = threadIdx.x;
    {
        int l = t >> 2, e0 = (t & 3) * 16;
        size_t g = ((size_t)(b * SEQ_L + lt * 64 + l)) * D_MODEL + h * 64 + e0;
        int4 a0 = *(const int4*)(V + g);
        int4 a1 = *(const int4*)(V + g + 8);
        *(int4*)&tile[l][e0]     = a0;
        *(int4*)&tile[l][e0 + 8] = a1;
    }
    __syncthreads();
    {
        int e = t >> 2, l0 = (t & 3) * 16;
        __align__(16) __half buf[16];
#pragma unroll
        for (int i = 0; i < 16; ++i) buf[i] = tile[l0 + i][e];
        size_t g = ((size_t)((b * N_HEADS + h) * 64 + e)) * SEQ_L + lt * 64 + l0;
        ((int4*)(Vt + g))[0] = ((int4*)buf)[0];
        ((int4*)(Vt + g))[1] = ((int4*)buf)[1];
    }
}

// ---------------------------------------------------------------------------
// fp16 tensor-core causal flash attention — all single fp16 operands.
// 128q x 64k tile, 8 warps. Output = fp16 single.
// ---------------------------------------------------------------------------
#define AT_S 72
#define AT_SMEM ((128 + 2 * 64) * AT_S * 2)   // 36864 B

__global__ __launch_bounds__(256, 1) void attn_mma_kernel(
    const __half* __restrict__ Q, const __half* __restrict__ K,
    const __half* __restrict__ Vt, __half* __restrict__ O)
{
    extern __shared__ __half smh[];
    __half* sQ = smh;
    __half* sK = sQ + 128 * AT_S;
    __half* sV = sK + 64 * AT_S;

    const int tid = threadIdx.x, lane = tid & 31, warp = tid >> 5;
    const int qt = blockIdx.x, h = blockIdx.y, b = blockIdx.z;
    const int q0 = qt * 128;
    const size_t qkBase = ((size_t)b * SEQ_L) * D_MODEL + (size_t)h * HEAD_E;
    const size_t vtBase = ((size_t)(b * N_HEADS + h)) * HEAD_E * SEQ_L;

    {
        int row = tid >> 1, e0 = (tid & 1) * 32;
        size_t g = qkBase + (size_t)(q0 + row) * D_MODEL + e0;
        int4 a0 = *(const int4*)(Q + g);
        int4 a1 = *(const int4*)(Q + g + 8);
        int4 a2 = *(const int4*)(Q + g + 16);
        int4 a3 = *(const int4*)(Q + g + 24);
        int4* d = (int4*)(sQ + row * AT_S + e0);
        d[0] = a0; d[1] = a1; d[2] = a2; d[3] = a3;
    }

    float m0 = -1e30f, m1 = -1e30f, l0s = 0.f, l1s = 0.f;
    float oacc[8][4];
#pragma unroll
    for (int nt = 0; nt < 8; ++nt)
#pragma unroll
        for (int r = 0; r < 4; ++r) oacc[nt][r] = 0.f;

    const int ldr = tid >> 2;
    const int ldc = (tid & 3) * 16;
    const int nkt = 2 * qt + 2;

    int4 pK0, pK1, pV0, pV1;
    {
        size_t gk = qkBase + (size_t)ldr * D_MODEL + ldc;
        pK0 = *(const int4*)(K + gk); pK1 = *(const int4*)(K + gk + 8);
        size_t gv = vtBase + (size_t)ldr * SEQ_L + ldc;
        pV0 = *(const int4*)(Vt + gv); pV1 = *(const int4*)(Vt + gv + 8);
    }

    const int gr = warp * 16 + (lane >> 2);
    const int cc = 2 * (lane & 3);

    for (int kt = 0; kt < nkt; ++kt) {
        const int k0 = kt * 64;
        __syncthreads();
        {
            int4* d;
            d = (int4*)(sK + ldr * AT_S + ldc); d[0] = pK0; d[1] = pK1;
            d = (int4*)(sV + ldr * AT_S + ldc); d[0] = pV0; d[1] = pV1;
        }
        __syncthreads();
        if (kt + 1 < nkt) {
            size_t gk = qkBase + (size_t)(k0 + 64 + ldr) * D_MODEL + ldc;
            pK0 = *(const int4*)(K + gk); pK1 = *(const int4*)(K + gk + 8);
            size_t gv = vtBase + (size_t)ldr * SEQ_L + k0 + 64 + ldc;
            pV0 = *(const int4*)(Vt + gv); pV1 = *(const int4*)(Vt + gv + 8);
        }

        float sacc[8][4];
#pragma unroll
        for (int nt = 0; nt < 8; ++nt)
#pragma unroll
            for (int r = 0; r < 4; ++r) sacc[nt][r] = 0.f;

#pragma unroll
        for (int es = 0; es < 4; ++es) {
            const int e = es * 16 + cc;
            uint32_t a0 = *(const uint32_t*)&sQ[gr * AT_S + e];
            uint32_t a1 = *(const uint32_t*)&sQ[(gr + 8) * AT_S + e];
            uint32_t a2 = *(const uint32_t*)&sQ[gr * AT_S + e + 8];
            uint32_t a3 = *(const uint32_t*)&sQ[(gr + 8) * AT_S + e + 8];
#pragma unroll
            for (int nt = 0; nt < 8; ++nt) {
                const int n = nt * 8 + (lane >> 2);
                uint32_t b0 = *(const uint32_t*)&sK[n * AT_S + e];
                uint32_t b1 = *(const uint32_t*)&sK[n * AT_S + e + 8];
                float* dd = sacc[nt];
                mma_f16(dd[0], dd[1], dd[2], dd[3], a0, a1, a2, a3, b0, b1);
            }
        }

        const float scl = 0.125f;
        if (kt >= 2 * qt) {
            const int qg0 = q0 + gr, qg1 = qg0 + 8;
#pragma unroll
            for (int nt = 0; nt < 8; ++nt) {
                const int kg = k0 + nt * 8 + cc;
                sacc[nt][0] = (kg     > qg0) ? -1e30f : sacc[nt][0] * scl;
                sacc[nt][1] = (kg + 1 > qg0) ? -1e30f : sacc[nt][1] * scl;
                sacc[nt][2] = (kg     > qg1) ? -1e30f : sacc[nt][2] * scl;
                sacc[nt][3] = (kg + 1 > qg1) ? -1e30f : sacc[nt][3] * scl;
            }
        } else {
#pragma unroll
            for (int nt = 0; nt < 8; ++nt) {
                sacc[nt][0] *= scl; sacc[nt][1] *= scl;
                sacc[nt][2] *= scl; sacc[nt][3] *= scl;
            }
        }

        float mx0 = -1e30f, mx1 = -1e30f;
#pragma unroll
        for (int nt = 0; nt < 8; ++nt) {
            mx0 = fmaxf(mx0, fmaxf(sacc[nt][0], sacc[nt][1]));
            mx1 = fmaxf(mx1, fmaxf(sacc[nt][2], sacc[nt][3]));
        }
        mx0 = fmaxf(mx0, __shfl_xor_sync(0xffffffffu, mx0, 1));
        mx0 = fmaxf(mx0, __shfl_xor_sync(0xffffffffu, mx0, 2));
        mx1 = fmaxf(mx1, __shfl_xor_sync(0xffffffffu, mx1, 1));
        mx1 = fmaxf(mx1, __shfl_xor_sync(0xffffffffu, mx1, 2));
        const float mn0 = fmaxf(m0, mx0), mn1 = fmaxf(m1, mx1);
        const float a0 = __expf(m0 - mn0), a1 = __expf(m1 - mn1);
        m0 = mn0; m1 = mn1;

        float s0 = 0.f, s1 = 0.f;
        uint32_t pP[4][4];
#pragma unroll
        for (int ks = 0; ks < 4; ++ks) {
            const int n0t = 2 * ks, n1t = 2 * ks + 1;
            float p00 = __expf(sacc[n0t][0] - mn0);
            float p01 = __expf(sacc[n0t][1] - mn0);
            float p10 = __expf(sacc[n0t][2] - mn1);
            float p11 = __expf(sacc[n0t][3] - mn1);
            float p20 = __expf(sacc[n1t][0] - mn0);
            float p21 = __expf(sacc[n1t][1] - mn0);
            float p30 = __expf(sacc[n1t][2] - mn1);
            float p31 = __expf(sacc[n1t][3] - mn1);
            s0 += p00 + p01 + p20 + p21;
            s1 += p10 + p11 + p30 + p31;
            pP[ks][0] = pack2h(p00, p01);
            pP[ks][1] = pack2h(p10, p11);
            pP[ks][2] = pack2h(p20, p21);
            pP[ks][3] = pack2h(p30, p31);
        }
        s0 += __shfl_xor_sync(0xffffffffu, s0, 1);
        s0 += __shfl_xor_sync(0xffffffffu, s0, 2);
        s1 += __shfl_xor_sync(0xffffffffu, s1, 1);
        s1 += __shfl_xor_sync(0xffffffffu, s1, 2);
        l0s = l0s * a0 + s0;
        l1s = l1s * a1 + s1;
#pragma unroll
        for (int nt = 0; nt < 8; ++nt) {
            oacc[nt][0] *= a0; oacc[nt][1] *= a0;
            oacc[nt][2] *= a1; oacc[nt][3] *= a1;
        }

#pragma unroll
        for (int ks = 0; ks < 4; ++ks) {
            const int kk = ks * 16 + cc;
#pragma unroll
            for (int nt = 0; nt < 8; ++nt) {
                const int n = nt * 8 + (lane >> 2);
                uint32_t b0 = *(const uint32_t*)&sV[n * AT_S + kk];
                uint32_t b1 = *(const uint32_t*)&sV[n * AT_S + kk + 8];
                float* dd = oacc[nt];
                mma_f16(dd[0], dd[1], dd[2], dd[3],
                        pP[ks][0], pP[ks][1], pP[ks][2], pP[ks][3], b0, b1);
            }
        }
    }

    const float inv0 = 1.f / l0s, inv1 = 1.f / l1s;
    const size_t r0 = qkBase + (size_t)(q0 + gr) * D_MODEL + cc;
    const size_t r1 = r0 + 8 * D_MODEL;
#pragma unroll
    for (int nt = 0; nt < 8; ++nt) {
        *(uint32_t*)&O[r0 + nt * 8] =
            pack2h(oacc[nt][0] * inv0, oacc[nt][1] * inv0);
        *(uint32_t*)&O[r1 + nt * 8] =
            pack2h(oacc[nt][2] * inv1, oacc[nt][3] * inv1);
    }
}

// ---------------------------------------------------------------------------
// Residual + LayerNorm (rows of 512); optional fp32 out + fp16 single out
// ---------------------------------------------------------------------------
template<bool F32OUT>
__global__ __launch_bounds__(128) void residual_ln_kernel(
    const float* __restrict__ a, const float* __restrict__ b,
    const float* __restrict__ gamma, const float* __restrict__ beta,
    float* __restrict__ out, __half* __restrict__ outh)
{
    const int row = blockIdx.x;
    const int tid = threadIdx.x;
    const size_t base = (size_t)row * D_VALUE;

    float4 va = ((const float4*)(a + base))[tid];
    float4 vb = ((const float4*)(b + base))[tid];
    float4 v = make_float4(va.x + vb.x, va.y + vb.y, va.z + vb.z, va.w + vb.w);

    float s  = v.x + v.y + v.z + v.w;
    float ss = v.x * v.x + v.y * v.y + v.z * v.z + v.w * v.w;
#pragma unroll
    for (int off = 16; off >= 1; off >>= 1) {
        s  += __shfl_xor_sync(0xffffffffu, s, off);
        ss += __shfl_xor_sync(0xffffffffu, ss, off);
    }
    __shared__ float red[8];
    const int wid = tid >> 5;
    if ((tid & 31) == 0) { red[wid] = s; red[4 + wid] = ss; }
    __syncthreads();
    s  = red[0] + red[1] + red[2] + red[3];
    ss = red[4] + red[5] + red[6] + red[7];

    const float mu = s * (1.f / (float)D_VALUE);
    float var = ss * (1.f / (float)D_VALUE) - mu * mu;
    const float rn = rsqrtf(var + 1e-5f);

    float4 g4 = ((const float4*)gamma)[tid];
    float4 b4 = ((const float4*)beta)[tid];
    float4 r;
    r.x = (v.x - mu) * rn * g4.x + b4.x;
    r.y = (v.y - mu) * rn * g4.y + b4.y;
    r.z = (v.z - mu) * rn * g4.z + b4.z;
    r.w = (v.w - mu) * rn * g4.w + b4.w;
    if (F32OUT) ((float4*)(out + base))[tid] = r;
    ((uint32_t*)(outh + base))[2 * tid]     = pack2h(r.x, r.y);
    ((uint32_t*)(outh + base))[2 * tid + 1] = pack2h(r.z, r.w);
}

// ---------------------------------------------------------------------------
// Launch
// ---------------------------------------------------------------------------
static inline void run_conv_f16(const float* x, __half* o, int n)
{
    int n4 = n / 4;
    conv_f16_kernel<<<(n4 + 255) / 256, 256>>>(x, o, n4);
}

template<bool RELU, int OUT>
static inline void run_gemm(
    const __half* A, const __half* B,
    const float* bias, float* C, __half* Ch,
    int M, int N, int K)
{
    cudaFuncSetAttribute(gemm_f16_kernel<RELU, OUT>,
                         cudaFuncAttributeMaxDynamicSharedMemorySize, GSMEM);
    gemm_f16_kernel<RELU, OUT><<<dim3(N / 128, M / 128), 256, GSMEM>>>(
        A, B, bias, C, Ch, M, N, K);
}

extern "C" void kernel_launch(void* const* d_in, const int* in_sizes, int n_in,
                              void* d_out, int out_size)
{
    const float* q   = (const float*)d_in[0];
    const float* k   = (const float*)d_in[1];
    const float* v   = (const float*)d_in[2];
    const float* Wq  = (const float*)d_in[3];
    const float* bq  = (const float*)d_in[4];
    const float* Wk  = (const float*)d_in[5];
    const float* bk  = (const float*)d_in[6];
    const float* Wv  = (const float*)d_in[7];
    const float* bv  = (const float*)d_in[8];
    const float* Wo  = (const float*)d_in[9];
    const float* bo  = (const float*)d_in[10];
    const float* Wc1 = (const float*)d_in[11];
    const float* bc1 = (const float*)d_in[12];
    const float* Wc2 = (const float*)d_in[13];
    const float* bc2 = (const float*)d_in[14];
    const float* g1  = (const float*)d_in[15];
    const float* b1  = (const float*)d_in[16];
    const float* g2  = (const float*)d_in[17];
    const float* b2  = (const float*)d_in[18];
    const float* Wl  = (const float*)d_in[19];
    const float* bl  = (const float*)d_in[20];
    float* out = (float*)d_out;

    float *Proj, *X, *Y;
    __half *q16, *k16, *v16;
    __half *Wq16, *Wk16, *Wv16, *Wo16, *Wc116, *Wc216, *Wl16;
    __half *Qf, *Kf, *Vf, *Vt, *Of, *Xh, *Ff, *X2h;
    cudaGetSymbolAddress((void**)&Proj,  g_proj);
    cudaGetSymbolAddress((void**)&X,     g_x);
    cudaGetSymbolAddress((void**)&Y,     g_y);
    cudaGetSymbolAddress((void**)&q16,   g_q16);
    cudaGetSymbolAddress((void**)&k16,   g_k16);
    cudaGetSymbolAddress((void**)&v16,   g_v16);
    cudaGetSymbolAddress((void**)&Wq16,  g_Wq16);
    cudaGetSymbolAddress((void**)&Wk16,  g_Wk16);
    cudaGetSymbolAddress((void**)&Wv16,  g_Wv16);
    cudaGetSymbolAddress((void**)&Wo16,  g_Wo16);
    cudaGetSymbolAddress((void**)&Wc116, g_Wc116);
    cudaGetSymbolAddress((void**)&Wc216, g_Wc216);
    cudaGetSymbolAddress((void**)&Wl16,  g_Wl16);
    cudaGetSymbolAddress((void**)&Qf,    g_Q);
    cudaGetSymbolAddress((void**)&Kf,    g_K);
    cudaGetSymbolAddress((void**)&Vf,    g_V);
    cudaGetSymbolAddress((void**)&Vt,    g_Vt);
    cudaGetSymbolAddress((void**)&Of,    g_O);
    cudaGetSymbolAddress((void**)&Xh,    g_Xh);
    cudaGetSymbolAddress((void**)&Ff,    g_F);
    cudaGetSymbolAddress((void**)&X2h,   g_X2h);

    // ---- conversions up front ----
    run_conv_f16(q, q16, M_ROWS * D_MODEL);
    run_conv_f16(k, k16, M_ROWS * D_MODEL);
    run_conv_f16(v, v16, M_ROWS * D_MODEL);
    run_conv_f16(Wq,  Wq16,  D_MODEL * D_MODEL);
    run_conv_f16(Wk,  Wk16,  D_MODEL * D_MODEL);
    run_conv_f16(Wv,  Wv16,  D_MODEL * D_MODEL);
    run_conv_f16(Wo,  Wo16,  D_MODEL * D_VALUE);
    run_conv_f16(Wc1, Wc116, D_FF * D_VALUE);
    run_conv_f16(Wc2, Wc216, D_VALUE * D_FF);
    run_conv_f16(Wl,  Wl16,  D_MODEL * D_VALUE);

    // ---- QKV projections ----
    run_gemm<false, 3>(q16, Wq16, bq, nullptr, Qf, M_ROWS, D_MODEL, D_MODEL);
    run_gemm<false, 3>(k16, Wk16, bk, nullptr, Kf, M_ROWS, D_MODEL, D_MODEL);
    run_gemm<false, 3>(v16, Wv16, bv, nullptr, Vf, M_ROWS, D_MODEL, D_MODEL);

    // ---- V transpose per head ----
    vtrans_kernel<<<dim3(SEQ_L / 64, N_HEADS, B_BATCH), 256>>>(Vf, Vt);

    // ---- attention ----
    cudaFuncSetAttribute(attn_mma_kernel,
                         cudaFuncAttributeMaxDynamicSharedMemorySize, AT_SMEM);
    attn_mma_kernel<<<dim3(SEQ_L / 128, N_HEADS, B_BATCH), 256, AT_SMEM>>>(
        Qf, Kf, Vt, Of);

    // ---- output projection (fp32 out) ----
    run_gemm<false, 0>(Of, Wo16, bo, Proj, nullptr, M_ROWS, D_MODEL, D_MODEL);

    // ---- residual + LN1 (fp32 X + fp16) ----
    residual_ln_kernel<true><<<M_ROWS, 128>>>(v, Proj, g1, b1, X, Xh);

    // ---- FFN ----
    run_gemm<true, 3>(Xh, Wc116, bc1, nullptr, Ff, M_ROWS, D_FF, D_VALUE);
    run_gemm<false, 0>(Ff, Wc216, bc2, Y, nullptr, M_ROWS, D_VALUE, D_FF);

    // ---- residual + LN2 (fp16 only) ----
    residual_ln_kernel<false><<<M_ROWS, 128>>>(X, Y, g2, b2, nullptr, X2h);

    // ---- final projection ----
    run_gemm<false, 0>(X2h, Wl16, bl, out, nullptr, M_ROWS, D_MODEL, D_VALUE);
}

// round 17
// speedup vs baseline: 5.1034x; 1.0492x over previous
#include <cuda_runtime.h>
#include <cuda_fp16.h>
#include <cstdint>

// ---------------------------------------------------------------------------
// Problem constants
// ---------------------------------------------------------------------------
#define B_BATCH 4
#define SEQ_L   2048
#define D_MODEL 512
#define D_VALUE 512
#define N_HEADS 8
#define HEAD_E  64
#define D_FF    2048
#define M_ROWS  (B_BATCH * SEQ_L)   // 8192

// ---------------------------------------------------------------------------
// Scratch (static device allocations)
// ---------------------------------------------------------------------------
__device__ float g_x[M_ROWS * D_VALUE];

__device__ __half g_q16[M_ROWS * D_MODEL];
__device__ __half g_k16[M_ROWS * D_MODEL];
__device__ __half g_v16[M_ROWS * D_MODEL];
__device__ __half g_Wq16[D_MODEL * D_MODEL];
__device__ __half g_Wk16[D_MODEL * D_MODEL];
__device__ __half g_Wv16[D_MODEL * D_MODEL];
__device__ __half g_Wo16[D_MODEL * D_VALUE];
__device__ __half g_Wc116[D_FF * D_VALUE];
__device__ __half g_Wc216[D_VALUE * D_FF];
__device__ __half g_Wl16[D_MODEL * D_VALUE];
__device__ __half g_Q  [M_ROWS * D_MODEL];
__device__ __half g_K  [M_ROWS * D_MODEL];
__device__ __half g_V  [M_ROWS * D_MODEL];
__device__ __half g_Vt [M_ROWS * D_MODEL];   // [B][H][E][L]
__device__ __half g_O  [M_ROWS * D_MODEL];
__device__ __half g_P16[M_ROWS * D_MODEL];   // Proj fp16
__device__ __half g_Xh [M_ROWS * D_VALUE];
__device__ __half g_F  [M_ROWS * D_FF];
__device__ __half g_Y16[M_ROWS * D_VALUE];
__device__ __half g_X2h[M_ROWS * D_VALUE];

// ---------------------------------------------------------------------------
// helpers
// ---------------------------------------------------------------------------
__device__ __forceinline__ uint32_t pack2h(float x, float y)
{
    __half2 h2 = __halves2half2(__float2half_rn(x), __float2half_rn(y));
    return *reinterpret_cast<uint32_t*>(&h2);
}

__device__ __forceinline__ void mma_f16(
    float& d0, float& d1, float& d2, float& d3,
    uint32_t a0, uint32_t a1, uint32_t a2, uint32_t a3,
    uint32_t b0, uint32_t b1)
{
    asm volatile(
        "mma.sync.aligned.m16n8k16.row.col.f32.f16.f16.f32 "
        "{%0,%1,%2,%3}, {%4,%5,%6,%7}, {%8,%9}, {%0,%1,%2,%3};"
        : "+f"(d0), "+f"(d1), "+f"(d2), "+f"(d3)
        : "r"(a0), "r"(a1), "r"(a2), "r"(a3), "r"(b0), "r"(b1));
}

__device__ __forceinline__ uint32_t smem_u32(const void* p)
{
    uint32_t a;
    asm("{ .reg .u64 t; cvta.to.shared.u64 t, %1; cvt.u32.u64 %0, t; }"
        : "=r"(a) : "l"(p));
    return a;
}

__device__ __forceinline__ void ldsm_x4(
    uint32_t& r0, uint32_t& r1, uint32_t& r2, uint32_t& r3, uint32_t addr)
{
    asm volatile(
        "ldmatrix.sync.aligned.m8n8.x4.shared.b16 {%0,%1,%2,%3}, [%4];"
        : "=r"(r0), "=r"(r1), "=r"(r2), "=r"(r3) : "r"(addr));
}

#define CP_ASYNC16(dst, src) \
    asm volatile("cp.async.cg.shared.global [%0], [%1], 16;" \
                 :: "r"(dst), "l"(src) : "memory")
#define CP_COMMIT() asm volatile("cp.async.commit_group;" ::: "memory")
#define CP_WAIT1()  asm volatile("cp.async.wait_group 1;" ::: "memory")
#define CP_WAIT0()  asm volatile("cp.async.wait_group 0;" ::: "memory")

// ---------------------------------------------------------------------------
// Multi-segment fp32 -> fp16 convert (all 10 tensors, one launch)
// ---------------------------------------------------------------------------
#define NSEG 10
struct Segs {
    const float* src[NSEG];
    __half*      dst[NSEG];
    int          n4[NSEG];
};

__global__ __launch_bounds__(256) void multiconv_kernel(Segs segs)
{
    int gi = blockIdx.x * 256 + threadIdx.x;
#pragma unroll
    for (int j = 0; j < NSEG; ++j) {
        const int n = segs.n4[j];
        if (gi < n) {
            float4 v = ((const float4*)segs.src[j])[gi];
            ((uint32_t*)segs.dst[j])[2 * gi]     = pack2h(v.x, v.y);
            ((uint32_t*)segs.dst[j])[2 * gi + 1] = pack2h(v.z, v.w);
            return;
        }
        gi -= n;
    }
}

// ---------------------------------------------------------------------------
// fp16 HMMA GEMM body (single x single): C = A @ W^T + bias.
// CTA 128x128, BK=32, 3-stage cp.async, ldmatrix, 1 mma term.
// OUT: 0 = fp32 C, 3 = fp16 single
// ---------------------------------------------------------------------------
#define GS 40
#define GA_BYTES (128 * GS * 2)
#define GSTAGE_BYTES (2 * GA_BYTES)
#define GSTAGES 3
#define GSMEM (GSTAGES * GSTAGE_BYTES)   // 61440

template<bool RELU, int OUT>
__device__ __forceinline__ void gemm_body(
    const __half* __restrict__ A, const __half* __restrict__ B,
    const float* __restrict__ bias, float* __restrict__ C,
    __half* __restrict__ Ch, int M, int N, int K, uint32_t su)
{
    const int tid  = threadIdx.x;
    const int lane = tid & 31;
    const int warp = tid >> 5;
    const int wm = (warp & 1) * 64;
    const int wn = (warp >> 1) * 32;
    const int m0 = blockIdx.y * 128;
    const int n0 = blockIdx.x * 128;

    const int crow = tid >> 1;
    const uint32_t cc32 = (uint32_t)(tid & 1) * 32;
    const int ce = (tid & 1) * 16;

    const __half* gA = A + (size_t)(m0 + crow) * K + ce;
    const __half* gB = B + (size_t)(n0 + crow) * K + ce;
    const uint32_t so = (uint32_t)crow * (GS * 2) + cc32;

    auto load_stage = [&](int i) {
        const uint32_t sb = su + (uint32_t)(i % GSTAGES) * GSTAGE_BYTES;
        const size_t kof = (size_t)i * 32;
        CP_ASYNC16(sb + 0 * GA_BYTES + so,      gA + kof);
        CP_ASYNC16(sb + 0 * GA_BYTES + so + 16, gA + kof + 8);
        CP_ASYNC16(sb + 1 * GA_BYTES + so,      gB + kof);
        CP_ASYNC16(sb + 1 * GA_BYTES + so + 16, gB + kof + 8);
        CP_COMMIT();
    };

    const int l8 = lane & 7, lq = lane >> 3;
    const uint32_t aOff = (uint32_t)(((wm + l8 + (lq & 1) * 8) * GS + (lq >> 1) * 8) * 2);
    const uint32_t bOff = (uint32_t)(((wn + l8 + (lq >> 1) * 8) * GS + (lq & 1) * 8) * 2);

    float acc[4][4][4];
#pragma unroll
    for (int mi = 0; mi < 4; ++mi)
#pragma unroll
        for (int ni = 0; ni < 4; ++ni)
#pragma unroll
            for (int r = 0; r < 4; ++r) acc[mi][ni][r] = 0.f;

    load_stage(0);
    load_stage(1);
    const int nch = K >> 5;

    for (int i = 0; i < nch; ++i) {
        if (i + 1 < nch) { CP_WAIT1(); } else { CP_WAIT0(); }
        __syncthreads();
        if (i + 2 < nch) load_stage(i + 2);
        const uint32_t sb = su + (uint32_t)(i % GSTAGES) * GSTAGE_BYTES;
#pragma unroll
        for (int ks = 0; ks < 2; ++ks) {
            const uint32_t ko = (uint32_t)ks * 32;
            uint32_t aF[4][4], bF[4][2];
#pragma unroll
            for (int mi = 0; mi < 4; ++mi) {
                const uint32_t ad = sb + aOff + (uint32_t)mi * (16 * GS * 2) + ko;
                ldsm_x4(aF[mi][0], aF[mi][1], aF[mi][2], aF[mi][3], ad);
            }
#pragma unroll
            for (int np = 0; np < 2; ++np) {
                const uint32_t bd = sb + GA_BYTES + bOff
                                  + (uint32_t)np * (16 * GS * 2) + ko;
                ldsm_x4(bF[2 * np][0], bF[2 * np][1],
                        bF[2 * np + 1][0], bF[2 * np + 1][1], bd);
            }
#pragma unroll
            for (int mi = 0; mi < 4; ++mi)
#pragma unroll
                for (int ni = 0; ni < 4; ++ni) {
                    float* d = acc[mi][ni];
                    mma_f16(d[0], d[1], d[2], d[3],
                            aF[mi][0], aF[mi][1], aF[mi][2], aF[mi][3],
                            bF[ni][0], bF[ni][1]);
                }
        }
    }

#pragma unroll
    for (int mi = 0; mi < 4; ++mi) {
        const int m = m0 + wm + mi * 16 + (lane >> 2);
#pragma unroll
        for (int ni = 0; ni < 4; ++ni) {
            const int nc = n0 + wn + ni * 8 + 2 * (lane & 3);
            float b0 = bias[nc], b1 = bias[nc + 1];
            float c0 = acc[mi][ni][0] + b0, c1 = acc[mi][ni][1] + b1;
            float c2 = acc[mi][ni][2] + b0, c3 = acc[mi][ni][3] + b1;
            if (RELU) {
                c0 = fmaxf(c0, 0.f); c1 = fmaxf(c1, 0.f);
                c2 = fmaxf(c2, 0.f); c3 = fmaxf(c3, 0.f);
            }
            if (OUT == 0) {
                *(float2*)&C[(size_t)m * N + nc]       = make_float2(c0, c1);
                *(float2*)&C[(size_t)(m + 8) * N + nc] = make_float2(c2, c3);
            } else {
                *(uint32_t*)&Ch[(size_t)m * N + nc]       = pack2h(c0, c1);
                *(uint32_t*)&Ch[(size_t)(m + 8) * N + nc] = pack2h(c2, c3);
            }
        }
    }
}

template<bool RELU, int OUT>
__global__ __launch_bounds__(256) void gemm_f16_kernel(
    const __half* __restrict__ A, const __half* __restrict__ B,
    const float* __restrict__ bias, float* __restrict__ C,
    __half* __restrict__ Ch, int M, int N, int K)
{
    extern __shared__ char smem[];
    gemm_body<RELU, OUT>(A, B, bias, C, Ch, M, N, K, smem_u32(smem));
}

// Batched QKV: blockIdx.z selects (A, W, bias, C) triple. fp16 out.
struct QKVArgs {
    const __half* A[3];
    const __half* B[3];
    const float*  bias[3];
    __half*       C[3];
};

__global__ __launch_bounds__(256) void gemm_qkv_kernel(QKVArgs a, int M, int N, int K)
{
    extern __shared__ char smem[];
    const int z = blockIdx.z;
    gemm_body<false, 3>(a.A[z], a.B[z], a.bias[z], nullptr, a.C[z],
                        M, N, K, smem_u32(smem));
}

// ---------------------------------------------------------------------------
// V transpose (fp16 single): V [token][512] -> Vt [B][H][E=64][L=2048]
// ---------------------------------------------------------------------------
__global__ __launch_bounds__(256) void vtrans_kernel(
    const __half* __restrict__ V, __half* __restrict__ Vt)
{
    __shared__ __half tile[64][72];
    const int lt = blockIdx.x, h = blockIdx.y, b = blockIdx.z;
    const int t = threadIdx.x;
    {
        int l = t >> 2, e0 = (t & 3) * 16;
        size_t g = ((size_t)(b * SEQ_L + lt * 64 + l)) * D_MODEL + h * 64 + e0;
        int4 a0 = *(const int4*)(V + g);
        int4 a1 = *(const int4*)(V + g + 8);
        *(int4*)&tile[l][e0]     = a0;
        *(int4*)&tile[l][e0 + 8] = a1;
    }
    __syncthreads();
    {
        int e = t >> 2, l0 = (t & 3) * 16;
        __align__(16) __half buf[16];
#pragma unroll
        for (int i = 0; i < 16; ++i) buf[i] = tile[l0 + i][e];
        size_t g = ((size_t)((b * N_HEADS + h) * 64 + e)) * SEQ_L + lt * 64 + l0;
        ((int4*)(Vt + g))[0] = ((int4*)buf)[0];
        ((int4*)(Vt + g))[1] = ((int4*)buf)[1];
    }
}

// ---------------------------------------------------------------------------
// fp16 tensor-core causal flash attention — all single fp16 operands.
// 128q x 64k tile, 8 warps. qt DESCENDING (long CTAs first).
// ---------------------------------------------------------------------------
#define AT_S 72
#define AT_SMEM ((128 + 2 * 64) * AT_S * 2)   // 36864 B

__global__ __launch_bounds__(256, 1) void attn_mma_kernel(
    const __half* __restrict__ Q, const __half* __restrict__ K,
    const __half* __restrict__ Vt, __half* __restrict__ O)
{
    extern __shared__ __half smh[];
    __half* sQ = smh;
    __half* sK = sQ + 128 * AT_S;
    __half* sV = sK + 64 * AT_S;

    const int tid = threadIdx.x, lane = tid & 31, warp = tid >> 5;
    const int qt = (int)gridDim.x - 1 - (int)blockIdx.x;  // long CTAs first
    const int h = blockIdx.y, b = blockIdx.z;
    const int q0 = qt * 128;
    const size_t qkBase = ((size_t)b * SEQ_L) * D_MODEL + (size_t)h * HEAD_E;
    const size_t vtBase = ((size_t)(b * N_HEADS + h)) * HEAD_E * SEQ_L;

    {
        int row = tid >> 1, e0 = (tid & 1) * 32;
        size_t g = qkBase + (size_t)(q0 + row) * D_MODEL + e0;
        int4 a0 = *(const int4*)(Q + g);
        int4 a1 = *(const int4*)(Q + g + 8);
        int4 a2 = *(const int4*)(Q + g + 16);
        int4 a3 = *(const int4*)(Q + g + 24);
        int4* d = (int4*)(sQ + row * AT_S + e0);
        d[0] = a0; d[1] = a1; d[2] = a2; d[3] = a3;
    }

    float m0 = -1e30f, m1 = -1e30f, l0s = 0.f, l1s = 0.f;
    float oacc[8][4];
#pragma unroll
    for (int nt = 0; nt < 8; ++nt)
#pragma unroll
        for (int r = 0; r < 4; ++r) oacc[nt][r] = 0.f;

    const int ldr = tid >> 2;
    const int ldc = (tid & 3) * 16;
    const int nkt = 2 * qt + 2;

    int4 pK0, pK1, pV0, pV1;
    {
        size_t gk = qkBase + (size_t)ldr * D_MODEL + ldc;
        pK0 = *(const int4*)(K + gk); pK1 = *(const int4*)(K + gk + 8);
        size_t gv = vtBase + (size_t)ldr * SEQ_L + ldc;
        pV0 = *(const int4*)(Vt + gv); pV1 = *(const int4*)(Vt + gv + 8);
    }

    const int gr = warp * 16 + (lane >> 2);
    const int cc = 2 * (lane & 3);

    for (int kt = 0; kt < nkt; ++kt) {
        const int k0 = kt * 64;
        __syncthreads();
        {
            int4* d;
            d = (int4*)(sK + ldr * AT_S + ldc); d[0] = pK0; d[1] = pK1;
            d = (int4*)(sV + ldr * AT_S + ldc); d[0] = pV0; d[1] = pV1;
        }
        __syncthreads();
        if (kt + 1 < nkt) {
            size_t gk = qkBase + (size_t)(k0 + 64 + ldr) * D_MODEL + ldc;
            pK0 = *(const int4*)(K + gk); pK1 = *(const int4*)(K + gk + 8);
            size_t gv = vtBase + (size_t)ldr * SEQ_L + k0 + 64 + ldc;
            pV0 = *(const int4*)(Vt + gv); pV1 = *(const int4*)(Vt + gv + 8);
        }

        float sacc[8][4];
#pragma unroll
        for (int nt = 0; nt < 8; ++nt)
#pragma unroll
            for (int r = 0; r < 4; ++r) sacc[nt][r] = 0.f;

#pragma unroll
        for (int es = 0; es < 4; ++es) {
            const int e = es * 16 + cc;
            uint32_t a0 = *(const uint32_t*)&sQ[gr * AT_S + e];
            uint32_t a1 = *(const uint32_t*)&sQ[(gr + 8) * AT_S + e];
            uint32_t a2 = *(const uint32_t*)&sQ[gr * AT_S + e + 8];
            uint32_t a3 = *(const uint32_t*)&sQ[(gr + 8) * AT_S + e + 8];
#pragma unroll
            for (int nt = 0; nt < 8; ++nt) {
                const int n = nt * 8 + (lane >> 2);
                uint32_t b0 = *(const uint32_t*)&sK[n * AT_S + e];
                uint32_t b1 = *(const uint32_t*)&sK[n * AT_S + e + 8];
                float* dd = sacc[nt];
                mma_f16(dd[0], dd[1], dd[2], dd[3], a0, a1, a2, a3, b0, b1);
            }
        }

        const float scl = 0.125f;
        if (kt >= 2 * qt) {
            const int qg0 = q0 + gr, qg1 = qg0 + 8;
#pragma unroll
            for (int nt = 0; nt < 8; ++nt) {
                const int kg = k0 + nt * 8 + cc;
                sacc[nt][0] = (kg     > qg0) ? -1e30f : sacc[nt][0] * scl;
                sacc[nt][1] = (kg + 1 > qg0) ? -1e30f : sacc[nt][1] * scl;
                sacc[nt][2] = (kg     > qg1) ? -1e30f : sacc[nt][2] * scl;
                sacc[nt][3] = (kg + 1 > qg1) ? -1e30f : sacc[nt][3] * scl;
            }
        } else {
#pragma unroll
            for (int nt = 0; nt < 8; ++nt) {
                sacc[nt][0] *= scl; sacc[nt][1] *= scl;
                sacc[nt][2] *= scl; sacc[nt][3] *= scl;
            }
        }

        float mx0 = -1e30f, mx1 = -1e30f;
#pragma unroll
        for (int nt = 0; nt < 8; ++nt) {
            mx0 = fmaxf(mx0, fmaxf(sacc[nt][0], sacc[nt][1]));
            mx1 = fmaxf(mx1, fmaxf(sacc[nt][2], sacc[nt][3]));
        }
        mx0 = fmaxf(mx0, __shfl_xor_sync(0xffffffffu, mx0, 1));
        mx0 = fmaxf(mx0, __shfl_xor_sync(0xffffffffu, mx0, 2));
        mx1 = fmaxf(mx1, __shfl_xor_sync(0xffffffffu, mx1, 1));
        mx1 = fmaxf(mx1, __shfl_xor_sync(0xffffffffu, mx1, 2));
        const float mn0 = fmaxf(m0, mx0), mn1 = fmaxf(m1, mx1);
        const float a0 = __expf(m0 - mn0), a1 = __expf(m1 - mn1);
        m0 = mn0; m1 = mn1;

        float s0 = 0.f, s1 = 0.f;
        uint32_t pP[4][4];
#pragma unroll
        for (int ks = 0; ks < 4; ++ks) {
            const int n0t = 2 * ks, n1t = 2 * ks + 1;
            float p00 = __expf(sacc[n0t][0] - mn0);
            float p01 = __expf(sacc[n0t][1] - mn0);
            float p10 = __expf(sacc[n0t][2] - mn1);
            float p11 = __expf(sacc[n0t][3] - mn1);
            float p20 = __expf(sacc[n1t][0] - mn0);
            float p21 = __expf(sacc[n1t][1] - mn0);
            float p30 = __expf(sacc[n1t][2] - mn1);
            float p31 = __expf(sacc[n1t][3] - mn1);
            s0 += p00 + p01 + p20 + p21;
            s1 += p10 + p11 + p30 + p31;
            pP[ks][0] = pack2h(p00, p01);
            pP[ks][1] = pack2h(p10, p11);
            pP[ks][2] = pack2h(p20, p21);
            pP[ks][3] = pack2h(p30, p31);
        }
        s0 += __shfl_xor_sync(0xffffffffu, s0, 1);
        s0 += __shfl_xor_sync(0xffffffffu, s0, 2);
        s1 += __shfl_xor_sync(0xffffffffu, s1, 1);
        s1 += __shfl_xor_sync(0xffffffffu, s1, 2);
        l0s = l0s * a0 + s0;
        l1s = l1s * a1 + s1;
#pragma unroll
        for (int nt = 0; nt < 8; ++nt) {
            oacc[nt][0] *= a0; oacc[nt][1] *= a0;
            oacc[nt][2] *= a1; oacc[nt][3] *= a1;
        }

#pragma unroll
        for (int ks = 0; ks < 4; ++ks) {
            const int kk = ks * 16 + cc;
#pragma unroll
            for (int nt = 0; nt < 8; ++nt) {
                const int n = nt * 8 + (lane >> 2);
                uint32_t b0 = *(const uint32_t*)&sV[n * AT_S + kk];
                uint32_t b1 = *(const uint32_t*)&sV[n * AT_S + kk + 8];
                float* dd = oacc[nt];
                mma_f16(dd[0], dd[1], dd[2], dd[3],
                        pP[ks][0], pP[ks][1], pP[ks][2], pP[ks][3], b0, b1);
            }
        }
    }

    const float inv0 = 1.f / l0s, inv1 = 1.f / l1s;
    const size_t r0 = qkBase + (size_t)(q0 + gr) * D_MODEL + cc;
    const size_t r1 = r0 + 8 * D_MODEL;
#pragma unroll
    for (int nt = 0; nt < 8; ++nt) {
        *(uint32_t*)&O[r0 + nt * 8] =
            pack2h(oacc[nt][0] * inv0, oacc[nt][1] * inv0);
        *(uint32_t*)&O[r1 + nt * 8] =
            pack2h(oacc[nt][2] * inv1, oacc[nt][3] * inv1);
    }
}

// ---------------------------------------------------------------------------
// Residual + LayerNorm (rows of 512): a fp32 + b fp16;
// optional fp32 out + fp16 single out
// ---------------------------------------------------------------------------
template<bool F32OUT>
__global__ __launch_bounds__(128) void residual_ln_kernel(
    const float* __restrict__ a, const __half* __restrict__ b,
    const float* __restrict__ gamma, const float* __restrict__ beta,
    float* __restrict__ out, __half* __restrict__ outh)
{
    const int row = blockIdx.x;
    const int tid = threadIdx.x;
    const size_t base = (size_t)row * D_VALUE;

    float4 va = ((const float4*)(a + base))[tid];
    uint2 hb = ((const uint2*)(b + base))[tid];
    __half2 hb0 = *reinterpret_cast<__half2*>(&hb.x);
    __half2 hb1 = *reinterpret_cast<__half2*>(&hb.y);
    float2 fb0 = __half22float2(hb0);
    float2 fb1 = __half22float2(hb1);
    float4 v = make_float4(va.x + fb0.x, va.y + fb0.y,
                           va.z + fb1.x, va.w + fb1.y);

    float s  = v.x + v.y + v.z + v.w;
    float ss = v.x * v.x + v.y * v.y + v.z * v.z + v.w * v.w;
#pragma unroll
    for (int off = 16; off >= 1; off >>= 1) {
        s  += __shfl_xor_sync(0xffffffffu, s, off);
        ss += __shfl_xor_sync(0xffffffffu, ss, off);
    }
    __shared__ float red[8];
    const int wid = tid >> 5;
    if ((tid & 31) == 0) { red[wid] = s; red[4 + wid] = ss; }
    __syncthreads();
    s  = red[0] + red[1] + red[2] + red[3];
    ss = red[4] + red[5] + red[6] + red[7];

    const float mu = s * (1.f / (float)D_VALUE);
    float var = ss * (1.f / (float)D_VALUE) - mu * mu;
    const float rn = rsqrtf(var + 1e-5f);

    float4 g4 = ((const float4*)gamma)[tid];
    float4 b4 = ((const float4*)beta)[tid];
    float4 r;
    r.x = (v.x - mu) * rn * g4.x + b4.x;
    r.y = (v.y - mu) * rn * g4.y + b4.y;
    r.z = (v.z - mu) * rn * g4.z + b4.z;
    r.w = (v.w - mu) * rn * g4.w + b4.w;
    if (F32OUT) ((float4*)(out + base))[tid] = r;
    ((uint32_t*)(outh + base))[2 * tid]     = pack2h(r.x, r.y);
    ((uint32_t*)(outh + base))[2 * tid + 1] = pack2h(r.z, r.w);
}

// ---------------------------------------------------------------------------
// Launch
// ---------------------------------------------------------------------------
template<bool RELU, int OUT>
static inline void run_gemm(
    const __half* A, const __half* B,
    const float* bias, float* C, __half* Ch,
    int M, int N, int K)
{
    cudaFuncSetAttribute(gemm_f16_kernel<RELU, OUT>,
                         cudaFuncAttributeMaxDynamicSharedMemorySize, GSMEM);
    gemm_f16_kernel<RELU, OUT><<<dim3(N / 128, M / 128), 256, GSMEM>>>(
        A, B, bias, C, Ch, M, N, K);
}

extern "C" void kernel_launch(void* const* d_in, const int* in_sizes, int n_in,
                              void* d_out, int out_size)
{
    const float* q   = (const float*)d_in[0];
    const float* k   = (const float*)d_in[1];
    const float* v   = (const float*)d_in[2];
    const float* Wq  = (const float*)d_in[3];
    const float* bq  = (const float*)d_in[4];
    const float* Wk  = (const float*)d_in[5];
    const float* bk  = (const float*)d_in[6];
    const float* Wv  = (const float*)d_in[7];
    const float* bv  = (const float*)d_in[8];
    const float* Wo  = (const float*)d_in[9];
    const float* bo  = (const float*)d_in[10];
    const float* Wc1 = (const float*)d_in[11];
    const float* bc1 = (const float*)d_in[12];
    const float* Wc2 = (const float*)d_in[13];
    const float* bc2 = (const float*)d_in[14];
    const float* g1  = (const float*)d_in[15];
    const float* b1  = (const float*)d_in[16];
    const float* g2  = (const float*)d_in[17];
    const float* b2  = (const float*)d_in[18];
    const float* Wl  = (const float*)d_in[19];
    const float* bl  = (const float*)d_in[20];
    float* out = (float*)d_out;

    float *X;
    __half *q16, *k16, *v16;
    __half *Wq16, *Wk16, *Wv16, *Wo16, *Wc116, *Wc216, *Wl16;
    __half *Qf, *Kf, *Vf, *Vt, *Of, *P16, *Xh, *Ff, *Y16, *X2h;
    cudaGetSymbolAddress((void**)&X,     g_x);
    cudaGetSymbolAddress((void**)&q16,   g_q16);
    cudaGetSymbolAddress((void**)&k16,   g_k16);
    cudaGetSymbolAddress((void**)&v16,   g_v16);
    cudaGetSymbolAddress((void**)&Wq16,  g_Wq16);
    cudaGetSymbolAddress((void**)&Wk16,  g_Wk16);
    cudaGetSymbolAddress((void**)&Wv16,  g_Wv16);
    cudaGetSymbolAddress((void**)&Wo16,  g_Wo16);
    cudaGetSymbolAddress((void**)&Wc116, g_Wc116);
    cudaGetSymbolAddress((void**)&Wc216, g_Wc216);
    cudaGetSymbolAddress((void**)&Wl16,  g_Wl16);
    cudaGetSymbolAddress((void**)&Qf,    g_Q);
    cudaGetSymbolAddress((void**)&Kf,    g_K);
    cudaGetSymbolAddress((void**)&Vf,    g_V);
    cudaGetSymbolAddress((void**)&Vt,    g_Vt);
    cudaGetSymbolAddress((void**)&Of,    g_O);
    cudaGetSymbolAddress((void**)&P16,   g_P16);
    cudaGetSymbolAddress((void**)&Xh,    g_Xh);
    cudaGetSymbolAddress((void**)&Ff,    g_F);
    cudaGetSymbolAddress((void**)&Y16,   g_Y16);
    cudaGetSymbolAddress((void**)&X2h,   g_X2h);

    // ---- all conversions: ONE launch ----
    {
        Segs s;
        const int NA = (M_ROWS * D_MODEL) / 4;   // 1048576
        const int NW = (D_MODEL * D_MODEL) / 4;  // 65536
        const int NF = (D_FF * D_VALUE) / 4;     // 262144
        s.src[0] = q;   s.dst[0] = q16;   s.n4[0] = NA;
        s.src[1] = k;   s.dst[1] = k16;   s.n4[1] = NA;
        s.src[2] = v;   s.dst[2] = v16;   s.n4[2] = NA;
        s.src[3] = Wq;  s.dst[3] = Wq16;  s.n4[3] = NW;
        s.src[4] = Wk;  s.dst[4] = Wk16;  s.n4[4] = NW;
        s.src[5] = Wv;  s.dst[5] = Wv16;  s.n4[5] = NW;
        s.src[6] = Wo;  s.dst[6] = Wo16;  s.n4[6] = NW;
        s.src[7] = Wc1; s.dst[7] = Wc116; s.n4[7] = NF;
        s.src[8] = Wc2; s.dst[8] = Wc216; s.n4[8] = NF;
        s.src[9] = Wl;  s.dst[9] = Wl16;  s.n4[9] = NW;
        const int total = 3 * NA + 5 * NW + 2 * NF;  // 3997696
        multiconv_kernel<<<(total + 255) / 256, 256>>>(s);
    }

    // ---- QKV projections: ONE batched launch ----
    {
        QKVArgs a;
        a.A[0] = q16;  a.A[1] = k16;  a.A[2] = v16;
        a.B[0] = Wq16; a.B[1] = Wk16; a.B[2] = Wv16;
        a.bias[0] = bq; a.bias[1] = bk; a.bias[2] = bv;
        a.C[0] = Qf;   a.C[1] = Kf;   a.C[2] = Vf;
        cudaFuncSetAttribute(gemm_qkv_kernel,
                             cudaFuncAttributeMaxDynamicSharedMemorySize, GSMEM);
        gemm_qkv_kernel<<<dim3(D_MODEL / 128, M_ROWS / 128, 3), 256, GSMEM>>>(
            a, M_ROWS, D_MODEL, D_MODEL);
    }

    // ---- V transpose per head ----
    vtrans_kernel<<<dim3(SEQ_L / 64, N_HEADS, B_BATCH), 256>>>(Vf, Vt);

    // ---- attention ----
    cudaFuncSetAttribute(attn_mma_kernel,
                         cudaFuncAttributeMaxDynamicSharedMemorySize, AT_SMEM);
    attn_mma_kernel<<<dim3(SEQ_L / 128, N_HEADS, B_BATCH), 256, AT_SMEM>>>(
        Qf, Kf, Vt, Of);

    // ---- output projection (fp16 out) ----
    run_gemm<false, 3>(Of, Wo16, bo, nullptr, P16, M_ROWS, D_MODEL, D_MODEL);

    // ---- residual + LN1 (fp32 X + fp16 Xh) ----
    residual_ln_kernel<true><<<M_ROWS, 128>>>(v, P16, g1, b1, X, Xh);

    // ---- FFN ----
    run_gemm<true, 3>(Xh, Wc116, bc1, nullptr, Ff, M_ROWS, D_FF, D_VALUE);
    run_gemm<false, 3>(Ff, Wc216, bc2, nullptr, Y16, M_ROWS, D_VALUE, D_FF);

    // ---- residual + LN2 (fp16 only) ----
    residual_ln_kernel<false><<<M_ROWS, 128>>>(X, Y16, g2, b2, nullptr, X2h);

    // ---- final projection (fp32 out) ----
    run_gemm<false, 0>(X2h, Wl16, bl, out, nullptr, M_ROWS, D_MODEL, D_VALUE);
}